// round 4
// baseline (speedup 1.0000x reference)
#include <cuda_runtime.h>
#include <cstdint>

// Problem dims
#define Bb 4
#define Tt 2048
#define Dd 1024
#define Hh 8
#define HD 128
#define Ee 8
#define BT 8192            // Bb*Tt
#define TH (Tt*HD)         // 262144

// ---------------- scratch (device globals; no allocations allowed) ----------
__device__ float g_x  [BT*Dd];   // running residual x
__device__ float g_xn [BT*Dd];   // LN1(x)
__device__ float g_q  [BT*Dd];   // [B,H,T,HD]
__device__ float g_k  [BT*Dd];
__device__ float g_v  [BT*Dd];
__device__ float g_att[BT*Dd];   // [B,H,T,HD]

__device__ __forceinline__ float neg_inf() { return __int_as_float(0xff800000); }

// ---------------- JAX threefry2x32 noise (PARTITIONABLE scheme) --------------
// jax_threefry_partitionable=True (default since JAX 0.4.30):
//   counter for element i is the 64-bit value i -> (hi, lo) = (0, i)
//   bits = out0 ^ out1 of threefry2x32(key=(0,42), (hi, lo))
__device__ __forceinline__ uint32_t rotl32(uint32_t v, int r) {
    return (v << r) | (v >> (32 - r));
}

__device__ float jax_noise(uint32_t i) {
    uint32_t x0 = 0u;        // counts_hi (i < 2^32)
    uint32_t x1 = i;         // counts_lo
    const uint32_t k0 = 0u, k1 = 42u, k2 = 0u ^ 42u ^ 0x1BD11BDAu;
    x0 += k0; x1 += k1;
#define TF_ROUND(r) { x0 += x1; x1 = rotl32(x1, r); x1 ^= x0; }
#define TF_G0 TF_ROUND(13) TF_ROUND(15) TF_ROUND(26) TF_ROUND(6)
#define TF_G1 TF_ROUND(17) TF_ROUND(29) TF_ROUND(16) TF_ROUND(24)
    TF_G0; x0 += k1; x1 += k2 + 1u;
    TF_G1; x0 += k2; x1 += k0 + 2u;
    TF_G0; x0 += k0; x1 += k1 + 3u;
    TF_G1; x0 += k1; x1 += k2 + 4u;
    TF_G0; x0 += k2; x1 += k0 + 5u;
#undef TF_G1
#undef TF_G0
#undef TF_ROUND
    uint32_t bits = x0 ^ x1;           // partitionable: xor of the two lanes
    // uniform in [lo, 1) with lo = nextafter(-1, 0)
    float f = __uint_as_float((bits >> 9) | 0x3f800000u) - 1.0f;  // [0,1)
    const float lo = -0.99999994f;
    float u = f * (1.0f - lo) + lo;
    u = fmaxf(u, lo);
    return 1.41421354f * erfinvf(u);   // sqrt(2) in f32
}

__device__ __forceinline__ float softplus_f(float x) {
    // jax.nn.softplus = logaddexp(x, 0)
    return fmaxf(x, 0.0f) + log1pf(expf(-fabsf(x)));
}

// ---------------- kernel 1: embedding + LayerNorm1 ---------------------------
__global__ __launch_bounds__(256) void embed_ln_kernel(
    const int* __restrict__ idx, const float* __restrict__ tok,
    const float* __restrict__ pos, const float* __restrict__ g1,
    const float* __restrict__ b1)
{
    int token = blockIdx.x;           // 0..8191 (b*T + t)
    int t     = token & (Tt - 1);
    int tid   = threadIdx.x;
    __shared__ float sx[Dd];
    __shared__ float rs_[8], rq_[8];

    const float* trow = tok + (size_t)idx[token] * Dd;
    const float* prow = pos + (size_t)t * Dd;

    float lsum = 0.f, lsq = 0.f;
    for (int c = tid; c < Dd; c += 256) {
        float v = trow[c] + prow[c];
        sx[c] = v; lsum += v; lsq += v * v;
    }
    #pragma unroll
    for (int o = 16; o; o >>= 1) {
        lsum += __shfl_xor_sync(0xffffffffu, lsum, o);
        lsq  += __shfl_xor_sync(0xffffffffu, lsq,  o);
    }
    if ((tid & 31) == 0) { rs_[tid >> 5] = lsum; rq_[tid >> 5] = lsq; }
    __syncthreads();
    float s = 0.f, q = 0.f;
    #pragma unroll
    for (int w = 0; w < 8; w++) { s += rs_[w]; q += rq_[w]; }
    float mu   = s * (1.0f / Dd);
    float var  = q * (1.0f / Dd) - mu * mu;
    float rstd = rsqrtf(var + 1e-5f);

    float* xr  = g_x  + (size_t)token * Dd;
    float* xnr = g_xn + (size_t)token * Dd;
    for (int c = tid; c < Dd; c += 256) {
        float v = sx[c];
        xr[c]  = v;
        xnr[c] = (v - mu) * rstd * g1[c] + b1[c];
    }
}

// ---------------- kernel 2: QKV projections ---------------------------------
// out[b,h,t,d] = sum_c xn[b,t,c] * W[h,c,d].  grid: (128, 2, 24)
__global__ __launch_bounds__(256) void qkv_gemm_kernel(
    const float* __restrict__ Wq, const float* __restrict__ Wk,
    const float* __restrict__ Wv)
{
    __shared__ float As[16][64];
    __shared__ float Bs[16][64];
    int z = blockIdx.z; int which = z >> 3; int h = z & 7;
    const float* W = (which == 0 ? Wq : which == 1 ? Wk : Wv) + (size_t)h * Dd * HD;
    float* Ob = (which == 0 ? g_q : which == 1 ? g_k : g_v);

    int m0 = blockIdx.x * 64, n0 = blockIdx.y * 64;
    int tid = threadIdx.x, tx = tid & 15, ty = tid >> 4;
    int lm = tid & 63, lk4 = (tid >> 6) << 2;
    int bk = tid >> 4, bn4 = (tid & 15) << 2;

    float c[4][4] = {};
    const float* Arow = g_xn + (size_t)(m0 + lm) * Dd;
    for (int k0 = 0; k0 < Dd; k0 += 16) {
        float4 av = *(const float4*)&Arow[k0 + lk4];
        As[lk4 + 0][lm] = av.x; As[lk4 + 1][lm] = av.y;
        As[lk4 + 2][lm] = av.z; As[lk4 + 3][lm] = av.w;
        *(float4*)&Bs[bk][bn4] = *(const float4*)&W[(size_t)(k0 + bk) * HD + n0 + bn4];
        __syncthreads();
        #pragma unroll
        for (int kk = 0; kk < 16; kk++) {
            float4 a = *(const float4*)&As[kk][ty << 2];
            float4 b = *(const float4*)&Bs[kk][tx << 2];
            c[0][0] += a.x * b.x; c[0][1] += a.x * b.y; c[0][2] += a.x * b.z; c[0][3] += a.x * b.w;
            c[1][0] += a.y * b.x; c[1][1] += a.y * b.y; c[1][2] += a.y * b.z; c[1][3] += a.y * b.w;
            c[2][0] += a.z * b.x; c[2][1] += a.z * b.y; c[2][2] += a.z * b.z; c[2][3] += a.z * b.w;
            c[3][0] += a.w * b.x; c[3][1] += a.w * b.y; c[3][2] += a.w * b.z; c[3][3] += a.w * b.w;
        }
        __syncthreads();
    }
    #pragma unroll
    for (int i = 0; i < 4; i++) {
        int m = m0 + (ty << 2) + i;
        int bb = m >> 11, tt = m & (Tt - 1);
        float* orow = Ob + ((size_t)(bb * Hh + h) * Tt + tt) * HD + n0 + (tx << 2);
        float4 o = make_float4(c[i][0], c[i][1], c[i][2], c[i][3]);
        *(float4*)orow = o;
    }
}

// ---------------- kernel 3: causal flash attention (fp32) --------------------
// grid: (32 q-tiles, B*H=32), 256 threads, dynamic smem 118784 B
#define ATT_SMEM_FLOATS (8192 + 128*68 + 64*132 + 64*68)
__global__ __launch_bounds__(256) void attn_kernel()
{
    extern __shared__ float sm[];
    float* Qs = sm;                    // [64][128]
    float* Kt = sm + 8192;             // [128][68]  (K transposed)
    float* Vs = Kt + 128 * 68;         // [64][132]
    float* Ps = Vs + 64 * 132;         // [64][68]

    int bh = blockIdx.y;
    int qt = blockIdx.x;
    int t0 = qt * 64;
    const float* Qg = g_q + (size_t)bh * TH;
    const float* Kg = g_k + (size_t)bh * TH;
    const float* Vg = g_v + (size_t)bh * TH;

    int tid = threadIdx.x, tx = tid & 15, ty = tid >> 4;
    const float scale = 0.03125f;      // D^-0.5 = 1/32

    // load Q tile (scaled)
    for (int i = tid; i < 64 * 32; i += 256) {
        int r = i >> 5, c4 = (i & 31) << 2;
        float4 qv = *(const float4*)&Qg[(size_t)(t0 + r) * HD + c4];
        qv.x *= scale; qv.y *= scale; qv.z *= scale; qv.w *= scale;
        *(float4*)&Qs[r * 128 + c4] = qv;
    }

    float acc[4][8];
    #pragma unroll
    for (int i = 0; i < 4; i++)
        #pragma unroll
        for (int j = 0; j < 8; j++) acc[i][j] = 0.f;
    float m_i[4] = {neg_inf(), neg_inf(), neg_inf(), neg_inf()};
    float l_i[4] = {0.f, 0.f, 0.f, 0.f};

    for (int j = 0; j <= qt; j++) {
        int s0 = j * 64;
        // load K (transposed) and V tiles
        for (int i = tid; i < 64 * 32; i += 256) {
            int s = i >> 5, d4 = (i & 31) << 2;
            float4 kv = *(const float4*)&Kg[(size_t)(s0 + s) * HD + d4];
            Kt[(d4 + 0) * 68 + s] = kv.x;
            Kt[(d4 + 1) * 68 + s] = kv.y;
            Kt[(d4 + 2) * 68 + s] = kv.z;
            Kt[(d4 + 3) * 68 + s] = kv.w;
            float4 vv = *(const float4*)&Vg[(size_t)(s0 + s) * HD + d4];
            *(float4*)&Vs[s * 132 + d4] = vv;
        }
        __syncthreads();

        // S = Q K^T (already scaled via Q)
        float S[4][4] = {};
        #pragma unroll 4
        for (int d = 0; d < 128; d += 4) {
            float4 kk[4];
            #pragma unroll
            for (int u = 0; u < 4; u++)
                kk[u] = *(const float4*)&Kt[(d + u) * 68 + (tx << 2)];
            #pragma unroll
            for (int i = 0; i < 4; i++) {
                float4 qv = *(const float4*)&Qs[(ty * 4 + i) * 128 + d];
                float qa[4] = {qv.x, qv.y, qv.z, qv.w};
                #pragma unroll
                for (int u = 0; u < 4; u++) {
                    S[i][0] = fmaf(qa[u], kk[u].x, S[i][0]);
                    S[i][1] = fmaf(qa[u], kk[u].y, S[i][1]);
                    S[i][2] = fmaf(qa[u], kk[u].z, S[i][2]);
                    S[i][3] = fmaf(qa[u], kk[u].w, S[i][3]);
                }
            }
        }
        // causal mask on diagonal tile
        if (j == qt) {
            #pragma unroll
            for (int i = 0; i < 4; i++) {
                int r = (ty << 2) + i;
                #pragma unroll
                for (int jj = 0; jj < 4; jj++) {
                    if (((tx << 2) + jj) > r) S[i][jj] = neg_inf();
                }
            }
        }
        // online softmax (row r = ty*4+i spread over tx 0..15)
        #pragma unroll
        for (int i = 0; i < 4; i++) {
            float rm = fmaxf(fmaxf(S[i][0], S[i][1]), fmaxf(S[i][2], S[i][3]));
            #pragma unroll
            for (int o = 8; o; o >>= 1)
                rm = fmaxf(rm, __shfl_xor_sync(0xffffffffu, rm, o));
            float mn = fmaxf(m_i[i], rm);
            float al = expf(m_i[i] - mn);
            float rsum = 0.f;
            #pragma unroll
            for (int jj = 0; jj < 4; jj++) {
                S[i][jj] = expf(S[i][jj] - mn);
                rsum += S[i][jj];
            }
            #pragma unroll
            for (int o = 8; o; o >>= 1)
                rsum += __shfl_xor_sync(0xffffffffu, rsum, o);
            l_i[i] = l_i[i] * al + rsum;
            m_i[i] = mn;
            #pragma unroll
            for (int cc = 0; cc < 8; cc++) acc[i][cc] *= al;
            *(float4*)&Ps[(ty * 4 + i) * 68 + (tx << 2)] =
                make_float4(S[i][0], S[i][1], S[i][2], S[i][3]);
        }
        __syncthreads();

        // O += P V
        #pragma unroll 4
        for (int s = 0; s < 64; s++) {
            float4 v0 = *(const float4*)&Vs[s * 132 + (tx << 3)];
            float4 v1 = *(const float4*)&Vs[s * 132 + (tx << 3) + 4];
            #pragma unroll
            for (int i = 0; i < 4; i++) {
                float p = Ps[(ty * 4 + i) * 68 + s];
                acc[i][0] = fmaf(p, v0.x, acc[i][0]);
                acc[i][1] = fmaf(p, v0.y, acc[i][1]);
                acc[i][2] = fmaf(p, v0.z, acc[i][2]);
                acc[i][3] = fmaf(p, v0.w, acc[i][3]);
                acc[i][4] = fmaf(p, v1.x, acc[i][4]);
                acc[i][5] = fmaf(p, v1.y, acc[i][5]);
                acc[i][6] = fmaf(p, v1.z, acc[i][6]);
                acc[i][7] = fmaf(p, v1.w, acc[i][7]);
            }
        }
        __syncthreads();
    }

    // write O / l
    #pragma unroll
    for (int i = 0; i < 4; i++) {
        float inv = 1.0f / l_i[i];
        int r = t0 + (ty << 2) + i;
        float* orow = g_att + ((size_t)bh * Tt + r) * HD + (tx << 3);
        float4 o0 = make_float4(acc[i][0]*inv, acc[i][1]*inv, acc[i][2]*inv, acc[i][3]*inv);
        float4 o1 = make_float4(acc[i][4]*inv, acc[i][5]*inv, acc[i][6]*inv, acc[i][7]*inv);
        *(float4*)&orow[0] = o0;
        *(float4*)&orow[4] = o1;
    }
}

// ---------------- kernel 4: output projection + residual ---------------------
// x <- x + concat_heads(att) @ Wo + bo.  grid: (128, 16)
__global__ __launch_bounds__(256) void proj_gemm_kernel(
    const float* __restrict__ Wo, const float* __restrict__ bo)
{
    __shared__ float As[16][64];
    __shared__ float Bs[16][64];
    int m0 = blockIdx.x * 64, n0 = blockIdx.y * 64;
    int tid = threadIdx.x, tx = tid & 15, ty = tid >> 4;
    int lm = tid & 63, lk4 = (tid >> 6) << 2;
    int bk = tid >> 4, bn4 = (tid & 15) << 2;

    int m = m0 + lm;
    int bb = m >> 11, tt = m & (Tt - 1);
    const float* Abase = g_att + (size_t)bb * Hh * TH + (size_t)tt * HD;

    float c[4][4] = {};
    for (int k0 = 0; k0 < Dd; k0 += 16) {
        int cc = k0 + lk4;
        int h = cc >> 7, dd = cc & 127;
        float4 av = *(const float4*)&Abase[(size_t)h * TH + dd];
        As[lk4 + 0][lm] = av.x; As[lk4 + 1][lm] = av.y;
        As[lk4 + 2][lm] = av.z; As[lk4 + 3][lm] = av.w;
        *(float4*)&Bs[bk][bn4] = *(const float4*)&Wo[(size_t)(k0 + bk) * Dd + n0 + bn4];
        __syncthreads();
        #pragma unroll
        for (int kk = 0; kk < 16; kk++) {
            float4 a = *(const float4*)&As[kk][ty << 2];
            float4 b = *(const float4*)&Bs[kk][tx << 2];
            c[0][0] += a.x * b.x; c[0][1] += a.x * b.y; c[0][2] += a.x * b.z; c[0][3] += a.x * b.w;
            c[1][0] += a.y * b.x; c[1][1] += a.y * b.y; c[1][2] += a.y * b.z; c[1][3] += a.y * b.w;
            c[2][0] += a.z * b.x; c[2][1] += a.z * b.y; c[2][2] += a.z * b.z; c[2][3] += a.z * b.w;
            c[3][0] += a.w * b.x; c[3][1] += a.w * b.y; c[3][2] += a.w * b.z; c[3][3] += a.w * b.w;
        }
        __syncthreads();
    }
    #pragma unroll
    for (int i = 0; i < 4; i++) {
        int mi = m0 + (ty << 2) + i;
        int n = n0 + (tx << 2);
        float4 bv = *(const float4*)&bo[n];
        float4 xv = *(const float4*)&g_x[(size_t)mi * Dd + n];
        float4 o = make_float4(c[i][0] + bv.x + xv.x, c[i][1] + bv.y + xv.y,
                               c[i][2] + bv.z + xv.z, c[i][3] + bv.w + xv.w);
        *(float4*)&g_x[(size_t)mi * Dd + n] = o;
    }
}

// ---------------- kernel 5: LayerNorm2 + noisy top-2 router + outputs --------
// output packing (f32): [x_norm | router_probs | indices | x]
#define OUT_OFF_PROBS (BT * Dd)
#define OUT_OFF_IDX   (OUT_OFF_PROBS + BT * Ee)
#define OUT_OFF_X     (OUT_OFF_IDX + BT * 2)
__global__ __launch_bounds__(256) void ln2_router_kernel(
    const float* __restrict__ g2, const float* __restrict__ b2,
    const float* __restrict__ Wr, const float* __restrict__ br,
    const float* __restrict__ Wn, const float* __restrict__ bn,
    float* __restrict__ out)
{
    int token = blockIdx.x;
    int tid = threadIdx.x;
    __shared__ float sxn[Dd];
    __shared__ float rs_[8], rq_[8];
    __shared__ float red[8][16];

    const float* xr = g_x + (size_t)token * Dd;
    float lsum = 0.f, lsq = 0.f;
    for (int c = tid; c < Dd; c += 256) {
        float v = xr[c];
        sxn[c] = v;
        out[OUT_OFF_X + (size_t)token * Dd + c] = v;     // x output
        lsum += v; lsq += v * v;
    }
    #pragma unroll
    for (int o = 16; o; o >>= 1) {
        lsum += __shfl_xor_sync(0xffffffffu, lsum, o);
        lsq  += __shfl_xor_sync(0xffffffffu, lsq,  o);
    }
    if ((tid & 31) == 0) { rs_[tid >> 5] = lsum; rq_[tid >> 5] = lsq; }
    __syncthreads();
    float s = 0.f, q = 0.f;
    #pragma unroll
    for (int w = 0; w < 8; w++) { s += rs_[w]; q += rq_[w]; }
    float mu   = s * (1.0f / Dd);
    float var  = q * (1.0f / Dd) - mu * mu;
    float rstd = rsqrtf(var + 1e-5f);

    for (int c = tid; c < Dd; c += 256) {
        float v  = sxn[c];
        float xn = (v - mu) * rstd * g2[c] + b2[c];
        sxn[c] = xn;
        out[(size_t)token * Dd + c] = xn;                // x_norm output
    }
    __syncthreads();

    // router logits: logits[e] = xn . Wr[:,e];  noise_logits[e] = xn . Wn[:,e]
    float ar[8] = {}, an_[8] = {};
    for (int c = tid; c < Dd; c += 256) {
        float v = sxn[c];
        float4 w0 = *(const float4*)&Wr[(size_t)c * Ee];
        float4 w1 = *(const float4*)&Wr[(size_t)c * Ee + 4];
        ar[0] += v * w0.x; ar[1] += v * w0.y; ar[2] += v * w0.z; ar[3] += v * w0.w;
        ar[4] += v * w1.x; ar[5] += v * w1.y; ar[6] += v * w1.z; ar[7] += v * w1.w;
        float4 n0 = *(const float4*)&Wn[(size_t)c * Ee];
        float4 n1 = *(const float4*)&Wn[(size_t)c * Ee + 4];
        an_[0] += v * n0.x; an_[1] += v * n0.y; an_[2] += v * n0.z; an_[3] += v * n0.w;
        an_[4] += v * n1.x; an_[5] += v * n1.y; an_[6] += v * n1.z; an_[7] += v * n1.w;
    }
    #pragma unroll
    for (int o = 16; o; o >>= 1) {
        #pragma unroll
        for (int e = 0; e < 8; e++) {
            ar[e]  += __shfl_xor_sync(0xffffffffu, ar[e],  o);
            an_[e] += __shfl_xor_sync(0xffffffffu, an_[e], o);
        }
    }
    int w = tid >> 5;
    if ((tid & 31) == 0) {
        #pragma unroll
        for (int e = 0; e < 8; e++) { red[w][e] = ar[e]; red[w][8 + e] = an_[e]; }
    }
    __syncthreads();

    if (tid == 0) {
        float lg[8], nl[8];
        #pragma unroll
        for (int e = 0; e < 8; e++) { lg[e] = br[e]; nl[e] = bn[e]; }
        for (int ww = 0; ww < 8; ww++)
            #pragma unroll
            for (int e = 0; e < 8; e++) { lg[e] += red[ww][e]; nl[e] += red[ww][8 + e]; }

        float noisy[8];
        #pragma unroll
        for (int e = 0; e < 8; e++) {
            float nz = jax_noise((uint32_t)(token * Ee + e));
            noisy[e] = lg[e] + nz * softplus_f(nl[e]);
        }
        // top-2 (stable: lower index wins ties)
        int i0 = 0; float v0 = noisy[0];
        #pragma unroll
        for (int e = 1; e < 8; e++) if (noisy[e] > v0) { v0 = noisy[e]; i0 = e; }
        int i1 = -1; float v1 = neg_inf();
        #pragma unroll
        for (int e = 0; e < 8; e++)
            if (e != i0 && noisy[e] > v1) { v1 = noisy[e]; i1 = e; }

        float e1 = expf(v1 - v0);
        float inv = 1.0f / (1.0f + e1);
        float p0 = inv, p1 = e1 * inv;

        float probs[8] = {};
        probs[i0] = p0; probs[i1] = p1;
        float* pout = out + OUT_OFF_PROBS + (size_t)token * Ee;
        #pragma unroll
        for (int e = 0; e < 8; e++) pout[e] = probs[e];
        out[OUT_OFF_IDX + (size_t)token * 2 + 0] = (float)i0;
        out[OUT_OFF_IDX + (size_t)token * 2 + 1] = (float)i1;
    }
}

// ---------------- launcher ---------------------------------------------------
extern "C" void kernel_launch(void* const* d_in, const int* in_sizes, int n_in,
                              void* d_out, int out_size)
{
    const int*   idx = (const int*)  d_in[0];
    const float* tok = (const float*)d_in[1];
    const float* pos = (const float*)d_in[2];
    const float* Wq  = (const float*)d_in[3];
    const float* Wk  = (const float*)d_in[4];
    const float* Wv  = (const float*)d_in[5];
    const float* Wo  = (const float*)d_in[6];
    const float* bo  = (const float*)d_in[7];
    const float* g1  = (const float*)d_in[8];
    const float* b1  = (const float*)d_in[9];
    const float* g2  = (const float*)d_in[10];
    const float* b2  = (const float*)d_in[11];
    const float* Wr  = (const float*)d_in[12];
    const float* br  = (const float*)d_in[13];
    const float* Wn  = (const float*)d_in[14];
    const float* bn  = (const float*)d_in[15];
    float* out = (float*)d_out;

    // dynamic smem for attention (118784 B > default 48 KB)
    cudaFuncSetAttribute(attn_kernel, cudaFuncAttributeMaxDynamicSharedMemorySize,
                         ATT_SMEM_FLOATS * (int)sizeof(float));

    embed_ln_kernel<<<BT, 256>>>(idx, tok, pos, g1, b1);
    qkv_gemm_kernel<<<dim3(BT / 64, HD / 64, 3 * Hh), 256>>>(Wq, Wk, Wv);
    attn_kernel<<<dim3(Tt / 64, Bb * Hh), 256, ATT_SMEM_FLOATS * sizeof(float)>>>();
    proj_gemm_kernel<<<dim3(BT / 64, Dd / 64), 256>>>(Wo, bo);
    ln2_router_kernel<<<BT, 256>>>(g2, b2, Wr, br, Wn, bn, out);
}

// round 6
// speedup vs baseline: 1.2594x; 1.2594x over previous
#include <cuda_runtime.h>
#include <cstdint>

// Problem dims
#define Bb 4
#define Tt 2048
#define Dd 1024
#define Hh 8
#define HD 128
#define Ee 8
#define BT 8192            // Bb*Tt
#define TH (Tt*HD)         // 262144

// ---------------- scratch (device globals; no allocations allowed) ----------
__device__ float g_x  [BT*Dd];   // running residual x
__device__ float g_xn [BT*Dd];   // LN1(x)
__device__ float g_q  [BT*Dd];   // [B,H,T,HD]
__device__ float g_k  [BT*Dd];
__device__ float g_v  [BT*Dd];
__device__ float g_att[BT*Dd];   // [B,T,H*HD]  (concat-head layout)
__device__ float g_wt [3*Hh*HD*Dd];  // [which*8+h][d][c]  transposed QKV weights
__device__ float g_wot[Dd*Dd];       // Wo^T [n][k]

__device__ __forceinline__ float neg_inf() { return __int_as_float(0xff800000); }

// tf32 round-to-nearest conversion (base PTX, sm_80+)
__device__ __forceinline__ float tf32_hi(float a) {
    uint32_t r; asm("cvt.rna.tf32.f32 %0, %1;" : "=r"(r) : "f"(a));
    return __uint_as_float(r);
}

// m16n8k8 tf32 MMA (base PTX, sm_80+): D += A * B
__device__ __forceinline__ void mma_frag(float* d, const uint32_t* a, const uint32_t* b) {
    asm volatile("mma.sync.aligned.m16n8k8.row.col.f32.tf32.tf32.f32 "
        "{%0,%1,%2,%3}, {%4,%5,%6,%7}, {%8,%9}, {%0,%1,%2,%3};"
        : "+f"(d[0]), "+f"(d[1]), "+f"(d[2]), "+f"(d[3])
        : "r"(a[0]), "r"(a[1]), "r"(a[2]), "r"(a[3]), "r"(b[0]), "r"(b[1]));
}

// ---------------- JAX threefry2x32 noise (partitionable scheme) --------------
__device__ __forceinline__ uint32_t rotl32(uint32_t v, int r) {
    return (v << r) | (v >> (32 - r));
}
__device__ float jax_noise(uint32_t i) {
    uint32_t x0 = 0u, x1 = i;
    const uint32_t k0 = 0u, k1 = 42u, k2 = 0u ^ 42u ^ 0x1BD11BDAu;
    x0 += k0; x1 += k1;
#define TF_ROUND(r) { x0 += x1; x1 = rotl32(x1, r); x1 ^= x0; }
#define TF_G0 TF_ROUND(13) TF_ROUND(15) TF_ROUND(26) TF_ROUND(6)
#define TF_G1 TF_ROUND(17) TF_ROUND(29) TF_ROUND(16) TF_ROUND(24)
    TF_G0; x0 += k1; x1 += k2 + 1u;
    TF_G1; x0 += k2; x1 += k0 + 2u;
    TF_G0; x0 += k0; x1 += k1 + 3u;
    TF_G1; x0 += k1; x1 += k2 + 4u;
    TF_G0; x0 += k2; x1 += k0 + 5u;
#undef TF_G1
#undef TF_G0
#undef TF_ROUND
    uint32_t bits = x0 ^ x1;
    float f = __uint_as_float((bits >> 9) | 0x3f800000u) - 1.0f;
    const float lo = -0.99999994f;
    float u = f * (1.0f - lo) + lo;
    u = fmaxf(u, lo);
    return 1.41421354f * erfinvf(u);
}
__device__ __forceinline__ float softplus_f(float x) {
    return fmaxf(x, 0.0f) + log1pf(expf(-fabsf(x)));
}

// ---------------- kernel 1: embedding + LayerNorm1 ---------------------------
__global__ __launch_bounds__(256) void embed_ln_kernel(
    const int* __restrict__ idx, const float* __restrict__ tok,
    const float* __restrict__ pos, const float* __restrict__ g1,
    const float* __restrict__ b1)
{
    int token = blockIdx.x;
    int t     = token & (Tt - 1);
    int tid   = threadIdx.x;
    __shared__ float sx[Dd];
    __shared__ float rs_[8], rq_[8];

    const float* trow = tok + (size_t)idx[token] * Dd;
    const float* prow = pos + (size_t)t * Dd;

    float lsum = 0.f, lsq = 0.f;
    for (int c = tid; c < Dd; c += 256) {
        float v = trow[c] + prow[c];
        sx[c] = v; lsum += v; lsq += v * v;
    }
    #pragma unroll
    for (int o = 16; o; o >>= 1) {
        lsum += __shfl_xor_sync(0xffffffffu, lsum, o);
        lsq  += __shfl_xor_sync(0xffffffffu, lsq,  o);
    }
    if ((tid & 31) == 0) { rs_[tid >> 5] = lsum; rq_[tid >> 5] = lsq; }
    __syncthreads();
    float s = 0.f, q = 0.f;
    #pragma unroll
    for (int w = 0; w < 8; w++) { s += rs_[w]; q += rq_[w]; }
    float mu   = s * (1.0f / Dd);
    float var  = q * (1.0f / Dd) - mu * mu;
    float rstd = rsqrtf(var + 1e-5f);

    float* xr  = g_x  + (size_t)token * Dd;
    float* xnr = g_xn + (size_t)token * Dd;
    for (int c = tid; c < Dd; c += 256) {
        float v = sx[c];
        xr[c]  = v;
        xnr[c] = (v - mu) * rstd * g1[c] + b1[c];
    }
}

// ---------------- weight transposes ------------------------------------------
__global__ __launch_bounds__(256) void transpose_qkv_kernel(
    const float* __restrict__ Wq, const float* __restrict__ Wk,
    const float* __restrict__ Wv)
{
    __shared__ float tile[32][33];
    int z = blockIdx.z; int which = z >> 3, h = z & 7;
    const float* src = (which == 0 ? Wq : which == 1 ? Wk : Wv) + (size_t)h * Dd * HD;
    float* dst = g_wt + (size_t)z * HD * Dd;
    int c0 = blockIdx.x * 32, d0 = blockIdx.y * 32;
    int tx = threadIdx.x, ty = threadIdx.y;
    #pragma unroll
    for (int j = 0; j < 32; j += 8)
        tile[ty + j][tx] = src[(size_t)(c0 + ty + j) * HD + d0 + tx];
    __syncthreads();
    #pragma unroll
    for (int j = 0; j < 32; j += 8)
        dst[(size_t)(d0 + ty + j) * Dd + c0 + tx] = tile[tx][ty + j];
}

__global__ __launch_bounds__(256) void transpose_wo_kernel(const float* __restrict__ Wo)
{
    __shared__ float tile[32][33];
    int k0 = blockIdx.x * 32, n0 = blockIdx.y * 32;
    int tx = threadIdx.x, ty = threadIdx.y;
    #pragma unroll
    for (int j = 0; j < 32; j += 8)
        tile[ty + j][tx] = Wo[(size_t)(k0 + ty + j) * Dd + n0 + tx];
    __syncthreads();
    #pragma unroll
    for (int j = 0; j < 32; j += 8)
        g_wot[(size_t)(n0 + ty + j) * Dd + k0 + tx] = tile[tx][ty + j];
}

// ---------------- 3xTF32 mma.sync GEMM core ----------------------------------
// C[128x128] = A[128x1024] * B[128x1024]^T  (B stored [n][k])
// block 256 thr (8 warps, 4x2), warp tile 32x64, K chunks of 32.
#define NCHUNK 32
#define LDP 36                       // smem row pitch (floats)
#define TILE_FP (128 * LDP)          // 4608 floats per tile array
#define GEMM_SMEM_BYTES (4 * TILE_FP * 4)   // 73728

__device__ __forceinline__ void gemm3x_mainloop(
    const float* __restrict__ Abase, const float* __restrict__ Bbase,
    float acc[2][8][4], float* sm, int tid)
{
    float* Ah = sm;
    float* Al = sm + TILE_FP;
    float* Bh = sm + 2 * TILE_FP;
    float* Bl = sm + 3 * TILE_FP;
    int wid = tid >> 5, lane = tid & 31;
    int wm = (wid & 3) * 32, wn = (wid >> 2) * 64;
    int lr = lane >> 2, lc = lane & 3;

    for (int c = 0; c < NCHUNK; c++) {
        __syncthreads();            // protect prior iteration's frag reads
        #pragma unroll
        for (int p = 0; p < 4; p++) {
            int f = tid + p * 256;          // float4 index 0..1023
            int r = f >> 3, c4 = (f & 7) << 2;
            size_t go = (size_t)r * Dd + c * 32 + c4;
            float4 va = *(const float4*)&Abase[go];
            float4 h, l;
            h.x = tf32_hi(va.x); l.x = tf32_hi(va.x - h.x);
            h.y = tf32_hi(va.y); l.y = tf32_hi(va.y - h.y);
            h.z = tf32_hi(va.z); l.z = tf32_hi(va.z - h.z);
            h.w = tf32_hi(va.w); l.w = tf32_hi(va.w - h.w);
            *(float4*)&Ah[r * LDP + c4] = h;
            *(float4*)&Al[r * LDP + c4] = l;
            float4 vb = *(const float4*)&Bbase[go];
            h.x = tf32_hi(vb.x); l.x = tf32_hi(vb.x - h.x);
            h.y = tf32_hi(vb.y); l.y = tf32_hi(vb.y - h.y);
            h.z = tf32_hi(vb.z); l.z = tf32_hi(vb.z - h.z);
            h.w = tf32_hi(vb.w); l.w = tf32_hi(vb.w - h.w);
            *(float4*)&Bh[r * LDP + c4] = h;
            *(float4*)&Bl[r * LDP + c4] = l;
        }
        __syncthreads();
        #pragma unroll
        for (int k8 = 0; k8 < 4; k8++) {
            int k0 = k8 * 8;
            uint32_t ah[2][4], al[2][4];
            #pragma unroll
            for (int mt = 0; mt < 2; mt++) {
                int rb = (wm + mt * 16 + lr) * LDP + k0 + lc;
                ah[mt][0] = __float_as_uint(Ah[rb]);
                ah[mt][1] = __float_as_uint(Ah[rb + 8 * LDP]);
                ah[mt][2] = __float_as_uint(Ah[rb + 4]);
                ah[mt][3] = __float_as_uint(Ah[rb + 8 * LDP + 4]);
                al[mt][0] = __float_as_uint(Al[rb]);
                al[mt][1] = __float_as_uint(Al[rb + 8 * LDP]);
                al[mt][2] = __float_as_uint(Al[rb + 4]);
                al[mt][3] = __float_as_uint(Al[rb + 8 * LDP + 4]);
            }
            #pragma unroll
            for (int nt = 0; nt < 8; nt++) {
                int nb = (wn + nt * 8 + lr) * LDP + k0 + lc;
                uint32_t bh[2] = {__float_as_uint(Bh[nb]), __float_as_uint(Bh[nb + 4])};
                uint32_t bl[2] = {__float_as_uint(Bl[nb]), __float_as_uint(Bl[nb + 4])};
                #pragma unroll
                for (int mt = 0; mt < 2; mt++) {
                    mma_frag(acc[mt][nt], ah[mt], bh);
                    mma_frag(acc[mt][nt], ah[mt], bl);
                    mma_frag(acc[mt][nt], al[mt], bh);
                }
            }
        }
    }
}

// ---------------- kernel 2: QKV via mma.sync (grid 64 x 24) ------------------
__global__ __launch_bounds__(256) void qkv_mma_kernel()
{
    extern __shared__ float sm[];
    int tid = threadIdx.x, wid = tid >> 5, lane = tid & 31;
    int m0 = blockIdx.x * 128;
    int z  = blockIdx.y;                 // which*8 + h
    const float* Abase = g_xn + (size_t)m0 * Dd;
    const float* Bbase = g_wt + (size_t)z * HD * Dd;

    float acc[2][8][4];
    #pragma unroll
    for (int mt = 0; mt < 2; mt++)
        #pragma unroll
        for (int nt = 0; nt < 8; nt++)
            #pragma unroll
            for (int r = 0; r < 4; r++) acc[mt][nt][r] = 0.f;

    gemm3x_mainloop(Abase, Bbase, acc, sm, tid);

    int wm = (wid & 3) * 32, wn = (wid >> 2) * 64;
    int lr = lane >> 2, lc = lane & 3;
    int which = z >> 3, h = z & 7;
    float* Ob = (which == 0 ? g_q : which == 1 ? g_k : g_v);
    #pragma unroll
    for (int mt = 0; mt < 2; mt++) {
        int m = m0 + wm + mt * 16 + lr;
        int bb = m >> 11, tt = m & (Tt - 1);
        float* row0 = Ob + ((size_t)(bb * Hh + h) * Tt + tt) * HD + wn + lc * 2;
        #pragma unroll
        for (int nt = 0; nt < 8; nt++) {
            float* p0 = row0 + nt * 8;
            p0[0]          = acc[mt][nt][0];
            p0[1]          = acc[mt][nt][1];
            p0[8 * HD]     = acc[mt][nt][2];
            p0[8 * HD + 1] = acc[mt][nt][3];
        }
    }
}

// ---------------- kernel 4: proj + residual via mma.sync (grid 64 x 8) -------
__global__ __launch_bounds__(256) void proj_mma_kernel(const float* __restrict__ bo)
{
    extern __shared__ float sm[];
    int tid = threadIdx.x, wid = tid >> 5, lane = tid & 31;
    int m0 = blockIdx.x * 128;
    int n0 = blockIdx.y * 128;
    const float* Abase = g_att + (size_t)m0 * Dd;
    const float* Bbase = g_wot + (size_t)n0 * Dd;

    float acc[2][8][4];
    #pragma unroll
    for (int mt = 0; mt < 2; mt++)
        #pragma unroll
        for (int nt = 0; nt < 8; nt++)
            #pragma unroll
            for (int r = 0; r < 4; r++) acc[mt][nt][r] = 0.f;

    gemm3x_mainloop(Abase, Bbase, acc, sm, tid);

    int wm = (wid & 3) * 32, wn = (wid >> 2) * 64;
    int lr = lane >> 2, lc = lane & 3;
    #pragma unroll
    for (int mt = 0; mt < 2; mt++) {
        int m = m0 + wm + mt * 16 + lr;
        float* xrow = g_x + (size_t)m * Dd + n0 + wn + lc * 2;
        const float* brow = bo + n0 + wn + lc * 2;
        #pragma unroll
        for (int nt = 0; nt < 8; nt++) {
            float* p0 = xrow + nt * 8;
            const float* b0 = brow + nt * 8;
            p0[0]          += acc[mt][nt][0] + b0[0];
            p0[1]          += acc[mt][nt][1] + b0[1];
            p0[8 * Dd]     += acc[mt][nt][2] + b0[0];
            p0[8 * Dd + 1] += acc[mt][nt][3] + b0[1];
        }
    }
}

// ---------------- kernel 3: causal flash attention (fp32) --------------------
#define ATT_SMEM_FLOATS (8192 + 128*68 + 64*132 + 64*68)
__global__ __launch_bounds__(256) void attn_kernel()
{
    extern __shared__ float smx[];
    float* Qs = smx;
    float* Kt = smx + 8192;
    float* Vs = Kt + 128 * 68;
    float* Ps = Vs + 64 * 132;

    int bh = blockIdx.y;
    int qt = blockIdx.x;
    int t0 = qt * 64;
    const float* Qg = g_q + (size_t)bh * TH;
    const float* Kg = g_k + (size_t)bh * TH;
    const float* Vg = g_v + (size_t)bh * TH;

    int tid = threadIdx.x, tx = tid & 15, ty = tid >> 4;
    const float scale = 0.03125f;

    for (int i = tid; i < 64 * 32; i += 256) {
        int r = i >> 5, c4 = (i & 31) << 2;
        float4 qv = *(const float4*)&Qg[(size_t)(t0 + r) * HD + c4];
        qv.x *= scale; qv.y *= scale; qv.z *= scale; qv.w *= scale;
        *(float4*)&Qs[r * 128 + c4] = qv;
    }

    float acc[4][8];
    #pragma unroll
    for (int i = 0; i < 4; i++)
        #pragma unroll
        for (int j = 0; j < 8; j++) acc[i][j] = 0.f;
    float m_i[4] = {neg_inf(), neg_inf(), neg_inf(), neg_inf()};
    float l_i[4] = {0.f, 0.f, 0.f, 0.f};

    for (int j = 0; j <= qt; j++) {
        int s0 = j * 64;
        for (int i = tid; i < 64 * 32; i += 256) {
            int s = i >> 5, d4 = (i & 31) << 2;
            float4 kv = *(const float4*)&Kg[(size_t)(s0 + s) * HD + d4];
            Kt[(d4 + 0) * 68 + s] = kv.x;
            Kt[(d4 + 1) * 68 + s] = kv.y;
            Kt[(d4 + 2) * 68 + s] = kv.z;
            Kt[(d4 + 3) * 68 + s] = kv.w;
            float4 vv = *(const float4*)&Vg[(size_t)(s0 + s) * HD + d4];
            *(float4*)&Vs[s * 132 + d4] = vv;
        }
        __syncthreads();

        float S[4][4] = {};
        #pragma unroll 4
        for (int d = 0; d < 128; d += 4) {
            float4 kk[4];
            #pragma unroll
            for (int u = 0; u < 4; u++)
                kk[u] = *(const float4*)&Kt[(d + u) * 68 + (tx << 2)];
            #pragma unroll
            for (int i = 0; i < 4; i++) {
                float4 qv = *(const float4*)&Qs[(ty * 4 + i) * 128 + d];
                float qa[4] = {qv.x, qv.y, qv.z, qv.w};
                #pragma unroll
                for (int u = 0; u < 4; u++) {
                    S[i][0] = fmaf(qa[u], kk[u].x, S[i][0]);
                    S[i][1] = fmaf(qa[u], kk[u].y, S[i][1]);
                    S[i][2] = fmaf(qa[u], kk[u].z, S[i][2]);
                    S[i][3] = fmaf(qa[u], kk[u].w, S[i][3]);
                }
            }
        }
        if (j == qt) {
            #pragma unroll
            for (int i = 0; i < 4; i++) {
                int r = (ty << 2) + i;
                #pragma unroll
                for (int jj = 0; jj < 4; jj++) {
                    if (((tx << 2) + jj) > r) S[i][jj] = neg_inf();
                }
            }
        }
        #pragma unroll
        for (int i = 0; i < 4; i++) {
            float rm = fmaxf(fmaxf(S[i][0], S[i][1]), fmaxf(S[i][2], S[i][3]));
            #pragma unroll
            for (int o = 8; o; o >>= 1)
                rm = fmaxf(rm, __shfl_xor_sync(0xffffffffu, rm, o));
            float mn = fmaxf(m_i[i], rm);
            float al = expf(m_i[i] - mn);
            float rsum = 0.f;
            #pragma unroll
            for (int jj = 0; jj < 4; jj++) {
                S[i][jj] = expf(S[i][jj] - mn);
                rsum += S[i][jj];
            }
            #pragma unroll
            for (int o = 8; o; o >>= 1)
                rsum += __shfl_xor_sync(0xffffffffu, rsum, o);
            l_i[i] = l_i[i] * al + rsum;
            m_i[i] = mn;
            #pragma unroll
            for (int cc = 0; cc < 8; cc++) acc[i][cc] *= al;
            *(float4*)&Ps[(ty * 4 + i) * 68 + (tx << 2)] =
                make_float4(S[i][0], S[i][1], S[i][2], S[i][3]);
        }
        __syncthreads();

        #pragma unroll 4
        for (int s = 0; s < 64; s++) {
            float4 v0 = *(const float4*)&Vs[s * 132 + (tx << 3)];
            float4 v1 = *(const float4*)&Vs[s * 132 + (tx << 3) + 4];
            #pragma unroll
            for (int i = 0; i < 4; i++) {
                float p = Ps[(ty * 4 + i) * 68 + s];
                acc[i][0] = fmaf(p, v0.x, acc[i][0]);
                acc[i][1] = fmaf(p, v0.y, acc[i][1]);
                acc[i][2] = fmaf(p, v0.z, acc[i][2]);
                acc[i][3] = fmaf(p, v0.w, acc[i][3]);
                acc[i][4] = fmaf(p, v1.x, acc[i][4]);
                acc[i][5] = fmaf(p, v1.y, acc[i][5]);
                acc[i][6] = fmaf(p, v1.z, acc[i][6]);
                acc[i][7] = fmaf(p, v1.w, acc[i][7]);
            }
        }
        __syncthreads();
    }

    // write O in concat-head layout [B, T, H*HD]
    int bb = bh >> 3, h = bh & 7;
    #pragma unroll
    for (int i = 0; i < 4; i++) {
        float inv = 1.0f / l_i[i];
        int r = t0 + (ty << 2) + i;
        float* orow = g_att + ((size_t)(bb * Tt + r)) * Dd + h * HD + (tx << 3);
        float4 o0 = make_float4(acc[i][0]*inv, acc[i][1]*inv, acc[i][2]*inv, acc[i][3]*inv);
        float4 o1 = make_float4(acc[i][4]*inv, acc[i][5]*inv, acc[i][6]*inv, acc[i][7]*inv);
        *(float4*)&orow[0] = o0;
        *(float4*)&orow[4] = o1;
    }
}

// ---------------- kernel 5: LayerNorm2 + noisy top-2 router + outputs --------
#define OUT_OFF_PROBS (BT * Dd)
#define OUT_OFF_IDX   (OUT_OFF_PROBS + BT * Ee)
#define OUT_OFF_X     (OUT_OFF_IDX + BT * 2)
__global__ __launch_bounds__(256) void ln2_router_kernel(
    const float* __restrict__ g2, const float* __restrict__ b2,
    const float* __restrict__ Wr, const float* __restrict__ br,
    const float* __restrict__ Wn, const float* __restrict__ bn,
    float* __restrict__ out)
{
    int token = blockIdx.x;
    int tid = threadIdx.x;
    __shared__ float sxn[Dd];
    __shared__ float rs_[8], rq_[8];
    __shared__ float red[8][16];

    const float* xr = g_x + (size_t)token * Dd;
    float lsum = 0.f, lsq = 0.f;
    for (int c = tid; c < Dd; c += 256) {
        float v = xr[c];
        sxn[c] = v;
        out[OUT_OFF_X + (size_t)token * Dd + c] = v;
        lsum += v; lsq += v * v;
    }
    #pragma unroll
    for (int o = 16; o; o >>= 1) {
        lsum += __shfl_xor_sync(0xffffffffu, lsum, o);
        lsq  += __shfl_xor_sync(0xffffffffu, lsq,  o);
    }
    if ((tid & 31) == 0) { rs_[tid >> 5] = lsum; rq_[tid >> 5] = lsq; }
    __syncthreads();
    float s = 0.f, q = 0.f;
    #pragma unroll
    for (int w = 0; w < 8; w++) { s += rs_[w]; q += rq_[w]; }
    float mu   = s * (1.0f / Dd);
    float var  = q * (1.0f / Dd) - mu * mu;
    float rstd = rsqrtf(var + 1e-5f);

    for (int c = tid; c < Dd; c += 256) {
        float v  = sxn[c];
        float xn = (v - mu) * rstd * g2[c] + b2[c];
        sxn[c] = xn;
        out[(size_t)token * Dd + c] = xn;
    }
    __syncthreads();

    float ar[8] = {}, an_[8] = {};
    for (int c = tid; c < Dd; c += 256) {
        float v = sxn[c];
        float4 w0 = *(const float4*)&Wr[(size_t)c * Ee];
        float4 w1 = *(const float4*)&Wr[(size_t)c * Ee + 4];
        ar[0] += v * w0.x; ar[1] += v * w0.y; ar[2] += v * w0.z; ar[3] += v * w0.w;
        ar[4] += v * w1.x; ar[5] += v * w1.y; ar[6] += v * w1.z; ar[7] += v * w1.w;
        float4 n0 = *(const float4*)&Wn[(size_t)c * Ee];
        float4 n1 = *(const float4*)&Wn[(size_t)c * Ee + 4];
        an_[0] += v * n0.x; an_[1] += v * n0.y; an_[2] += v * n0.z; an_[3] += v * n0.w;
        an_[4] += v * n1.x; an_[5] += v * n1.y; an_[6] += v * n1.z; an_[7] += v * n1.w;
    }
    #pragma unroll
    for (int o = 16; o; o >>= 1) {
        #pragma unroll
        for (int e = 0; e < 8; e++) {
            ar[e]  += __shfl_xor_sync(0xffffffffu, ar[e],  o);
            an_[e] += __shfl_xor_sync(0xffffffffu, an_[e], o);
        }
    }
    int w = tid >> 5;
    if ((tid & 31) == 0) {
        #pragma unroll
        for (int e = 0; e < 8; e++) { red[w][e] = ar[e]; red[w][8 + e] = an_[e]; }
    }
    __syncthreads();

    if (tid == 0) {
        float lg[8], nl[8];
        #pragma unroll
        for (int e = 0; e < 8; e++) { lg[e] = br[e]; nl[e] = bn[e]; }
        for (int ww = 0; ww < 8; ww++)
            #pragma unroll
            for (int e = 0; e < 8; e++) { lg[e] += red[ww][e]; nl[e] += red[ww][8 + e]; }

        float noisy[8];
        #pragma unroll
        for (int e = 0; e < 8; e++) {
            float nz = jax_noise((uint32_t)(token * Ee + e));
            noisy[e] = lg[e] + nz * softplus_f(nl[e]);
        }
        int i0 = 0; float v0 = noisy[0];
        #pragma unroll
        for (int e = 1; e < 8; e++) if (noisy[e] > v0) { v0 = noisy[e]; i0 = e; }
        int i1 = -1; float v1 = neg_inf();
        #pragma unroll
        for (int e = 0; e < 8; e++)
            if (e != i0 && noisy[e] > v1) { v1 = noisy[e]; i1 = e; }

        float e1 = expf(v1 - v0);
        float inv = 1.0f / (1.0f + e1);
        float p0 = inv, p1 = e1 * inv;

        float probs[8] = {};
        probs[i0] = p0; probs[i1] = p1;
        float* pout = out + OUT_OFF_PROBS + (size_t)token * Ee;
        #pragma unroll
        for (int e = 0; e < 8; e++) pout[e] = probs[e];
        out[OUT_OFF_IDX + (size_t)token * 2 + 0] = (float)i0;
        out[OUT_OFF_IDX + (size_t)token * 2 + 1] = (float)i1;
    }
}

// ---------------- launcher ---------------------------------------------------
extern "C" void kernel_launch(void* const* d_in, const int* in_sizes, int n_in,
                              void* d_out, int out_size)
{
    const int*   idx = (const int*)  d_in[0];
    const float* tok = (const float*)d_in[1];
    const float* pos = (const float*)d_in[2];
    const float* Wq  = (const float*)d_in[3];
    const float* Wk  = (const float*)d_in[4];
    const float* Wv  = (const float*)d_in[5];
    const float* Wo  = (const float*)d_in[6];
    const float* bo  = (const float*)d_in[7];
    const float* g1  = (const float*)d_in[8];
    const float* b1  = (const float*)d_in[9];
    const float* g2  = (const float*)d_in[10];
    const float* b2  = (const float*)d_in[11];
    const float* Wr  = (const float*)d_in[12];
    const float* br  = (const float*)d_in[13];
    const float* Wn  = (const float*)d_in[14];
    const float* bn  = (const float*)d_in[15];
    float* out = (float*)d_out;

    cudaFuncSetAttribute(attn_kernel, cudaFuncAttributeMaxDynamicSharedMemorySize,
                         ATT_SMEM_FLOATS * (int)sizeof(float));
    cudaFuncSetAttribute(qkv_mma_kernel, cudaFuncAttributeMaxDynamicSharedMemorySize,
                         GEMM_SMEM_BYTES);
    cudaFuncSetAttribute(proj_mma_kernel, cudaFuncAttributeMaxDynamicSharedMemorySize,
                         GEMM_SMEM_BYTES);

    embed_ln_kernel<<<BT, 256>>>(idx, tok, pos, g1, b1);
    transpose_qkv_kernel<<<dim3(32, 4, 24), dim3(32, 8)>>>(Wq, Wk, Wv);
    transpose_wo_kernel<<<dim3(32, 32), dim3(32, 8)>>>(Wo);
    qkv_mma_kernel<<<dim3(BT / 128, 24), 256, GEMM_SMEM_BYTES>>>();
    attn_kernel<<<dim3(Tt / 64, Bb * Hh), 256, ATT_SMEM_FLOATS * sizeof(float)>>>();
    proj_mma_kernel<<<dim3(BT / 128, Dd / 128), 256, GEMM_SMEM_BYTES>>>(bo);
    ln2_router_kernel<<<BT, 256>>>(g2, b2, Wr, br, Wn, bn, out);
}

// round 7
// speedup vs baseline: 1.4683x; 1.1659x over previous
#include <cuda_runtime.h>
#include <cstdint>

// Problem dims
#define Bb 4
#define Tt 2048
#define Dd 1024
#define Hh 8
#define HD 128
#define Ee 8
#define BT 8192            // Bb*Tt
#define TH (Tt*HD)         // 262144

// ---------------- scratch (device globals; no allocations allowed) ----------
__device__ float g_x   [BT*Dd];   // running residual x
__device__ float g_xnh [BT*Dd];   // LN1(x) tf32 hi
__device__ float g_xnl [BT*Dd];   // LN1(x) tf32 lo
__device__ float g_q   [BT*Dd];   // [B,H,T,HD]
__device__ float g_k   [BT*Dd];
__device__ float g_v   [BT*Dd];
__device__ float g_atth[BT*Dd];   // attention out hi  [B,T,H*HD]
__device__ float g_attl[BT*Dd];   // attention out lo
__device__ float g_wth [3*Hh*HD*Dd];  // transposed QKV weights hi  [z][d][c]
__device__ float g_wtl [3*Hh*HD*Dd];
__device__ float g_woth[Dd*Dd];       // Wo^T hi [n][k]
__device__ float g_wotl[Dd*Dd];

__device__ __forceinline__ float neg_inf() { return __int_as_float(0xff800000); }

// tf32 round-to-nearest (base PTX, sm_80+)
__device__ __forceinline__ float tf32_hi(float a) {
    uint32_t r; asm("cvt.rna.tf32.f32 %0, %1;" : "=r"(r) : "f"(a));
    return __uint_as_float(r);
}
// split fp32 -> (hi, lo) both tf32-rounded, as uint bit patterns
__device__ __forceinline__ void split2(float v, uint32_t& h, uint32_t& l) {
    float hf = tf32_hi(v);
    h = __float_as_uint(hf);
    l = __float_as_uint(tf32_hi(v - hf));
}

// m16n8k8 tf32 MMA (base PTX, sm_80+): D += A * B
__device__ __forceinline__ void mma_frag(float* d, const uint32_t* a, const uint32_t* b) {
    asm volatile("mma.sync.aligned.m16n8k8.row.col.f32.tf32.tf32.f32 "
        "{%0,%1,%2,%3}, {%4,%5,%6,%7}, {%8,%9}, {%0,%1,%2,%3};"
        : "+f"(d[0]), "+f"(d[1]), "+f"(d[2]), "+f"(d[3])
        : "r"(a[0]), "r"(a[1]), "r"(a[2]), "r"(a[3]), "r"(b[0]), "r"(b[1]));
}

// cp.async (base PTX, sm_80+)
__device__ __forceinline__ uint32_t smem_to_u32(const void* p) {
    uint32_t a;
    asm("{ .reg .u64 t; cvta.to.shared.u64 t, %1; cvt.u32.u64 %0, t; }" : "=r"(a) : "l"(p));
    return a;
}
__device__ __forceinline__ void cp_async16(uint32_t saddr, const void* gaddr) {
    asm volatile("cp.async.cg.shared.global [%0], [%1], 16;" :: "r"(saddr), "l"(gaddr));
}
__device__ __forceinline__ void cp_commit() { asm volatile("cp.async.commit_group;" ::: "memory"); }
template<int N> __device__ __forceinline__ void cp_wait() {
    asm volatile("cp.async.wait_group %0;" :: "n"(N) : "memory");
}

// ---------------- JAX threefry2x32 noise (partitionable scheme) --------------
__device__ __forceinline__ uint32_t rotl32(uint32_t v, int r) {
    return (v << r) | (v >> (32 - r));
}
__device__ float jax_noise(uint32_t i) {
    uint32_t x0 = 0u, x1 = i;
    const uint32_t k0 = 0u, k1 = 42u, k2 = 0u ^ 42u ^ 0x1BD11BDAu;
    x0 += k0; x1 += k1;
#define TF_ROUND(r) { x0 += x1; x1 = rotl32(x1, r); x1 ^= x0; }
#define TF_G0 TF_ROUND(13) TF_ROUND(15) TF_ROUND(26) TF_ROUND(6)
#define TF_G1 TF_ROUND(17) TF_ROUND(29) TF_ROUND(16) TF_ROUND(24)
    TF_G0; x0 += k1; x1 += k2 + 1u;
    TF_G1; x0 += k2; x1 += k0 + 2u;
    TF_G0; x0 += k0; x1 += k1 + 3u;
    TF_G1; x0 += k1; x1 += k2 + 4u;
    TF_G0; x0 += k2; x1 += k0 + 5u;
#undef TF_G1
#undef TF_G0
#undef TF_ROUND
    uint32_t bits = x0 ^ x1;
    float f = __uint_as_float((bits >> 9) | 0x3f800000u) - 1.0f;
    const float lo = -0.99999994f;
    float u = f * (1.0f - lo) + lo;
    u = fmaxf(u, lo);
    return 1.41421354f * erfinvf(u);
}
__device__ __forceinline__ float softplus_f(float x) {
    return fmaxf(x, 0.0f) + log1pf(expf(-fabsf(x)));
}

// ---------------- kernel 1: embedding + LayerNorm1 (writes split xn) ---------
__global__ __launch_bounds__(256) void embed_ln_kernel(
    const int* __restrict__ idx, const float* __restrict__ tok,
    const float* __restrict__ pos, const float* __restrict__ g1,
    const float* __restrict__ b1)
{
    int token = blockIdx.x;
    int t     = token & (Tt - 1);
    int tid   = threadIdx.x;
    __shared__ float sx[Dd];
    __shared__ float rs_[8], rq_[8];

    const float* trow = tok + (size_t)idx[token] * Dd;
    const float* prow = pos + (size_t)t * Dd;

    float lsum = 0.f, lsq = 0.f;
    for (int c = tid; c < Dd; c += 256) {
        float v = trow[c] + prow[c];
        sx[c] = v; lsum += v; lsq += v * v;
    }
    #pragma unroll
    for (int o = 16; o; o >>= 1) {
        lsum += __shfl_xor_sync(0xffffffffu, lsum, o);
        lsq  += __shfl_xor_sync(0xffffffffu, lsq,  o);
    }
    if ((tid & 31) == 0) { rs_[tid >> 5] = lsum; rq_[tid >> 5] = lsq; }
    __syncthreads();
    float s = 0.f, q = 0.f;
    #pragma unroll
    for (int w = 0; w < 8; w++) { s += rs_[w]; q += rq_[w]; }
    float mu   = s * (1.0f / Dd);
    float var  = q * (1.0f / Dd) - mu * mu;
    float rstd = rsqrtf(var + 1e-5f);

    float* xr = g_x + (size_t)token * Dd;
    for (int c = tid; c < Dd; c += 256) {
        float v = sx[c];
        xr[c] = v;
        float xn = (v - mu) * rstd * g1[c] + b1[c];
        float h = tf32_hi(xn);
        g_xnh[(size_t)token * Dd + c] = h;
        g_xnl[(size_t)token * Dd + c] = tf32_hi(xn - h);
    }
}

// ---------------- weight transposes (split to hi/lo) -------------------------
__global__ __launch_bounds__(256) void transpose_qkv_kernel(
    const float* __restrict__ Wq, const float* __restrict__ Wk,
    const float* __restrict__ Wv)
{
    __shared__ float tile[32][33];
    int z = blockIdx.z; int which = z >> 3, h = z & 7;
    const float* src = (which == 0 ? Wq : which == 1 ? Wk : Wv) + (size_t)h * Dd * HD;
    size_t dbase = (size_t)z * HD * Dd;
    int c0 = blockIdx.x * 32, d0 = blockIdx.y * 32;
    int tx = threadIdx.x, ty = threadIdx.y;
    #pragma unroll
    for (int j = 0; j < 32; j += 8)
        tile[ty + j][tx] = src[(size_t)(c0 + ty + j) * HD + d0 + tx];
    __syncthreads();
    #pragma unroll
    for (int j = 0; j < 32; j += 8) {
        float v = tile[tx][ty + j];
        float h2 = tf32_hi(v);
        size_t o = dbase + (size_t)(d0 + ty + j) * Dd + c0 + tx;
        g_wth[o] = h2;
        g_wtl[o] = tf32_hi(v - h2);
    }
}

__global__ __launch_bounds__(256) void transpose_wo_kernel(const float* __restrict__ Wo)
{
    __shared__ float tile[32][33];
    int k0 = blockIdx.x * 32, n0 = blockIdx.y * 32;
    int tx = threadIdx.x, ty = threadIdx.y;
    #pragma unroll
    for (int j = 0; j < 32; j += 8)
        tile[ty + j][tx] = Wo[(size_t)(k0 + ty + j) * Dd + n0 + tx];
    __syncthreads();
    #pragma unroll
    for (int j = 0; j < 32; j += 8) {
        float v = tile[tx][ty + j];
        float h2 = tf32_hi(v);
        size_t o = (size_t)(n0 + ty + j) * Dd + k0 + tx;
        g_woth[o] = h2;
        g_wotl[o] = tf32_hi(v - h2);
    }
}

// ---------------- 3xTF32 cp.async double-buffered GEMM core ------------------
// C[128x128] = A[128x1024] * B[128x1024]^T  (B stored [n][k]); operands pre-split
#define NCHUNK 32
#define LDP 36
#define STG_F (128 * LDP)                 // 4608 floats per array
#define STAGE_F (4 * STG_F)               // Ah, Al, Bh, Bl
#define GEMM_SMEM_BYTES (2 * STAGE_F * 4) // 147456

__device__ __forceinline__ void gemm_issue_chunk(
    uint32_t sbase, int stage, int c,
    const float* __restrict__ Ah_g, const float* __restrict__ Al_g,
    const float* __restrict__ Bh_g, const float* __restrict__ Bl_g, int tid)
{
    const float* srcs[4] = {Ah_g, Al_g, Bh_g, Bl_g};
    #pragma unroll
    for (int arr = 0; arr < 4; arr++) {
        #pragma unroll
        for (int p = 0; p < 4; p++) {
            int f = tid + p * 256;               // 0..1023 float4 slots
            int r = f >> 3, c4 = (f & 7) << 2;
            uint32_t sa = sbase + (uint32_t)(((stage * 4 + arr) * STG_F + r * LDP + c4) * 4);
            cp_async16(sa, srcs[arr] + (size_t)r * Dd + c * 32 + c4);
        }
    }
}

__device__ __forceinline__ void gemm3x_mainloop(
    const float* __restrict__ Ah_g, const float* __restrict__ Al_g,
    const float* __restrict__ Bh_g, const float* __restrict__ Bl_g,
    float acc[2][8][4], float* sm, int tid)
{
    uint32_t sbase = smem_to_u32(sm);
    int wid = tid >> 5, lane = tid & 31;
    int wm = (wid & 3) * 32, wn = (wid >> 2) * 64;
    int lr = lane >> 2, lc = lane & 3;

    gemm_issue_chunk(sbase, 0, 0, Ah_g, Al_g, Bh_g, Bl_g, tid);
    cp_commit();

    for (int c = 0; c < NCHUNK; c++) {
        if (c + 1 < NCHUNK) {
            gemm_issue_chunk(sbase, (c + 1) & 1, c + 1, Ah_g, Al_g, Bh_g, Bl_g, tid);
            cp_commit();
            cp_wait<1>();
        } else {
            cp_wait<0>();
        }
        __syncthreads();

        float* Ah = sm + ((c & 1) * 4 + 0) * STG_F;
        float* Al = sm + ((c & 1) * 4 + 1) * STG_F;
        float* Bh = sm + ((c & 1) * 4 + 2) * STG_F;
        float* Bl = sm + ((c & 1) * 4 + 3) * STG_F;

        #pragma unroll
        for (int k8 = 0; k8 < 4; k8++) {
            int k0 = k8 * 8;
            uint32_t ah[2][4], al[2][4];
            #pragma unroll
            for (int mt = 0; mt < 2; mt++) {
                int rb = (wm + mt * 16 + lr) * LDP + k0 + lc;
                ah[mt][0] = __float_as_uint(Ah[rb]);
                ah[mt][1] = __float_as_uint(Ah[rb + 8 * LDP]);
                ah[mt][2] = __float_as_uint(Ah[rb + 4]);
                ah[mt][3] = __float_as_uint(Ah[rb + 8 * LDP + 4]);
                al[mt][0] = __float_as_uint(Al[rb]);
                al[mt][1] = __float_as_uint(Al[rb + 8 * LDP]);
                al[mt][2] = __float_as_uint(Al[rb + 4]);
                al[mt][3] = __float_as_uint(Al[rb + 8 * LDP + 4]);
            }
            #pragma unroll
            for (int nt = 0; nt < 8; nt++) {
                int nb = (wn + nt * 8 + lr) * LDP + k0 + lc;
                uint32_t bh[2] = {__float_as_uint(Bh[nb]), __float_as_uint(Bh[nb + 4])};
                uint32_t bl[2] = {__float_as_uint(Bl[nb]), __float_as_uint(Bl[nb + 4])};
                #pragma unroll
                for (int mt = 0; mt < 2; mt++) {
                    mma_frag(acc[mt][nt], ah[mt], bh);
                    mma_frag(acc[mt][nt], ah[mt], bl);
                    mma_frag(acc[mt][nt], al[mt], bh);
                }
            }
        }
        __syncthreads();
    }
}

// ---------------- kernel 2: QKV via mma.sync (grid 64 x 24) ------------------
__global__ __launch_bounds__(256) void qkv_mma_kernel()
{
    extern __shared__ float sm[];
    int tid = threadIdx.x, wid = tid >> 5, lane = tid & 31;
    int m0 = blockIdx.x * 128;
    int z  = blockIdx.y;
    const float* Ah = g_xnh + (size_t)m0 * Dd;
    const float* Al = g_xnl + (size_t)m0 * Dd;
    const float* Bh = g_wth + (size_t)z * HD * Dd;
    const float* Bl = g_wtl + (size_t)z * HD * Dd;

    float acc[2][8][4];
    #pragma unroll
    for (int mt = 0; mt < 2; mt++)
        #pragma unroll
        for (int nt = 0; nt < 8; nt++)
            #pragma unroll
            for (int r = 0; r < 4; r++) acc[mt][nt][r] = 0.f;

    gemm3x_mainloop(Ah, Al, Bh, Bl, acc, sm, tid);

    int wm = (wid & 3) * 32, wn = (wid >> 2) * 64;
    int lr = lane >> 2, lc = lane & 3;
    int which = z >> 3, h = z & 7;
    float* Ob = (which == 0 ? g_q : which == 1 ? g_k : g_v);
    #pragma unroll
    for (int mt = 0; mt < 2; mt++) {
        int m = m0 + wm + mt * 16 + lr;
        int bb = m >> 11, tt = m & (Tt - 1);
        float* row0 = Ob + ((size_t)(bb * Hh + h) * Tt + tt) * HD + wn + lc * 2;
        #pragma unroll
        for (int nt = 0; nt < 8; nt++) {
            float* p0 = row0 + nt * 8;
            p0[0]          = acc[mt][nt][0];
            p0[1]          = acc[mt][nt][1];
            p0[8 * HD]     = acc[mt][nt][2];
            p0[8 * HD + 1] = acc[mt][nt][3];
        }
    }
}

// ---------------- kernel 4: proj + residual via mma.sync (grid 64 x 8) -------
__global__ __launch_bounds__(256) void proj_mma_kernel(const float* __restrict__ bo)
{
    extern __shared__ float sm[];
    int tid = threadIdx.x, wid = tid >> 5, lane = tid & 31;
    int m0 = blockIdx.x * 128;
    int n0 = blockIdx.y * 128;
    const float* Ah = g_atth + (size_t)m0 * Dd;
    const float* Al = g_attl + (size_t)m0 * Dd;
    const float* Bh = g_woth + (size_t)n0 * Dd;
    const float* Bl = g_wotl + (size_t)n0 * Dd;

    float acc[2][8][4];
    #pragma unroll
    for (int mt = 0; mt < 2; mt++)
        #pragma unroll
        for (int nt = 0; nt < 8; nt++)
            #pragma unroll
            for (int r = 0; r < 4; r++) acc[mt][nt][r] = 0.f;

    gemm3x_mainloop(Ah, Al, Bh, Bl, acc, sm, tid);

    int wm = (wid & 3) * 32, wn = (wid >> 2) * 64;
    int lr = lane >> 2, lc = lane & 3;
    #pragma unroll
    for (int mt = 0; mt < 2; mt++) {
        int m = m0 + wm + mt * 16 + lr;
        float* xrow = g_x + (size_t)m * Dd + n0 + wn + lc * 2;
        const float* brow = bo + n0 + wn + lc * 2;
        #pragma unroll
        for (int nt = 0; nt < 8; nt++) {
            float* p0 = xrow + nt * 8;
            const float* b0 = brow + nt * 8;
            p0[0]          += acc[mt][nt][0] + b0[0];
            p0[1]          += acc[mt][nt][1] + b0[1];
            p0[8 * Dd]     += acc[mt][nt][2] + b0[0];
            p0[8 * Dd + 1] += acc[mt][nt][3] + b0[1];
        }
    }
}

// ---------------- kernel 3: causal flash attention via 3xTF32 mma ------------
// Q tile 128 rows x KV tile 64. 256 threads, 8 warps; warp w owns rows [16w,16w+16).
#define AT_QP 132
#define AT_VP 68
#define AT_PP 68
#define ATT_SMEM_F (128*AT_QP + 64*AT_QP + 128*AT_VP + 128*AT_PP)   // 42752
__global__ __launch_bounds__(256) void attn_mma_kernel()
{
    extern __shared__ float smx[];
    float* Qs = smx;                        // [128][132] fp32 (scaled)
    float* Ks = Qs + 128 * AT_QP;           // [64][132]
    float* Vt = Ks + 64 * AT_QP;            // [128][68]  (d, s)
    float* Ps = Vt + 128 * AT_VP;           // [128][68]

    int bh = blockIdx.y, qt = blockIdx.x;
    int t0 = qt * 128;
    const float* Qg = g_q + (size_t)bh * TH;
    const float* Kg = g_k + (size_t)bh * TH;
    const float* Vg = g_v + (size_t)bh * TH;

    int tid = threadIdx.x, wid = tid >> 5, lane = tid & 31;
    int lr = lane >> 2, lc = lane & 3;
    const float scale = 0.03125f;           // D^-0.5

    // load Q tile (scaled): 128x128
    for (int i = tid; i < 128 * 32; i += 256) {
        int r = i >> 5, c4 = (i & 31) << 2;
        float4 qv = *(const float4*)&Qg[(size_t)(t0 + r) * HD + c4];
        qv.x *= scale; qv.y *= scale; qv.z *= scale; qv.w *= scale;
        *(float4*)&Qs[r * AT_QP + c4] = qv;
    }

    float o_acc[16][4];
    #pragma unroll
    for (int nt = 0; nt < 16; nt++)
        #pragma unroll
        for (int r = 0; r < 4; r++) o_acc[nt][r] = 0.f;
    float m_i[2] = {neg_inf(), neg_inf()};
    float l_i[2] = {0.f, 0.f};

    int row_w = t0 + 16 * wid;              // warp's first row
    int ntiles = 2 * (qt + 1);
    for (int j = 0; j < ntiles; j++) {
        int s0 = 64 * j;
        __syncthreads();                    // Ks/Vt reuse guard
        for (int i = tid; i < 64 * 32; i += 256) {
            int s = i >> 5, d4 = (i & 31) << 2;
            float4 kv = *(const float4*)&Kg[(size_t)(s0 + s) * HD + d4];
            *(float4*)&Ks[s * AT_QP + d4] = kv;
            float4 vv = *(const float4*)&Vg[(size_t)(s0 + s) * HD + d4];
            Vt[(d4 + 0) * AT_VP + s] = vv.x;
            Vt[(d4 + 1) * AT_VP + s] = vv.y;
            Vt[(d4 + 2) * AT_VP + s] = vv.z;
            Vt[(d4 + 3) * AT_VP + s] = vv.w;
        }
        __syncthreads();

        if (s0 > row_w + 15) continue;      // fully masked for this warp

        // ---- S = Q K^T (16 x 64), 3xTF32 ----
        float sacc[8][4];
        #pragma unroll
        for (int nt = 0; nt < 8; nt++)
            #pragma unroll
            for (int r = 0; r < 4; r++) sacc[nt][r] = 0.f;

        #pragma unroll 4
        for (int k8 = 0; k8 < 16; k8++) {
            int k0 = k8 * 8;
            int rb = (16 * wid + lr) * AT_QP + k0 + lc;
            uint32_t ah[4], al[4];
            split2(Qs[rb],                 ah[0], al[0]);
            split2(Qs[rb + 8 * AT_QP],     ah[1], al[1]);
            split2(Qs[rb + 4],             ah[2], al[2]);
            split2(Qs[rb + 8 * AT_QP + 4], ah[3], al[3]);
            #pragma unroll
            for (int nt = 0; nt < 8; nt++) {
                int nb = (8 * nt + lr) * AT_QP + k0 + lc;
                uint32_t bh[2], bl[2];
                split2(Ks[nb],     bh[0], bl[0]);
                split2(Ks[nb + 4], bh[1], bl[1]);
                mma_frag(sacc[nt], ah, bh);
                mma_frag(sacc[nt], ah, bl);
                mma_frag(sacc[nt], al, bh);
            }
        }

        // ---- causal mask ----
        if (s0 + 63 > row_w) {
            int r0 = row_w + lr;
            #pragma unroll
            for (int nt = 0; nt < 8; nt++) {
                int cb = s0 + 8 * nt + 2 * lc;
                if (cb     > r0)     sacc[nt][0] = neg_inf();
                if (cb + 1 > r0)     sacc[nt][1] = neg_inf();
                if (cb     > r0 + 8) sacc[nt][2] = neg_inf();
                if (cb + 1 > r0 + 8) sacc[nt][3] = neg_inf();
            }
        }

        // ---- online softmax (rows lr and lr+8, warp-local via quad shfl) ----
        float rm0 = neg_inf(), rm1 = neg_inf();
        #pragma unroll
        for (int nt = 0; nt < 8; nt++) {
            rm0 = fmaxf(rm0, fmaxf(sacc[nt][0], sacc[nt][1]));
            rm1 = fmaxf(rm1, fmaxf(sacc[nt][2], sacc[nt][3]));
        }
        rm0 = fmaxf(rm0, __shfl_xor_sync(0xffffffffu, rm0, 1));
        rm0 = fmaxf(rm0, __shfl_xor_sync(0xffffffffu, rm0, 2));
        rm1 = fmaxf(rm1, __shfl_xor_sync(0xffffffffu, rm1, 1));
        rm1 = fmaxf(rm1, __shfl_xor_sync(0xffffffffu, rm1, 2));
        float mn0 = fmaxf(m_i[0], rm0), mn1 = fmaxf(m_i[1], rm1);
        float al0 = expf(m_i[0] - mn0), al1 = expf(m_i[1] - mn1);
        float rs0 = 0.f, rs1 = 0.f;
        #pragma unroll
        for (int nt = 0; nt < 8; nt++) {
            sacc[nt][0] = expf(sacc[nt][0] - mn0);
            sacc[nt][1] = expf(sacc[nt][1] - mn0);
            sacc[nt][2] = expf(sacc[nt][2] - mn1);
            sacc[nt][3] = expf(sacc[nt][3] - mn1);
            rs0 += sacc[nt][0] + sacc[nt][1];
            rs1 += sacc[nt][2] + sacc[nt][3];
        }
        rs0 += __shfl_xor_sync(0xffffffffu, rs0, 1);
        rs0 += __shfl_xor_sync(0xffffffffu, rs0, 2);
        rs1 += __shfl_xor_sync(0xffffffffu, rs1, 1);
        rs1 += __shfl_xor_sync(0xffffffffu, rs1, 2);
        l_i[0] = l_i[0] * al0 + rs0;  m_i[0] = mn0;
        l_i[1] = l_i[1] * al1 + rs1;  m_i[1] = mn1;
        #pragma unroll
        for (int nt = 0; nt < 16; nt++) {
            o_acc[nt][0] *= al0; o_acc[nt][1] *= al0;
            o_acc[nt][2] *= al1; o_acc[nt][3] *= al1;
        }
        // store P to smem (warp-private rows)
        #pragma unroll
        for (int nt = 0; nt < 8; nt++) {
            *(float2*)&Ps[(16 * wid + lr) * AT_PP + 8 * nt + 2 * lc] =
                make_float2(sacc[nt][0], sacc[nt][1]);
            *(float2*)&Ps[(16 * wid + lr + 8) * AT_PP + 8 * nt + 2 * lc] =
                make_float2(sacc[nt][2], sacc[nt][3]);
        }
        __syncwarp();

        // ---- O += P V (16 x 128), 3xTF32 ----
        #pragma unroll 2
        for (int k8 = 0; k8 < 8; k8++) {
            int k0 = k8 * 8;
            int pb = (16 * wid + lr) * AT_PP + k0 + lc;
            uint32_t ah[4], al[4];
            split2(Ps[pb],                 ah[0], al[0]);
            split2(Ps[pb + 8 * AT_PP],     ah[1], al[1]);
            split2(Ps[pb + 4],             ah[2], al[2]);
            split2(Ps[pb + 8 * AT_PP + 4], ah[3], al[3]);
            #pragma unroll
            for (int nt = 0; nt < 16; nt++) {
                int vb = (8 * nt + lr) * AT_VP + k0 + lc;
                uint32_t bh[2], bl[2];
                split2(Vt[vb],     bh[0], bl[0]);
                split2(Vt[vb + 4], bh[1], bl[1]);
                mma_frag(o_acc[nt], ah, bh);
                mma_frag(o_acc[nt], ah, bl);
                mma_frag(o_acc[nt], al, bh);
            }
        }
        __syncwarp();
    }

    // ---- epilogue: write split attention output [B, T, H*HD] ----
    float inv0 = 1.0f / l_i[0], inv1 = 1.0f / l_i[1];
    int bb = bh >> 3, h = bh & 7;
    int r0 = row_w + lr;
    size_t base0 = ((size_t)(bb * Tt + r0)) * Dd + h * HD;
    size_t base1 = ((size_t)(bb * Tt + r0 + 8)) * Dd + h * HD;
    #pragma unroll
    for (int nt = 0; nt < 16; nt++) {
        int col = 8 * nt + 2 * lc;
        float v0 = o_acc[nt][0] * inv0, v1 = o_acc[nt][1] * inv0;
        float v2 = o_acc[nt][2] * inv1, v3 = o_acc[nt][3] * inv1;
        float h0 = tf32_hi(v0), h1 = tf32_hi(v1);
        float h2 = tf32_hi(v2), h3 = tf32_hi(v3);
        *(float2*)&g_atth[base0 + col] = make_float2(h0, h1);
        *(float2*)&g_attl[base0 + col] = make_float2(tf32_hi(v0 - h0), tf32_hi(v1 - h1));
        *(float2*)&g_atth[base1 + col] = make_float2(h2, h3);
        *(float2*)&g_attl[base1 + col] = make_float2(tf32_hi(v2 - h2), tf32_hi(v3 - h3));
    }
}

// ---------------- kernel 5: LayerNorm2 + noisy top-2 router + outputs --------
#define OUT_OFF_PROBS (BT * Dd)
#define OUT_OFF_IDX   (OUT_OFF_PROBS + BT * Ee)
#define OUT_OFF_X     (OUT_OFF_IDX + BT * 2)
__global__ __launch_bounds__(256) void ln2_router_kernel(
    const float* __restrict__ g2, const float* __restrict__ b2,
    const float* __restrict__ Wr, const float* __restrict__ br,
    const float* __restrict__ Wn, const float* __restrict__ bn,
    float* __restrict__ out)
{
    int token = blockIdx.x;
    int tid = threadIdx.x;
    __shared__ float sxn[Dd];
    __shared__ float rs_[8], rq_[8];
    __shared__ float red[8][16];

    const float* xr = g_x + (size_t)token * Dd;
    float lsum = 0.f, lsq = 0.f;
    for (int c = tid; c < Dd; c += 256) {
        float v = xr[c];
        sxn[c] = v;
        out[OUT_OFF_X + (size_t)token * Dd + c] = v;
        lsum += v; lsq += v * v;
    }
    #pragma unroll
    for (int o = 16; o; o >>= 1) {
        lsum += __shfl_xor_sync(0xffffffffu, lsum, o);
        lsq  += __shfl_xor_sync(0xffffffffu, lsq,  o);
    }
    if ((tid & 31) == 0) { rs_[tid >> 5] = lsum; rq_[tid >> 5] = lsq; }
    __syncthreads();
    float s = 0.f, q = 0.f;
    #pragma unroll
    for (int w = 0; w < 8; w++) { s += rs_[w]; q += rq_[w]; }
    float mu   = s * (1.0f / Dd);
    float var  = q * (1.0f / Dd) - mu * mu;
    float rstd = rsqrtf(var + 1e-5f);

    for (int c = tid; c < Dd; c += 256) {
        float v  = sxn[c];
        float xn = (v - mu) * rstd * g2[c] + b2[c];
        sxn[c] = xn;
        out[(size_t)token * Dd + c] = xn;
    }
    __syncthreads();

    float ar[8] = {}, an_[8] = {};
    for (int c = tid; c < Dd; c += 256) {
        float v = sxn[c];
        float4 w0 = *(const float4*)&Wr[(size_t)c * Ee];
        float4 w1 = *(const float4*)&Wr[(size_t)c * Ee + 4];
        ar[0] += v * w0.x; ar[1] += v * w0.y; ar[2] += v * w0.z; ar[3] += v * w0.w;
        ar[4] += v * w1.x; ar[5] += v * w1.y; ar[6] += v * w1.z; ar[7] += v * w1.w;
        float4 n0 = *(const float4*)&Wn[(size_t)c * Ee];
        float4 n1 = *(const float4*)&Wn[(size_t)c * Ee + 4];
        an_[0] += v * n0.x; an_[1] += v * n0.y; an_[2] += v * n0.z; an_[3] += v * n0.w;
        an_[4] += v * n1.x; an_[5] += v * n1.y; an_[6] += v * n1.z; an_[7] += v * n1.w;
    }
    #pragma unroll
    for (int o = 16; o; o >>= 1) {
        #pragma unroll
        for (int e = 0; e < 8; e++) {
            ar[e]  += __shfl_xor_sync(0xffffffffu, ar[e],  o);
            an_[e] += __shfl_xor_sync(0xffffffffu, an_[e], o);
        }
    }
    int w = tid >> 5;
    if ((tid & 31) == 0) {
        #pragma unroll
        for (int e = 0; e < 8; e++) { red[w][e] = ar[e]; red[w][8 + e] = an_[e]; }
    }
    __syncthreads();

    if (tid == 0) {
        float lg[8], nl[8];
        #pragma unroll
        for (int e = 0; e < 8; e++) { lg[e] = br[e]; nl[e] = bn[e]; }
        for (int ww = 0; ww < 8; ww++)
            #pragma unroll
            for (int e = 0; e < 8; e++) { lg[e] += red[ww][e]; nl[e] += red[ww][8 + e]; }

        float noisy[8];
        #pragma unroll
        for (int e = 0; e < 8; e++) {
            float nz = jax_noise((uint32_t)(token * Ee + e));
            noisy[e] = lg[e] + nz * softplus_f(nl[e]);
        }
        int i0 = 0; float v0 = noisy[0];
        #pragma unroll
        for (int e = 1; e < 8; e++) if (noisy[e] > v0) { v0 = noisy[e]; i0 = e; }
        int i1 = -1; float v1 = neg_inf();
        #pragma unroll
        for (int e = 0; e < 8; e++)
            if (e != i0 && noisy[e] > v1) { v1 = noisy[e]; i1 = e; }

        float e1 = expf(v1 - v0);
        float inv = 1.0f / (1.0f + e1);
        float p0 = inv, p1 = e1 * inv;

        float probs[8] = {};
        probs[i0] = p0; probs[i1] = p1;
        float* pout = out + OUT_OFF_PROBS + (size_t)token * Ee;
        #pragma unroll
        for (int e = 0; e < 8; e++) pout[e] = probs[e];
        out[OUT_OFF_IDX + (size_t)token * 2 + 0] = (float)i0;
        out[OUT_OFF_IDX + (size_t)token * 2 + 1] = (float)i1;
    }
}

// ---------------- launcher ---------------------------------------------------
extern "C" void kernel_launch(void* const* d_in, const int* in_sizes, int n_in,
                              void* d_out, int out_size)
{
    const int*   idx = (const int*)  d_in[0];
    const float* tok = (const float*)d_in[1];
    const float* pos = (const float*)d_in[2];
    const float* Wq  = (const float*)d_in[3];
    const float* Wk  = (const float*)d_in[4];
    const float* Wv  = (const float*)d_in[5];
    const float* Wo  = (const float*)d_in[6];
    const float* bo  = (const float*)d_in[7];
    const float* g1  = (const float*)d_in[8];
    const float* b1  = (const float*)d_in[9];
    const float* g2  = (const float*)d_in[10];
    const float* b2  = (const float*)d_in[11];
    const float* Wr  = (const float*)d_in[12];
    const float* br  = (const float*)d_in[13];
    const float* Wn  = (const float*)d_in[14];
    const float* bn  = (const float*)d_in[15];
    float* out = (float*)d_out;

    cudaFuncSetAttribute(attn_mma_kernel, cudaFuncAttributeMaxDynamicSharedMemorySize,
                         ATT_SMEM_F * (int)sizeof(float));
    cudaFuncSetAttribute(qkv_mma_kernel, cudaFuncAttributeMaxDynamicSharedMemorySize,
                         GEMM_SMEM_BYTES);
    cudaFuncSetAttribute(proj_mma_kernel, cudaFuncAttributeMaxDynamicSharedMemorySize,
                         GEMM_SMEM_BYTES);

    embed_ln_kernel<<<BT, 256>>>(idx, tok, pos, g1, b1);
    transpose_qkv_kernel<<<dim3(32, 4, 24), dim3(32, 8)>>>(Wq, Wk, Wv);
    transpose_wo_kernel<<<dim3(32, 32), dim3(32, 8)>>>(Wo);
    qkv_mma_kernel<<<dim3(BT / 128, 24), 256, GEMM_SMEM_BYTES>>>();
    attn_mma_kernel<<<dim3(Tt / 128, Bb * Hh), 256, ATT_SMEM_F * sizeof(float)>>>();
    proj_mma_kernel<<<dim3(BT / 128, Dd / 128), 256, GEMM_SMEM_BYTES>>>(bo);
    ln2_router_kernel<<<BT, 256>>>(g2, b2, Wr, br, Wn, bn, out);
}

// round 8
// speedup vs baseline: 1.7017x; 1.1589x over previous
#include <cuda_runtime.h>
#include <cstdint>

// Problem dims
#define Bb 4
#define Tt 2048
#define Dd 1024
#define Hh 8
#define HD 128
#define Ee 8
#define BT 8192            // Bb*Tt
#define TH (Tt*HD)         // 262144

// ---------------- scratch (device globals; no allocations allowed) ----------
__device__ float g_x   [BT*Dd];   // running residual x
__device__ float g_xnh [BT*Dd];   // LN1(x) tf32 hi
__device__ float g_xnl [BT*Dd];   // LN1(x) tf32 lo
__device__ float g_q   [BT*Dd];   // [B,H,T,HD]
__device__ float g_k   [BT*Dd];
__device__ float g_v   [BT*Dd];
__device__ float g_atth[BT*Dd];   // attention out hi  [B,T,H*HD]
__device__ float g_attl[BT*Dd];   // attention out lo
__device__ float g_wth [3*Hh*HD*Dd];  // transposed QKV weights hi  [z][d][c]
__device__ float g_wtl [3*Hh*HD*Dd];
__device__ float g_woth[Dd*Dd];       // Wo^T hi [n][k]
__device__ float g_wotl[Dd*Dd];

__device__ __forceinline__ float neg_inf() { return __int_as_float(0xff800000); }

// tf32 round-to-nearest (base PTX, sm_80+)
__device__ __forceinline__ float tf32_hi(float a) {
    uint32_t r; asm("cvt.rna.tf32.f32 %0, %1;" : "=r"(r) : "f"(a));
    return __uint_as_float(r);
}
__device__ __forceinline__ void split2(float v, uint32_t& h, uint32_t& l) {
    float hf = tf32_hi(v);
    h = __float_as_uint(hf);
    l = __float_as_uint(tf32_hi(v - hf));
}

// m16n8k8 tf32 MMA (base PTX, sm_80+): D += A * B
__device__ __forceinline__ void mma_frag(float* d, const uint32_t* a, const uint32_t* b) {
    asm volatile("mma.sync.aligned.m16n8k8.row.col.f32.tf32.tf32.f32 "
        "{%0,%1,%2,%3}, {%4,%5,%6,%7}, {%8,%9}, {%0,%1,%2,%3};"
        : "+f"(d[0]), "+f"(d[1]), "+f"(d[2]), "+f"(d[3])
        : "r"(a[0]), "r"(a[1]), "r"(a[2]), "r"(a[3]), "r"(b[0]), "r"(b[1]));
}

// cp.async (base PTX, sm_80+)
__device__ __forceinline__ uint32_t smem_to_u32(const void* p) {
    uint32_t a;
    asm("{ .reg .u64 t; cvta.to.shared.u64 t, %1; cvt.u32.u64 %0, t; }" : "=r"(a) : "l"(p));
    return a;
}
__device__ __forceinline__ void cp_async16(uint32_t saddr, const void* gaddr) {
    asm volatile("cp.async.cg.shared.global [%0], [%1], 16;" :: "r"(saddr), "l"(gaddr));
}
__device__ __forceinline__ void cp_commit() { asm volatile("cp.async.commit_group;" ::: "memory"); }
template<int N> __device__ __forceinline__ void cp_wait() {
    asm volatile("cp.async.wait_group %0;" :: "n"(N) : "memory");
}

// ---------------- JAX threefry2x32 noise (partitionable scheme) --------------
__device__ __forceinline__ uint32_t rotl32(uint32_t v, int r) {
    return (v << r) | (v >> (32 - r));
}
__device__ float jax_noise(uint32_t i) {
    uint32_t x0 = 0u, x1 = i;
    const uint32_t k0 = 0u, k1 = 42u, k2 = 0u ^ 42u ^ 0x1BD11BDAu;
    x0 += k0; x1 += k1;
#define TF_ROUND(r) { x0 += x1; x1 = rotl32(x1, r); x1 ^= x0; }
#define TF_G0 TF_ROUND(13) TF_ROUND(15) TF_ROUND(26) TF_ROUND(6)
#define TF_G1 TF_ROUND(17) TF_ROUND(29) TF_ROUND(16) TF_ROUND(24)
    TF_G0; x0 += k1; x1 += k2 + 1u;
    TF_G1; x0 += k2; x1 += k0 + 2u;
    TF_G0; x0 += k0; x1 += k1 + 3u;
    TF_G1; x0 += k1; x1 += k2 + 4u;
    TF_G0; x0 += k2; x1 += k0 + 5u;
#undef TF_G1
#undef TF_G0
#undef TF_ROUND
    uint32_t bits = x0 ^ x1;
    float f = __uint_as_float((bits >> 9) | 0x3f800000u) - 1.0f;
    const float lo = -0.99999994f;
    float u = f * (1.0f - lo) + lo;
    u = fmaxf(u, lo);
    return 1.41421354f * erfinvf(u);
}
__device__ __forceinline__ float softplus_f(float x) {
    return fmaxf(x, 0.0f) + log1pf(expf(-fabsf(x)));
}

// ---------------- kernel 1: embedding + LayerNorm1 (writes split xn) ---------
__global__ __launch_bounds__(256) void embed_ln_kernel(
    const int* __restrict__ idx, const float* __restrict__ tok,
    const float* __restrict__ pos, const float* __restrict__ g1,
    const float* __restrict__ b1)
{
    int token = blockIdx.x;
    int t     = token & (Tt - 1);
    int tid   = threadIdx.x;
    __shared__ float sx[Dd];
    __shared__ float rs_[8], rq_[8];

    const float* trow = tok + (size_t)idx[token] * Dd;
    const float* prow = pos + (size_t)t * Dd;

    float lsum = 0.f, lsq = 0.f;
    for (int c = tid; c < Dd; c += 256) {
        float v = trow[c] + prow[c];
        sx[c] = v; lsum += v; lsq += v * v;
    }
    #pragma unroll
    for (int o = 16; o; o >>= 1) {
        lsum += __shfl_xor_sync(0xffffffffu, lsum, o);
        lsq  += __shfl_xor_sync(0xffffffffu, lsq,  o);
    }
    if ((tid & 31) == 0) { rs_[tid >> 5] = lsum; rq_[tid >> 5] = lsq; }
    __syncthreads();
    float s = 0.f, q = 0.f;
    #pragma unroll
    for (int w = 0; w < 8; w++) { s += rs_[w]; q += rq_[w]; }
    float mu   = s * (1.0f / Dd);
    float var  = q * (1.0f / Dd) - mu * mu;
    float rstd = rsqrtf(var + 1e-5f);

    float* xr = g_x + (size_t)token * Dd;
    for (int c = tid; c < Dd; c += 256) {
        float v = sx[c];
        xr[c] = v;
        float xn = (v - mu) * rstd * g1[c] + b1[c];
        float h = tf32_hi(xn);
        g_xnh[(size_t)token * Dd + c] = h;
        g_xnl[(size_t)token * Dd + c] = tf32_hi(xn - h);
    }
}

// ---------------- weight transposes (split to hi/lo) -------------------------
__global__ __launch_bounds__(256) void transpose_qkv_kernel(
    const float* __restrict__ Wq, const float* __restrict__ Wk,
    const float* __restrict__ Wv)
{
    __shared__ float tile[32][33];
    int z = blockIdx.z; int which = z >> 3, h = z & 7;
    const float* src = (which == 0 ? Wq : which == 1 ? Wk : Wv) + (size_t)h * Dd * HD;
    size_t dbase = (size_t)z * HD * Dd;
    int c0 = blockIdx.x * 32, d0 = blockIdx.y * 32;
    int tx = threadIdx.x, ty = threadIdx.y;
    #pragma unroll
    for (int j = 0; j < 32; j += 8)
        tile[ty + j][tx] = src[(size_t)(c0 + ty + j) * HD + d0 + tx];
    __syncthreads();
    #pragma unroll
    for (int j = 0; j < 32; j += 8) {
        float v = tile[tx][ty + j];
        float h2 = tf32_hi(v);
        size_t o = dbase + (size_t)(d0 + ty + j) * Dd + c0 + tx;
        g_wth[o] = h2;
        g_wtl[o] = tf32_hi(v - h2);
    }
}

__global__ __launch_bounds__(256) void transpose_wo_kernel(const float* __restrict__ Wo)
{
    __shared__ float tile[32][33];
    int k0 = blockIdx.x * 32, n0 = blockIdx.y * 32;
    int tx = threadIdx.x, ty = threadIdx.y;
    #pragma unroll
    for (int j = 0; j < 32; j += 8)
        tile[ty + j][tx] = Wo[(size_t)(k0 + ty + j) * Dd + n0 + tx];
    __syncthreads();
    #pragma unroll
    for (int j = 0; j < 32; j += 8) {
        float v = tile[tx][ty + j];
        float h2 = tf32_hi(v);
        size_t o = (size_t)(n0 + ty + j) * Dd + k0 + tx;
        g_woth[o] = h2;
        g_wotl[o] = tf32_hi(v - h2);
    }
}

// ---------------- 3xTF32 cp.async double-buffered GEMM core ------------------
// C[256x128] = A[256x1024] * B[128x1024]^T  (B stored [n][k]); operands pre-split
// 512 threads (16 warps, 8x2); warp tile 32x64; K-chunk 32, 2 stages.
#define NCHUNK 32
#define LDP 36
#define A_F (256 * LDP)                    // 9216 floats
#define B_F (128 * LDP)                    // 4608
#define STAGE_F (2 * A_F + 2 * B_F)        // 27648
#define GEMM_SMEM_BYTES (2 * STAGE_F * 4)  // 221184

__device__ __forceinline__ void gemm_issue_chunk(
    uint32_t sbase, int stage, int c,
    const float* __restrict__ Ah_g, const float* __restrict__ Al_g,
    const float* __restrict__ Bh_g, const float* __restrict__ Bl_g, int tid)
{
    uint32_t sb = sbase + (uint32_t)(stage * STAGE_F * 4);
    #pragma unroll
    for (int p = 0; p < 4; p++) {
        int f = tid + p * 512;                 // A: 2048 float4 slots
        int r = f >> 3, c4 = (f & 7) << 2;
        uint32_t off = (uint32_t)((r * LDP + c4) * 4);
        size_t go = (size_t)r * Dd + c * 32 + c4;
        cp_async16(sb + off,           Ah_g + go);
        cp_async16(sb + A_F * 4 + off, Al_g + go);
    }
    #pragma unroll
    for (int p = 0; p < 2; p++) {
        int f = tid + p * 512;                 // B: 1024 float4 slots
        int r = f >> 3, c4 = (f & 7) << 2;
        uint32_t off = (uint32_t)((r * LDP + c4) * 4);
        size_t go = (size_t)r * Dd + c * 32 + c4;
        cp_async16(sb + 2 * A_F * 4 + off,           Bh_g + go);
        cp_async16(sb + 2 * A_F * 4 + B_F * 4 + off, Bl_g + go);
    }
}

__device__ __forceinline__ void gemm3x_mainloop(
    const float* __restrict__ Ah_g, const float* __restrict__ Al_g,
    const float* __restrict__ Bh_g, const float* __restrict__ Bl_g,
    float acc[2][8][4], float* sm, int tid)
{
    uint32_t sbase = smem_to_u32(sm);
    int wid = tid >> 5, lane = tid & 31;
    int wm = (wid & 7) * 32, wn = (wid >> 3) * 64;
    int lr = lane >> 2, lc = lane & 3;

    gemm_issue_chunk(sbase, 0, 0, Ah_g, Al_g, Bh_g, Bl_g, tid);
    cp_commit();

    for (int c = 0; c < NCHUNK; c++) {
        if (c + 1 < NCHUNK) {
            gemm_issue_chunk(sbase, (c + 1) & 1, c + 1, Ah_g, Al_g, Bh_g, Bl_g, tid);
            cp_commit();
            cp_wait<1>();
        } else {
            cp_wait<0>();
        }
        __syncthreads();

        float* Ah = sm + (c & 1) * STAGE_F;
        float* Al = Ah + A_F;
        float* Bh = Ah + 2 * A_F;
        float* Bl = Bh + B_F;

        #pragma unroll
        for (int k8 = 0; k8 < 4; k8++) {
            int k0 = k8 * 8;
            uint32_t ah[2][4], al[2][4];
            #pragma unroll
            for (int mt = 0; mt < 2; mt++) {
                int rb = (wm + mt * 16 + lr) * LDP + k0 + lc;
                ah[mt][0] = __float_as_uint(Ah[rb]);
                ah[mt][1] = __float_as_uint(Ah[rb + 8 * LDP]);
                ah[mt][2] = __float_as_uint(Ah[rb + 4]);
                ah[mt][3] = __float_as_uint(Ah[rb + 8 * LDP + 4]);
                al[mt][0] = __float_as_uint(Al[rb]);
                al[mt][1] = __float_as_uint(Al[rb + 8 * LDP]);
                al[mt][2] = __float_as_uint(Al[rb + 4]);
                al[mt][3] = __float_as_uint(Al[rb + 8 * LDP + 4]);
            }
            #pragma unroll
            for (int nt = 0; nt < 8; nt++) {
                int nb = (wn + nt * 8 + lr) * LDP + k0 + lc;
                uint32_t bh[2] = {__float_as_uint(Bh[nb]), __float_as_uint(Bh[nb + 4])};
                uint32_t bl[2] = {__float_as_uint(Bl[nb]), __float_as_uint(Bl[nb + 4])};
                #pragma unroll
                for (int mt = 0; mt < 2; mt++) {
                    mma_frag(acc[mt][nt], ah[mt], bh);
                    mma_frag(acc[mt][nt], ah[mt], bl);
                    mma_frag(acc[mt][nt], al[mt], bh);
                }
            }
        }
        __syncthreads();
    }
}

// ---------------- kernel 2: QKV via mma.sync (grid 32 x 24, 512 thr) ---------
__global__ __launch_bounds__(512, 1) void qkv_mma_kernel()
{
    extern __shared__ float sm[];
    int tid = threadIdx.x, wid = tid >> 5, lane = tid & 31;
    int m0 = blockIdx.x * 256;
    int z  = blockIdx.y;
    const float* Ah = g_xnh + (size_t)m0 * Dd;
    const float* Al = g_xnl + (size_t)m0 * Dd;
    const float* Bh = g_wth + (size_t)z * HD * Dd;
    const float* Bl = g_wtl + (size_t)z * HD * Dd;

    float acc[2][8][4];
    #pragma unroll
    for (int mt = 0; mt < 2; mt++)
        #pragma unroll
        for (int nt = 0; nt < 8; nt++)
            #pragma unroll
            for (int r = 0; r < 4; r++) acc[mt][nt][r] = 0.f;

    gemm3x_mainloop(Ah, Al, Bh, Bl, acc, sm, tid);

    int wm = (wid & 7) * 32, wn = (wid >> 3) * 64;
    int lr = lane >> 2, lc = lane & 3;
    int which = z >> 3, h = z & 7;
    float* Ob = (which == 0 ? g_q : which == 1 ? g_k : g_v);
    #pragma unroll
    for (int mt = 0; mt < 2; mt++) {
        int m = m0 + wm + mt * 16 + lr;
        int bb = m >> 11, tt = m & (Tt - 1);
        float* row0 = Ob + ((size_t)(bb * Hh + h) * Tt + tt) * HD + wn + lc * 2;
        #pragma unroll
        for (int nt = 0; nt < 8; nt++) {
            float* p0 = row0 + nt * 8;
            p0[0]          = acc[mt][nt][0];
            p0[1]          = acc[mt][nt][1];
            p0[8 * HD]     = acc[mt][nt][2];
            p0[8 * HD + 1] = acc[mt][nt][3];
        }
    }
}

// ---------------- kernel 4: proj + residual (grid 32 x 8, 512 thr) -----------
__global__ __launch_bounds__(512, 1) void proj_mma_kernel(const float* __restrict__ bo)
{
    extern __shared__ float sm[];
    int tid = threadIdx.x, wid = tid >> 5, lane = tid & 31;
    int m0 = blockIdx.x * 256;
    int n0 = blockIdx.y * 128;
    const float* Ah = g_atth + (size_t)m0 * Dd;
    const float* Al = g_attl + (size_t)m0 * Dd;
    const float* Bh = g_woth + (size_t)n0 * Dd;
    const float* Bl = g_wotl + (size_t)n0 * Dd;

    float acc[2][8][4];
    #pragma unroll
    for (int mt = 0; mt < 2; mt++)
        #pragma unroll
        for (int nt = 0; nt < 8; nt++)
            #pragma unroll
            for (int r = 0; r < 4; r++) acc[mt][nt][r] = 0.f;

    gemm3x_mainloop(Ah, Al, Bh, Bl, acc, sm, tid);

    int wm = (wid & 7) * 32, wn = (wid >> 3) * 64;
    int lr = lane >> 2, lc = lane & 3;
    #pragma unroll
    for (int mt = 0; mt < 2; mt++) {
        int m = m0 + wm + mt * 16 + lr;
        float* xrow = g_x + (size_t)m * Dd + n0 + wn + lc * 2;
        const float* brow = bo + n0 + wn + lc * 2;
        #pragma unroll
        for (int nt = 0; nt < 8; nt++) {
            float* p0 = xrow + nt * 8;
            const float* b0 = brow + nt * 8;
            p0[0]          += acc[mt][nt][0] + b0[0];
            p0[1]          += acc[mt][nt][1] + b0[1];
            p0[8 * Dd]     += acc[mt][nt][2] + b0[0];
            p0[8 * Dd + 1] += acc[mt][nt][3] + b0[1];
        }
    }
}

// ---------------- kernel 3: causal flash attention, pre-split K/V ------------
// Q tile 128 x KV tile 64; 256 thr, 8 warps; warp w owns rows [16w,16w+16).
// smem: Qs fp32 [128][132]; Kh/Kl [64][132] (P [128][68] aliases); Vh/Vl [128][68]
#define AQ_P 132
#define AK_P 132
#define AV_P 68
#define AP_P 68
#define OFF_KH 16896
#define OFF_KL 25344
#define OFF_P  16896
#define OFF_VH 33792
#define OFF_VL 42496
#define ATT_SMEM_F 51200   // 204800 B
__global__ __launch_bounds__(256) void attn_mma_kernel()
{
    extern __shared__ float smx[];
    float* Qs = smx;
    float* Kh = smx + OFF_KH;
    float* Kl = smx + OFF_KL;
    float* Ps = smx + OFF_P;     // aliases Kh/Kl region (guarded by barrier)
    float* Vh = smx + OFF_VH;
    float* Vl = smx + OFF_VL;

    int bh = blockIdx.y, qt = blockIdx.x;
    int t0 = qt * 128;
    const float* Qg = g_q + (size_t)bh * TH;
    const float* Kg = g_k + (size_t)bh * TH;
    const float* Vg = g_v + (size_t)bh * TH;

    int tid = threadIdx.x, wid = tid >> 5, lane = tid & 31;
    int lr = lane >> 2, lc = lane & 3;
    const float scale = 0.03125f;

    // Q tile (scaled fp32)
    #pragma unroll 4
    for (int i = tid; i < 128 * 32; i += 256) {
        int r = i >> 5, c4 = (i & 31) << 2;
        float4 qv = *(const float4*)&Qg[(size_t)(t0 + r) * HD + c4];
        qv.x *= scale; qv.y *= scale; qv.z *= scale; qv.w *= scale;
        *(float4*)&Qs[r * AQ_P + c4] = qv;
    }

    float o_acc[16][4];
    #pragma unroll
    for (int nt = 0; nt < 16; nt++)
        #pragma unroll
        for (int r = 0; r < 4; r++) o_acc[nt][r] = 0.f;
    float m_i[2] = {neg_inf(), neg_inf()};
    float l_i[2] = {0.f, 0.f};

    int row_w = t0 + 16 * wid;
    int ntiles = 2 * (qt + 1);
    for (int j = 0; j < ntiles; j++) {
        int s0 = 64 * j;
        __syncthreads();                 // prior PV (P,V readers) done
        // K tile: split hi/lo, layout [s][d]
        #pragma unroll
        for (int p = 0; p < 8; p++) {
            int i = tid + p * 256;
            int s = i >> 5, d4 = (i & 31) << 2;
            float4 kv = *(const float4*)&Kg[(size_t)(s0 + s) * HD + d4];
            float4 h, l;
            h.x = tf32_hi(kv.x); l.x = tf32_hi(kv.x - h.x);
            h.y = tf32_hi(kv.y); l.y = tf32_hi(kv.y - h.y);
            h.z = tf32_hi(kv.z); l.z = tf32_hi(kv.z - h.z);
            h.w = tf32_hi(kv.w); l.w = tf32_hi(kv.w - h.w);
            *(float4*)&Kh[s * AK_P + d4] = h;
            *(float4*)&Kl[s * AK_P + d4] = l;
        }
        // V tile: split hi/lo, transposed [d][s]
        #pragma unroll
        for (int p = 0; p < 8; p++) {
            int i = tid + p * 256;
            int dq = i & 3, sg = (i >> 2) & 7, blk = i >> 5;
            int s = (blk & 7) * 8 + sg, d = (blk >> 3) * 16 + dq * 4;
            float4 vv = *(const float4*)&Vg[(size_t)(s0 + s) * HD + d];
            float h0 = tf32_hi(vv.x);
            Vh[(d + 0) * AV_P + s] = h0; Vl[(d + 0) * AV_P + s] = tf32_hi(vv.x - h0);
            h0 = tf32_hi(vv.y);
            Vh[(d + 1) * AV_P + s] = h0; Vl[(d + 1) * AV_P + s] = tf32_hi(vv.y - h0);
            h0 = tf32_hi(vv.z);
            Vh[(d + 2) * AV_P + s] = h0; Vl[(d + 2) * AV_P + s] = tf32_hi(vv.z - h0);
            h0 = tf32_hi(vv.w);
            Vh[(d + 3) * AV_P + s] = h0; Vl[(d + 3) * AV_P + s] = tf32_hi(vv.w - h0);
        }
        __syncthreads();

        bool active = (s0 <= row_w + 15);
        float sacc[8][4];
        if (active) {
            #pragma unroll
            for (int nt = 0; nt < 8; nt++)
                #pragma unroll
                for (int r = 0; r < 4; r++) sacc[nt][r] = 0.f;

            // S = Q K^T (16x64)
            #pragma unroll 4
            for (int k8 = 0; k8 < 16; k8++) {
                int k0 = k8 * 8;
                int rb = (16 * wid + lr) * AQ_P + k0 + lc;
                uint32_t ah[4], al4[4];
                split2(Qs[rb],                 ah[0], al4[0]);
                split2(Qs[rb + 8 * AQ_P],      ah[1], al4[1]);
                split2(Qs[rb + 4],             ah[2], al4[2]);
                split2(Qs[rb + 8 * AQ_P + 4],  ah[3], al4[3]);
                #pragma unroll
                for (int nt = 0; nt < 8; nt++) {
                    int nb = (8 * nt + lr) * AK_P + k0 + lc;
                    uint32_t bh2[2] = {__float_as_uint(Kh[nb]), __float_as_uint(Kh[nb + 4])};
                    uint32_t bl2[2] = {__float_as_uint(Kl[nb]), __float_as_uint(Kl[nb + 4])};
                    mma_frag(sacc[nt], ah, bh2);
                    mma_frag(sacc[nt], ah, bl2);
                    mma_frag(sacc[nt], al4, bh2);
                }
            }
            // causal mask
            if (s0 + 63 > row_w) {
                int r0 = row_w + lr;
                #pragma unroll
                for (int nt = 0; nt < 8; nt++) {
                    int cb = s0 + 8 * nt + 2 * lc;
                    if (cb     > r0)     sacc[nt][0] = neg_inf();
                    if (cb + 1 > r0)     sacc[nt][1] = neg_inf();
                    if (cb     > r0 + 8) sacc[nt][2] = neg_inf();
                    if (cb + 1 > r0 + 8) sacc[nt][3] = neg_inf();
                }
            }
            // online softmax (rows lr, lr+8; quad shuffles)
            float rm0 = neg_inf(), rm1 = neg_inf();
            #pragma unroll
            for (int nt = 0; nt < 8; nt++) {
                rm0 = fmaxf(rm0, fmaxf(sacc[nt][0], sacc[nt][1]));
                rm1 = fmaxf(rm1, fmaxf(sacc[nt][2], sacc[nt][3]));
            }
            rm0 = fmaxf(rm0, __shfl_xor_sync(0xffffffffu, rm0, 1));
            rm0 = fmaxf(rm0, __shfl_xor_sync(0xffffffffu, rm0, 2));
            rm1 = fmaxf(rm1, __shfl_xor_sync(0xffffffffu, rm1, 1));
            rm1 = fmaxf(rm1, __shfl_xor_sync(0xffffffffu, rm1, 2));
            float mn0 = fmaxf(m_i[0], rm0), mn1 = fmaxf(m_i[1], rm1);
            float al0 = expf(m_i[0] - mn0), al1 = expf(m_i[1] - mn1);
            float rs0 = 0.f, rs1 = 0.f;
            #pragma unroll
            for (int nt = 0; nt < 8; nt++) {
                sacc[nt][0] = expf(sacc[nt][0] - mn0);
                sacc[nt][1] = expf(sacc[nt][1] - mn0);
                sacc[nt][2] = expf(sacc[nt][2] - mn1);
                sacc[nt][3] = expf(sacc[nt][3] - mn1);
                rs0 += sacc[nt][0] + sacc[nt][1];
                rs1 += sacc[nt][2] + sacc[nt][3];
            }
            rs0 += __shfl_xor_sync(0xffffffffu, rs0, 1);
            rs0 += __shfl_xor_sync(0xffffffffu, rs0, 2);
            rs1 += __shfl_xor_sync(0xffffffffu, rs1, 1);
            rs1 += __shfl_xor_sync(0xffffffffu, rs1, 2);
            l_i[0] = l_i[0] * al0 + rs0;  m_i[0] = mn0;
            l_i[1] = l_i[1] * al1 + rs1;  m_i[1] = mn1;
            #pragma unroll
            for (int nt = 0; nt < 16; nt++) {
                o_acc[nt][0] *= al0; o_acc[nt][1] *= al0;
                o_acc[nt][2] *= al1; o_acc[nt][3] *= al1;
            }
        }
        __syncthreads();                 // all warps done reading Kh/Kl before P write
        if (active) {
            #pragma unroll
            for (int nt = 0; nt < 8; nt++) {
                *(float2*)&Ps[(16 * wid + lr) * AP_P + 8 * nt + 2 * lc] =
                    make_float2(sacc[nt][0], sacc[nt][1]);
                *(float2*)&Ps[(16 * wid + lr + 8) * AP_P + 8 * nt + 2 * lc] =
                    make_float2(sacc[nt][2], sacc[nt][3]);
            }
            __syncwarp();
            // O += P V (16x128)
            #pragma unroll 2
            for (int k8 = 0; k8 < 8; k8++) {
                int k0 = k8 * 8;
                int pb = (16 * wid + lr) * AP_P + k0 + lc;
                uint32_t ah[4], al4[4];
                split2(Ps[pb],                 ah[0], al4[0]);
                split2(Ps[pb + 8 * AP_P],      ah[1], al4[1]);
                split2(Ps[pb + 4],             ah[2], al4[2]);
                split2(Ps[pb + 8 * AP_P + 4],  ah[3], al4[3]);
                #pragma unroll
                for (int nt = 0; nt < 16; nt++) {
                    int vb = (8 * nt + lr) * AV_P + k0 + lc;
                    uint32_t bh2[2] = {__float_as_uint(Vh[vb]), __float_as_uint(Vh[vb + 4])};
                    uint32_t bl2[2] = {__float_as_uint(Vl[vb]), __float_as_uint(Vl[vb + 4])};
                    mma_frag(o_acc[nt], ah, bh2);
                    mma_frag(o_acc[nt], ah, bl2);
                    mma_frag(o_acc[nt], al4, bh2);
                }
            }
        }
    }

    // epilogue: write split attention output [B, T, H*HD]
    float inv0 = 1.0f / l_i[0], inv1 = 1.0f / l_i[1];
    int bb = bh >> 3, h = bh & 7;
    int r0 = row_w + lr;
    size_t base0 = ((size_t)(bb * Tt + r0)) * Dd + h * HD;
    size_t base1 = ((size_t)(bb * Tt + r0 + 8)) * Dd + h * HD;
    #pragma unroll
    for (int nt = 0; nt < 16; nt++) {
        int col = 8 * nt + 2 * lc;
        float v0 = o_acc[nt][0] * inv0, v1 = o_acc[nt][1] * inv0;
        float v2 = o_acc[nt][2] * inv1, v3 = o_acc[nt][3] * inv1;
        float h0 = tf32_hi(v0), h1 = tf32_hi(v1);
        float h2 = tf32_hi(v2), h3 = tf32_hi(v3);
        *(float2*)&g_atth[base0 + col] = make_float2(h0, h1);
        *(float2*)&g_attl[base0 + col] = make_float2(tf32_hi(v0 - h0), tf32_hi(v1 - h1));
        *(float2*)&g_atth[base1 + col] = make_float2(h2, h3);
        *(float2*)&g_attl[base1 + col] = make_float2(tf32_hi(v2 - h2), tf32_hi(v3 - h3));
    }
}

// ---------------- kernel 5: LayerNorm2 + noisy top-2 router + outputs --------
#define OUT_OFF_PROBS (BT * Dd)
#define OUT_OFF_IDX   (OUT_OFF_PROBS + BT * Ee)
#define OUT_OFF_X     (OUT_OFF_IDX + BT * 2)
__global__ __launch_bounds__(256) void ln2_router_kernel(
    const float* __restrict__ g2, const float* __restrict__ b2,
    const float* __restrict__ Wr, const float* __restrict__ br,
    const float* __restrict__ Wn, const float* __restrict__ bn,
    float* __restrict__ out)
{
    int token = blockIdx.x;
    int tid = threadIdx.x;
    __shared__ float sxn[Dd];
    __shared__ float rs_[8], rq_[8];
    __shared__ float red[8][16];

    const float* xr = g_x + (size_t)token * Dd;
    float lsum = 0.f, lsq = 0.f;
    for (int c = tid; c < Dd; c += 256) {
        float v = xr[c];
        sxn[c] = v;
        out[OUT_OFF_X + (size_t)token * Dd + c] = v;
        lsum += v; lsq += v * v;
    }
    #pragma unroll
    for (int o = 16; o; o >>= 1) {
        lsum += __shfl_xor_sync(0xffffffffu, lsum, o);
        lsq  += __shfl_xor_sync(0xffffffffu, lsq,  o);
    }
    if ((tid & 31) == 0) { rs_[tid >> 5] = lsum; rq_[tid >> 5] = lsq; }
    __syncthreads();
    float s = 0.f, q = 0.f;
    #pragma unroll
    for (int w = 0; w < 8; w++) { s += rs_[w]; q += rq_[w]; }
    float mu   = s * (1.0f / Dd);
    float var  = q * (1.0f / Dd) - mu * mu;
    float rstd = rsqrtf(var + 1e-5f);

    for (int c = tid; c < Dd; c += 256) {
        float v  = sxn[c];
        float xn = (v - mu) * rstd * g2[c] + b2[c];
        sxn[c] = xn;
        out[(size_t)token * Dd + c] = xn;
    }
    __syncthreads();

    float ar[8] = {}, an_[8] = {};
    for (int c = tid; c < Dd; c += 256) {
        float v = sxn[c];
        float4 w0 = *(const float4*)&Wr[(size_t)c * Ee];
        float4 w1 = *(const float4*)&Wr[(size_t)c * Ee + 4];
        ar[0] += v * w0.x; ar[1] += v * w0.y; ar[2] += v * w0.z; ar[3] += v * w0.w;
        ar[4] += v * w1.x; ar[5] += v * w1.y; ar[6] += v * w1.z; ar[7] += v * w1.w;
        float4 n0 = *(const float4*)&Wn[(size_t)c * Ee];
        float4 n1 = *(const float4*)&Wn[(size_t)c * Ee + 4];
        an_[0] += v * n0.x; an_[1] += v * n0.y; an_[2] += v * n0.z; an_[3] += v * n0.w;
        an_[4] += v * n1.x; an_[5] += v * n1.y; an_[6] += v * n1.z; an_[7] += v * n1.w;
    }
    #pragma unroll
    for (int o = 16; o; o >>= 1) {
        #pragma unroll
        for (int e = 0; e < 8; e++) {
            ar[e]  += __shfl_xor_sync(0xffffffffu, ar[e],  o);
            an_[e] += __shfl_xor_sync(0xffffffffu, an_[e], o);
        }
    }
    int w = tid >> 5;
    if ((tid & 31) == 0) {
        #pragma unroll
        for (int e = 0; e < 8; e++) { red[w][e] = ar[e]; red[w][8 + e] = an_[e]; }
    }
    __syncthreads();

    if (tid == 0) {
        float lg[8], nl[8];
        #pragma unroll
        for (int e = 0; e < 8; e++) { lg[e] = br[e]; nl[e] = bn[e]; }
        for (int ww = 0; ww < 8; ww++)
            #pragma unroll
            for (int e = 0; e < 8; e++) { lg[e] += red[ww][e]; nl[e] += red[ww][8 + e]; }

        float noisy[8];
        #pragma unroll
        for (int e = 0; e < 8; e++) {
            float nz = jax_noise((uint32_t)(token * Ee + e));
            noisy[e] = lg[e] + nz * softplus_f(nl[e]);
        }
        int i0 = 0; float v0 = noisy[0];
        #pragma unroll
        for (int e = 1; e < 8; e++) if (noisy[e] > v0) { v0 = noisy[e]; i0 = e; }
        int i1 = -1; float v1 = neg_inf();
        #pragma unroll
        for (int e = 0; e < 8; e++)
            if (e != i0 && noisy[e] > v1) { v1 = noisy[e]; i1 = e; }

        float e1 = expf(v1 - v0);
        float inv = 1.0f / (1.0f + e1);
        float p0 = inv, p1 = e1 * inv;

        float probs[8] = {};
        probs[i0] = p0; probs[i1] = p1;
        float* pout = out + OUT_OFF_PROBS + (size_t)token * Ee;
        #pragma unroll
        for (int e = 0; e < 8; e++) pout[e] = probs[e];
        out[OUT_OFF_IDX + (size_t)token * 2 + 0] = (float)i0;
        out[OUT_OFF_IDX + (size_t)token * 2 + 1] = (float)i1;
    }
}

// ---------------- launcher ---------------------------------------------------
extern "C" void kernel_launch(void* const* d_in, const int* in_sizes, int n_in,
                              void* d_out, int out_size)
{
    const int*   idx = (const int*)  d_in[0];
    const float* tok = (const float*)d_in[1];
    const float* pos = (const float*)d_in[2];
    const float* Wq  = (const float*)d_in[3];
    const float* Wk  = (const float*)d_in[4];
    const float* Wv  = (const float*)d_in[5];
    const float* Wo  = (const float*)d_in[6];
    const float* bo  = (const float*)d_in[7];
    const float* g1  = (const float*)d_in[8];
    const float* b1  = (const float*)d_in[9];
    const float* g2  = (const float*)d_in[10];
    const float* b2  = (const float*)d_in[11];
    const float* Wr  = (const float*)d_in[12];
    const float* br  = (const float*)d_in[13];
    const float* Wn  = (const float*)d_in[14];
    const float* bn  = (const float*)d_in[15];
    float* out = (float*)d_out;

    cudaFuncSetAttribute(attn_mma_kernel, cudaFuncAttributeMaxDynamicSharedMemorySize,
                         ATT_SMEM_F * (int)sizeof(float));
    cudaFuncSetAttribute(qkv_mma_kernel, cudaFuncAttributeMaxDynamicSharedMemorySize,
                         GEMM_SMEM_BYTES);
    cudaFuncSetAttribute(proj_mma_kernel, cudaFuncAttributeMaxDynamicSharedMemorySize,
                         GEMM_SMEM_BYTES);

    embed_ln_kernel<<<BT, 256>>>(idx, tok, pos, g1, b1);
    transpose_qkv_kernel<<<dim3(32, 4, 24), dim3(32, 8)>>>(Wq, Wk, Wv);
    transpose_wo_kernel<<<dim3(32, 32), dim3(32, 8)>>>(Wo);
    qkv_mma_kernel<<<dim3(BT / 256, 24), 512, GEMM_SMEM_BYTES>>>();
    attn_mma_kernel<<<dim3(Tt / 128, Bb * Hh), 256, ATT_SMEM_F * sizeof(float)>>>();
    proj_mma_kernel<<<dim3(BT / 256, Dd / 128), 512, GEMM_SMEM_BYTES>>>(bo);
    ln2_router_kernel<<<BT, 256>>>(g2, b2, Wr, br, Wn, bn, out);
}

// round 9
// speedup vs baseline: 1.7722x; 1.0414x over previous
#include <cuda_runtime.h>
#include <cstdint>

// Problem dims
#define Bb 4
#define Tt 2048
#define Dd 1024
#define Hh 8
#define HD 128
#define Ee 8
#define BT 8192            // Bb*Tt
#define TH (Tt*HD)         // 262144

// ---------------- scratch (device globals; no allocations allowed) ----------
__device__ float g_x   [BT*Dd];   // running residual x
__device__ float g_xnh [BT*Dd];   // LN1(x) tf32 hi
__device__ float g_xnl [BT*Dd];   // LN1(x) tf32 lo
__device__ float g_q   [BT*Dd];   // [B,H,T,HD]
__device__ float g_k   [BT*Dd];
__device__ float g_v   [BT*Dd];
__device__ float g_atth[BT*Dd];   // attention out hi  [B,T,H*HD]
__device__ float g_attl[BT*Dd];   // attention out lo
__device__ float g_wth [3*Hh*HD*Dd];  // transposed QKV weights hi  [z][d][c]
__device__ float g_wtl [3*Hh*HD*Dd];
__device__ float g_woth[Dd*Dd];       // Wo^T hi [n][k]
__device__ float g_wotl[Dd*Dd];

__device__ __forceinline__ float neg_inf() { return __int_as_float(0xff800000); }

// tf32 round-to-nearest (base PTX, sm_80+)
__device__ __forceinline__ float tf32_hi(float a) {
    uint32_t r; asm("cvt.rna.tf32.f32 %0, %1;" : "=r"(r) : "f"(a));
    return __uint_as_float(r);
}
__device__ __forceinline__ void split2(float v, uint32_t& h, uint32_t& l) {
    float hf = tf32_hi(v);
    h = __float_as_uint(hf);
    l = __float_as_uint(tf32_hi(v - hf));
}

// m16n8k8 tf32 MMA (base PTX, sm_80+): D += A * B
__device__ __forceinline__ void mma_frag(float* d, const uint32_t* a, const uint32_t* b) {
    asm volatile("mma.sync.aligned.m16n8k8.row.col.f32.tf32.tf32.f32 "
        "{%0,%1,%2,%3}, {%4,%5,%6,%7}, {%8,%9}, {%0,%1,%2,%3};"
        : "+f"(d[0]), "+f"(d[1]), "+f"(d[2]), "+f"(d[3])
        : "r"(a[0]), "r"(a[1]), "r"(a[2]), "r"(a[3]), "r"(b[0]), "r"(b[1]));
}

// ldmatrix x4 (base PTX, sm_75+). Lane l supplies the row address for
// row (l&7) of matrix (l>>3); result reg j = 32-bit element (lane>>2, lane&3)
// of matrix j viewed as an 8x4 b32 block.
__device__ __forceinline__ void ldsm4(uint32_t* r, uint32_t saddr) {
    asm volatile("ldmatrix.sync.aligned.m8n8.x4.shared.b16 {%0,%1,%2,%3}, [%4];"
        : "=r"(r[0]), "=r"(r[1]), "=r"(r[2]), "=r"(r[3]) : "r"(saddr));
}

// cp.async (base PTX, sm_80+)
__device__ __forceinline__ uint32_t smem_to_u32(const void* p) {
    uint32_t a;
    asm("{ .reg .u64 t; cvta.to.shared.u64 t, %1; cvt.u32.u64 %0, t; }" : "=r"(a) : "l"(p));
    return a;
}
__device__ __forceinline__ void cp_async16(uint32_t saddr, const void* gaddr) {
    asm volatile("cp.async.cg.shared.global [%0], [%1], 16;" :: "r"(saddr), "l"(gaddr));
}
__device__ __forceinline__ void cp_commit() { asm volatile("cp.async.commit_group;" ::: "memory"); }
template<int N> __device__ __forceinline__ void cp_wait() {
    asm volatile("cp.async.wait_group %0;" :: "n"(N) : "memory");
}

// ---------------- JAX threefry2x32 noise (partitionable scheme) --------------
__device__ __forceinline__ uint32_t rotl32(uint32_t v, int r) {
    return (v << r) | (v >> (32 - r));
}
__device__ float jax_noise(uint32_t i) {
    uint32_t x0 = 0u, x1 = i;
    const uint32_t k0 = 0u, k1 = 42u, k2 = 0u ^ 42u ^ 0x1BD11BDAu;
    x0 += k0; x1 += k1;
#define TF_ROUND(r) { x0 += x1; x1 = rotl32(x1, r); x1 ^= x0; }
#define TF_G0 TF_ROUND(13) TF_ROUND(15) TF_ROUND(26) TF_ROUND(6)
#define TF_G1 TF_ROUND(17) TF_ROUND(29) TF_ROUND(16) TF_ROUND(24)
    TF_G0; x0 += k1; x1 += k2 + 1u;
    TF_G1; x0 += k2; x1 += k0 + 2u;
    TF_G0; x0 += k0; x1 += k1 + 3u;
    TF_G1; x0 += k1; x1 += k2 + 4u;
    TF_G0; x0 += k2; x1 += k0 + 5u;
#undef TF_G1
#undef TF_G0
#undef TF_ROUND
    uint32_t bits = x0 ^ x1;
    float f = __uint_as_float((bits >> 9) | 0x3f800000u) - 1.0f;
    const float lo = -0.99999994f;
    float u = f * (1.0f - lo) + lo;
    u = fmaxf(u, lo);
    return 1.41421354f * erfinvf(u);
}
__device__ __forceinline__ float softplus_f(float x) {
    return fmaxf(x, 0.0f) + log1pf(expf(-fabsf(x)));
}

// ---------------- kernel 1: embedding + LayerNorm1 (writes split xn) ---------
__global__ __launch_bounds__(256) void embed_ln_kernel(
    const int* __restrict__ idx, const float* __restrict__ tok,
    const float* __restrict__ pos, const float* __restrict__ g1,
    const float* __restrict__ b1)
{
    int token = blockIdx.x;
    int t     = token & (Tt - 1);
    int tid   = threadIdx.x;
    __shared__ float sx[Dd];
    __shared__ float rs_[8], rq_[8];

    const float* trow = tok + (size_t)idx[token] * Dd;
    const float* prow = pos + (size_t)t * Dd;

    float lsum = 0.f, lsq = 0.f;
    for (int c = tid; c < Dd; c += 256) {
        float v = trow[c] + prow[c];
        sx[c] = v; lsum += v; lsq += v * v;
    }
    #pragma unroll
    for (int o = 16; o; o >>= 1) {
        lsum += __shfl_xor_sync(0xffffffffu, lsum, o);
        lsq  += __shfl_xor_sync(0xffffffffu, lsq,  o);
    }
    if ((tid & 31) == 0) { rs_[tid >> 5] = lsum; rq_[tid >> 5] = lsq; }
    __syncthreads();
    float s = 0.f, q = 0.f;
    #pragma unroll
    for (int w = 0; w < 8; w++) { s += rs_[w]; q += rq_[w]; }
    float mu   = s * (1.0f / Dd);
    float var  = q * (1.0f / Dd) - mu * mu;
    float rstd = rsqrtf(var + 1e-5f);

    float* xr = g_x + (size_t)token * Dd;
    for (int c = tid; c < Dd; c += 256) {
        float v = sx[c];
        xr[c] = v;
        float xn = (v - mu) * rstd * g1[c] + b1[c];
        float h = tf32_hi(xn);
        g_xnh[(size_t)token * Dd + c] = h;
        g_xnl[(size_t)token * Dd + c] = tf32_hi(xn - h);
    }
}

// ---------------- weight transposes (split to hi/lo) -------------------------
__global__ __launch_bounds__(256) void transpose_qkv_kernel(
    const float* __restrict__ Wq, const float* __restrict__ Wk,
    const float* __restrict__ Wv)
{
    __shared__ float tile[32][33];
    int z = blockIdx.z; int which = z >> 3, h = z & 7;
    const float* src = (which == 0 ? Wq : which == 1 ? Wk : Wv) + (size_t)h * Dd * HD;
    size_t dbase = (size_t)z * HD * Dd;
    int c0 = blockIdx.x * 32, d0 = blockIdx.y * 32;
    int tx = threadIdx.x, ty = threadIdx.y;
    #pragma unroll
    for (int j = 0; j < 32; j += 8)
        tile[ty + j][tx] = src[(size_t)(c0 + ty + j) * HD + d0 + tx];
    __syncthreads();
    #pragma unroll
    for (int j = 0; j < 32; j += 8) {
        float v = tile[tx][ty + j];
        float h2 = tf32_hi(v);
        size_t o = dbase + (size_t)(d0 + ty + j) * Dd + c0 + tx;
        g_wth[o] = h2;
        g_wtl[o] = tf32_hi(v - h2);
    }
}

__global__ __launch_bounds__(256) void transpose_wo_kernel(const float* __restrict__ Wo)
{
    __shared__ float tile[32][33];
    int k0 = blockIdx.x * 32, n0 = blockIdx.y * 32;
    int tx = threadIdx.x, ty = threadIdx.y;
    #pragma unroll
    for (int j = 0; j < 32; j += 8)
        tile[ty + j][tx] = Wo[(size_t)(k0 + ty + j) * Dd + n0 + tx];
    __syncthreads();
    #pragma unroll
    for (int j = 0; j < 32; j += 8) {
        float v = tile[tx][ty + j];
        float h2 = tf32_hi(v);
        size_t o = (size_t)(n0 + ty + j) * Dd + k0 + tx;
        g_woth[o] = h2;
        g_wotl[o] = tf32_hi(v - h2);
    }
}

// ---------------- 3xTF32 ldmatrix + cp.async GEMM core -----------------------
// C[256x128] = A[256x1024] * B[128x1024]^T  (B stored [n][k]); operands pre-split
// 256 threads (8 warps, 4x2); warp tile 64x64 (mt=4, nt=8); K-chunk 32, 2 stages.
#define NCHUNK 32
#define LDP 36
#define A_F (256 * LDP)                    // 9216 floats
#define B_F (128 * LDP)                    // 4608
#define STAGE_F (2 * A_F + 2 * B_F)        // 27648
#define GEMM_SMEM_BYTES (2 * STAGE_F * 4)  // 221184

__device__ __forceinline__ void gemm_issue_chunk(
    uint32_t sbase, int stage, int c,
    const float* __restrict__ Ah_g, const float* __restrict__ Al_g,
    const float* __restrict__ Bh_g, const float* __restrict__ Bl_g, int tid)
{
    uint32_t sb = sbase + (uint32_t)(stage * STAGE_F * 4);
    #pragma unroll
    for (int p = 0; p < 8; p++) {
        int f = tid + p * 256;                 // A: 2048 float4 slots
        int r = f >> 3, c4 = (f & 7) << 2;
        uint32_t off = (uint32_t)((r * LDP + c4) * 4);
        size_t go = (size_t)r * Dd + c * 32 + c4;
        cp_async16(sb + off,           Ah_g + go);
        cp_async16(sb + A_F * 4 + off, Al_g + go);
    }
    #pragma unroll
    for (int p = 0; p < 4; p++) {
        int f = tid + p * 256;                 // B: 1024 float4 slots
        int r = f >> 3, c4 = (f & 7) << 2;
        uint32_t off = (uint32_t)((r * LDP + c4) * 4);
        size_t go = (size_t)r * Dd + c * 32 + c4;
        cp_async16(sb + 2 * A_F * 4 + off,           Bh_g + go);
        cp_async16(sb + 2 * A_F * 4 + B_F * 4 + off, Bl_g + go);
    }
}

__device__ __forceinline__ void gemm3x_mainloop(
    const float* __restrict__ Ah_g, const float* __restrict__ Al_g,
    const float* __restrict__ Bh_g, const float* __restrict__ Bl_g,
    float acc[4][8][4], float* sm, int tid)
{
    uint32_t sbase = smem_to_u32(sm);
    int wid = tid >> 5, lane = tid & 31;
    int wm = (wid & 3) * 64, wn = (wid >> 2) * 64;
    // ldmatrix lane address components
    int m_row = ((lane >> 3) & 1) * 8 + (lane & 7);
    int m_col = (lane >> 4) * 4;
    int n_row = (lane >> 4) * 8 + (lane & 7);
    int n_col = ((lane >> 3) & 1) * 4;
    uint32_t aoff = (uint32_t)(((wm + m_row) * LDP + m_col) * 4);
    uint32_t boff = (uint32_t)((2 * A_F + (wn + n_row) * LDP + n_col) * 4);

    gemm_issue_chunk(sbase, 0, 0, Ah_g, Al_g, Bh_g, Bl_g, tid);
    cp_commit();

    for (int c = 0; c < NCHUNK; c++) {
        if (c + 1 < NCHUNK) {
            gemm_issue_chunk(sbase, (c + 1) & 1, c + 1, Ah_g, Al_g, Bh_g, Bl_g, tid);
            cp_commit();
            cp_wait<1>();
        } else {
            cp_wait<0>();
        }
        __syncthreads();

        uint32_t stg = sbase + (uint32_t)((c & 1) * STAGE_F * 4);
        uint32_t ah_u = stg + aoff;
        uint32_t al_u = ah_u + A_F * 4;
        uint32_t bh_u = stg + boff;
        uint32_t bl_u = bh_u + B_F * 4;

        #pragma unroll
        for (int k8 = 0; k8 < 4; k8++) {
            uint32_t ko = (uint32_t)(k8 * 32);    // 8 floats
            uint32_t ah[4][4], al[4][4];
            #pragma unroll
            for (int mt = 0; mt < 4; mt++) {
                ldsm4(ah[mt], ah_u + ko + mt * (16 * LDP * 4));
                ldsm4(al[mt], al_u + ko + mt * (16 * LDP * 4));
            }
            #pragma unroll
            for (int g = 0; g < 4; g++) {
                uint32_t b4h[4], b4l[4];
                ldsm4(b4h, bh_u + ko + g * (16 * LDP * 4));
                ldsm4(b4l, bl_u + ko + g * (16 * LDP * 4));
                #pragma unroll
                for (int half = 0; half < 2; half++) {
                    int nt = 2 * g + half;
                    uint32_t bh2[2] = {b4h[2 * half], b4h[2 * half + 1]};
                    uint32_t bl2[2] = {b4l[2 * half], b4l[2 * half + 1]};
                    #pragma unroll
                    for (int mt = 0; mt < 4; mt++) {
                        mma_frag(acc[mt][nt], ah[mt], bh2);
                        mma_frag(acc[mt][nt], ah[mt], bl2);
                        mma_frag(acc[mt][nt], al[mt], bh2);
                    }
                }
            }
        }
        __syncthreads();
    }
}

// ---------------- kernel 2: QKV via mma.sync (grid 32 x 24, 256 thr) ---------
__global__ __launch_bounds__(256, 1) void qkv_mma_kernel()
{
    extern __shared__ float sm[];
    int tid = threadIdx.x, wid = tid >> 5, lane = tid & 31;
    int m0 = blockIdx.x * 256;
    int z  = blockIdx.y;
    const float* Ah = g_xnh + (size_t)m0 * Dd;
    const float* Al = g_xnl + (size_t)m0 * Dd;
    const float* Bh = g_wth + (size_t)z * HD * Dd;
    const float* Bl = g_wtl + (size_t)z * HD * Dd;

    float acc[4][8][4];
    #pragma unroll
    for (int mt = 0; mt < 4; mt++)
        #pragma unroll
        for (int nt = 0; nt < 8; nt++)
            #pragma unroll
            for (int r = 0; r < 4; r++) acc[mt][nt][r] = 0.f;

    gemm3x_mainloop(Ah, Al, Bh, Bl, acc, sm, tid);

    int wm = (wid & 3) * 64, wn = (wid >> 2) * 64;
    int lr = lane >> 2, lc = lane & 3;
    int which = z >> 3, h = z & 7;
    float* Ob = (which == 0 ? g_q : which == 1 ? g_k : g_v);
    #pragma unroll
    for (int mt = 0; mt < 4; mt++) {
        int m = m0 + wm + mt * 16 + lr;
        int bb = m >> 11, tt = m & (Tt - 1);
        float* row0 = Ob + ((size_t)(bb * Hh + h) * Tt + tt) * HD + wn + lc * 2;
        #pragma unroll
        for (int nt = 0; nt < 8; nt++) {
            float* p0 = row0 + nt * 8;
            p0[0]          = acc[mt][nt][0];
            p0[1]          = acc[mt][nt][1];
            p0[8 * HD]     = acc[mt][nt][2];
            p0[8 * HD + 1] = acc[mt][nt][3];
        }
    }
}

// ---------------- kernel 4: proj + residual (grid 32 x 8, 256 thr) -----------
__global__ __launch_bounds__(256, 1) void proj_mma_kernel(const float* __restrict__ bo)
{
    extern __shared__ float sm[];
    int tid = threadIdx.x, wid = tid >> 5, lane = tid & 31;
    int m0 = blockIdx.x * 256;
    int n0 = blockIdx.y * 128;
    const float* Ah = g_atth + (size_t)m0 * Dd;
    const float* Al = g_attl + (size_t)m0 * Dd;
    const float* Bh = g_woth + (size_t)n0 * Dd;
    const float* Bl = g_wotl + (size_t)n0 * Dd;

    float acc[4][8][4];
    #pragma unroll
    for (int mt = 0; mt < 4; mt++)
        #pragma unroll
        for (int nt = 0; nt < 8; nt++)
            #pragma unroll
            for (int r = 0; r < 4; r++) acc[mt][nt][r] = 0.f;

    gemm3x_mainloop(Ah, Al, Bh, Bl, acc, sm, tid);

    int wm = (wid & 3) * 64, wn = (wid >> 2) * 64;
    int lr = lane >> 2, lc = lane & 3;
    #pragma unroll
    for (int mt = 0; mt < 4; mt++) {
        int m = m0 + wm + mt * 16 + lr;
        float* xrow = g_x + (size_t)m * Dd + n0 + wn + lc * 2;
        const float* brow = bo + n0 + wn + lc * 2;
        #pragma unroll
        for (int nt = 0; nt < 8; nt++) {
            float* p0 = xrow + nt * 8;
            const float* b0 = brow + nt * 8;
            p0[0]          += acc[mt][nt][0] + b0[0];
            p0[1]          += acc[mt][nt][1] + b0[1];
            p0[8 * Dd]     += acc[mt][nt][2] + b0[0];
            p0[8 * Dd + 1] += acc[mt][nt][3] + b0[1];
        }
    }
}

// ---------------- kernel 3: causal flash attention, pre-split K/V ------------
// Q tile 128 x KV tile 64; 256 thr, 8 warps; warp w owns rows [16w,16w+16).
// smem: Qs fp32 [128][132]; Kh/Kl [64][132] (P [128][68] aliases); Vh/Vl [128][68]
#define AQ_P 132
#define AK_P 132
#define AV_P 68
#define AP_P 68
#define OFF_KH 16896
#define OFF_KL 25344
#define OFF_P  16896
#define OFF_VH 33792
#define OFF_VL 42496
#define ATT_SMEM_F 51200   // 204800 B
__global__ __launch_bounds__(256) void attn_mma_kernel()
{
    extern __shared__ float smx[];
    float* Vh = smx + OFF_VH;
    float* Vl = smx + OFF_VL;
    float* Kh = smx + OFF_KH;
    float* Kl = smx + OFF_KL;
    float* Qs = smx;
    float* Ps = smx + OFF_P;     // aliases Kh/Kl region (guarded by barrier)

    int bh = blockIdx.y, qt = blockIdx.x;
    int t0 = qt * 128;
    const float* Qg = g_q + (size_t)bh * TH;
    const float* Kg = g_k + (size_t)bh * TH;
    const float* Vg = g_v + (size_t)bh * TH;

    int tid = threadIdx.x, wid = tid >> 5, lane = tid & 31;
    int lr = lane >> 2, lc = lane & 3;
    const float scale = 0.03125f;

    // ldmatrix lane address components
    int m_row = ((lane >> 3) & 1) * 8 + (lane & 7);
    int m_col = (lane >> 4) * 4;
    int n_row = (lane >> 4) * 8 + (lane & 7);
    int n_col = ((lane >> 3) & 1) * 4;
    uint32_t sb = smem_to_u32(smx);
    uint32_t q_u  = sb + (uint32_t)(((16 * wid + m_row) * AQ_P + m_col) * 4);
    uint32_t p_u  = sb + (uint32_t)((OFF_P + (16 * wid + m_row) * AP_P + m_col) * 4);
    uint32_t kh_u = sb + (uint32_t)((OFF_KH + n_row * AK_P + n_col) * 4);
    uint32_t kl_u = sb + (uint32_t)((OFF_KL + n_row * AK_P + n_col) * 4);
    uint32_t vh_u = sb + (uint32_t)((OFF_VH + n_row * AV_P + n_col) * 4);
    uint32_t vl_u = sb + (uint32_t)((OFF_VL + n_row * AV_P + n_col) * 4);

    // Q tile (scaled fp32)
    #pragma unroll 4
    for (int i = tid; i < 128 * 32; i += 256) {
        int r = i >> 5, c4 = (i & 31) << 2;
        float4 qv = *(const float4*)&Qg[(size_t)(t0 + r) * HD + c4];
        qv.x *= scale; qv.y *= scale; qv.z *= scale; qv.w *= scale;
        *(float4*)&Qs[r * AQ_P + c4] = qv;
    }

    float o_acc[16][4];
    #pragma unroll
    for (int nt = 0; nt < 16; nt++)
        #pragma unroll
        for (int r = 0; r < 4; r++) o_acc[nt][r] = 0.f;
    float m_i[2] = {neg_inf(), neg_inf()};
    float l_i[2] = {0.f, 0.f};

    int row_w = t0 + 16 * wid;
    int ntiles = 2 * (qt + 1);
    for (int j = 0; j < ntiles; j++) {
        int s0 = 64 * j;
        __syncthreads();                 // prior PV (P,V readers) done
        // K tile: split hi/lo, layout [s][d]
        #pragma unroll
        for (int p = 0; p < 8; p++) {
            int i = tid + p * 256;
            int s = i >> 5, d4 = (i & 31) << 2;
            float4 kv = *(const float4*)&Kg[(size_t)(s0 + s) * HD + d4];
            float4 h, l;
            h.x = tf32_hi(kv.x); l.x = tf32_hi(kv.x - h.x);
            h.y = tf32_hi(kv.y); l.y = tf32_hi(kv.y - h.y);
            h.z = tf32_hi(kv.z); l.z = tf32_hi(kv.z - h.z);
            h.w = tf32_hi(kv.w); l.w = tf32_hi(kv.w - h.w);
            *(float4*)&Kh[s * AK_P + d4] = h;
            *(float4*)&Kl[s * AK_P + d4] = l;
        }
        // V tile: split hi/lo, transposed [d][s]
        #pragma unroll
        for (int p = 0; p < 8; p++) {
            int i = tid + p * 256;
            int dq = i & 3, sg = (i >> 2) & 7, blk = i >> 5;
            int s = (blk & 7) * 8 + sg, d = (blk >> 3) * 16 + dq * 4;
            float4 vv = *(const float4*)&Vg[(size_t)(s0 + s) * HD + d];
            float h0 = tf32_hi(vv.x);
            Vh[(d + 0) * AV_P + s] = h0; Vl[(d + 0) * AV_P + s] = tf32_hi(vv.x - h0);
            h0 = tf32_hi(vv.y);
            Vh[(d + 1) * AV_P + s] = h0; Vl[(d + 1) * AV_P + s] = tf32_hi(vv.y - h0);
            h0 = tf32_hi(vv.z);
            Vh[(d + 2) * AV_P + s] = h0; Vl[(d + 2) * AV_P + s] = tf32_hi(vv.z - h0);
            h0 = tf32_hi(vv.w);
            Vh[(d + 3) * AV_P + s] = h0; Vl[(d + 3) * AV_P + s] = tf32_hi(vv.w - h0);
        }
        __syncthreads();

        bool active = (s0 <= row_w + 15);
        float sacc[8][4];
        if (active) {
            #pragma unroll
            for (int nt = 0; nt < 8; nt++)
                #pragma unroll
                for (int r = 0; r < 4; r++) sacc[nt][r] = 0.f;

            // S = Q K^T (16x64), frags via ldmatrix
            #pragma unroll 2
            for (int k8 = 0; k8 < 16; k8++) {
                uint32_t ko = (uint32_t)(k8 * 32);
                uint32_t qf[4]; ldsm4(qf, q_u + ko);
                uint32_t ah[4], al4[4];
                #pragma unroll
                for (int i = 0; i < 4; i++)
                    split2(__uint_as_float(qf[i]), ah[i], al4[i]);
                #pragma unroll
                for (int g = 0; g < 4; g++) {
                    uint32_t kh4[4], kl4[4];
                    ldsm4(kh4, kh_u + ko + g * (16 * AK_P * 4));
                    ldsm4(kl4, kl_u + ko + g * (16 * AK_P * 4));
                    #pragma unroll
                    for (int half = 0; half < 2; half++) {
                        int nt = 2 * g + half;
                        uint32_t bh2[2] = {kh4[2 * half], kh4[2 * half + 1]};
                        uint32_t bl2[2] = {kl4[2 * half], kl4[2 * half + 1]};
                        mma_frag(sacc[nt], ah, bh2);
                        mma_frag(sacc[nt], ah, bl2);
                        mma_frag(sacc[nt], al4, bh2);
                    }
                }
            }
            // causal mask
            if (s0 + 63 > row_w) {
                int r0 = row_w + lr;
                #pragma unroll
                for (int nt = 0; nt < 8; nt++) {
                    int cb = s0 + 8 * nt + 2 * lc;
                    if (cb     > r0)     sacc[nt][0] = neg_inf();
                    if (cb + 1 > r0)     sacc[nt][1] = neg_inf();
                    if (cb     > r0 + 8) sacc[nt][2] = neg_inf();
                    if (cb + 1 > r0 + 8) sacc[nt][3] = neg_inf();
                }
            }
            // online softmax (rows lr, lr+8; quad shuffles)
            float rm0 = neg_inf(), rm1 = neg_inf();
            #pragma unroll
            for (int nt = 0; nt < 8; nt++) {
                rm0 = fmaxf(rm0, fmaxf(sacc[nt][0], sacc[nt][1]));
                rm1 = fmaxf(rm1, fmaxf(sacc[nt][2], sacc[nt][3]));
            }
            rm0 = fmaxf(rm0, __shfl_xor_sync(0xffffffffu, rm0, 1));
            rm0 = fmaxf(rm0, __shfl_xor_sync(0xffffffffu, rm0, 2));
            rm1 = fmaxf(rm1, __shfl_xor_sync(0xffffffffu, rm1, 1));
            rm1 = fmaxf(rm1, __shfl_xor_sync(0xffffffffu, rm1, 2));
            float mn0 = fmaxf(m_i[0], rm0), mn1 = fmaxf(m_i[1], rm1);
            float al0 = expf(m_i[0] - mn0), al1 = expf(m_i[1] - mn1);
            float rs0 = 0.f, rs1 = 0.f;
            #pragma unroll
            for (int nt = 0; nt < 8; nt++) {
                sacc[nt][0] = expf(sacc[nt][0] - mn0);
                sacc[nt][1] = expf(sacc[nt][1] - mn0);
                sacc[nt][2] = expf(sacc[nt][2] - mn1);
                sacc[nt][3] = expf(sacc[nt][3] - mn1);
                rs0 += sacc[nt][0] + sacc[nt][1];
                rs1 += sacc[nt][2] + sacc[nt][3];
            }
            rs0 += __shfl_xor_sync(0xffffffffu, rs0, 1);
            rs0 += __shfl_xor_sync(0xffffffffu, rs0, 2);
            rs1 += __shfl_xor_sync(0xffffffffu, rs1, 1);
            rs1 += __shfl_xor_sync(0xffffffffu, rs1, 2);
            l_i[0] = l_i[0] * al0 + rs0;  m_i[0] = mn0;
            l_i[1] = l_i[1] * al1 + rs1;  m_i[1] = mn1;
            #pragma unroll
            for (int nt = 0; nt < 16; nt++) {
                o_acc[nt][0] *= al0; o_acc[nt][1] *= al0;
                o_acc[nt][2] *= al1; o_acc[nt][3] *= al1;
            }
        }
        __syncthreads();                 // all warps done reading Kh/Kl before P write
        if (active) {
            #pragma unroll
            for (int nt = 0; nt < 8; nt++) {
                *(float2*)&Ps[(16 * wid + lr) * AP_P + 8 * nt + 2 * lc] =
                    make_float2(sacc[nt][0], sacc[nt][1]);
                *(float2*)&Ps[(16 * wid + lr + 8) * AP_P + 8 * nt + 2 * lc] =
                    make_float2(sacc[nt][2], sacc[nt][3]);
            }
            __syncwarp();
            // O += P V (16x128), frags via ldmatrix
            #pragma unroll 2
            for (int k8 = 0; k8 < 8; k8++) {
                uint32_t ko = (uint32_t)(k8 * 32);
                uint32_t pf[4]; ldsm4(pf, p_u + ko);
                uint32_t ah[4], al4[4];
                #pragma unroll
                for (int i = 0; i < 4; i++)
                    split2(__uint_as_float(pf[i]), ah[i], al4[i]);
                #pragma unroll
                for (int g = 0; g < 8; g++) {
                    uint32_t vh4[4], vl4[4];
                    ldsm4(vh4, vh_u + ko + g * (16 * AV_P * 4));
                    ldsm4(vl4, vl_u + ko + g * (16 * AV_P * 4));
                    #pragma unroll
                    for (int half = 0; half < 2; half++) {
                        int nt = 2 * g + half;
                        uint32_t bh2[2] = {vh4[2 * half], vh4[2 * half + 1]};
                        uint32_t bl2[2] = {vl4[2 * half], vl4[2 * half + 1]};
                        mma_frag(o_acc[nt], ah, bh2);
                        mma_frag(o_acc[nt], ah, bl2);
                        mma_frag(o_acc[nt], al4, bh2);
                    }
                }
            }
        }
    }

    // epilogue: write split attention output [B, T, H*HD]
    float inv0 = 1.0f / l_i[0], inv1 = 1.0f / l_i[1];
    int bb = bh >> 3, h = bh & 7;
    int r0 = row_w + lr;
    size_t base0 = ((size_t)(bb * Tt + r0)) * Dd + h * HD;
    size_t base1 = ((size_t)(bb * Tt + r0 + 8)) * Dd + h * HD;
    #pragma unroll
    for (int nt = 0; nt < 16; nt++) {
        int col = 8 * nt + 2 * lc;
        float v0 = o_acc[nt][0] * inv0, v1 = o_acc[nt][1] * inv0;
        float v2 = o_acc[nt][2] * inv1, v3 = o_acc[nt][3] * inv1;
        float h0 = tf32_hi(v0), h1 = tf32_hi(v1);
        float h2 = tf32_hi(v2), h3 = tf32_hi(v3);
        *(float2*)&g_atth[base0 + col] = make_float2(h0, h1);
        *(float2*)&g_attl[base0 + col] = make_float2(tf32_hi(v0 - h0), tf32_hi(v1 - h1));
        *(float2*)&g_atth[base1 + col] = make_float2(h2, h3);
        *(float2*)&g_attl[base1 + col] = make_float2(tf32_hi(v2 - h2), tf32_hi(v3 - h3));
    }
}

// ---------------- kernel 5: LayerNorm2 + noisy top-2 router + outputs --------
#define OUT_OFF_PROBS (BT * Dd)
#define OUT_OFF_IDX   (OUT_OFF_PROBS + BT * Ee)
#define OUT_OFF_X     (OUT_OFF_IDX + BT * 2)
__global__ __launch_bounds__(256) void ln2_router_kernel(
    const float* __restrict__ g2, const float* __restrict__ b2,
    const float* __restrict__ Wr, const float* __restrict__ br,
    const float* __restrict__ Wn, const float* __restrict__ bn,
    float* __restrict__ out)
{
    int token = blockIdx.x;
    int tid = threadIdx.x;
    __shared__ float sxn[Dd];
    __shared__ float rs_[8], rq_[8];
    __shared__ float red[8][16];

    const float* xr = g_x + (size_t)token * Dd;
    float lsum = 0.f, lsq = 0.f;
    for (int c = tid; c < Dd; c += 256) {
        float v = xr[c];
        sxn[c] = v;
        out[OUT_OFF_X + (size_t)token * Dd + c] = v;
        lsum += v; lsq += v * v;
    }
    #pragma unroll
    for (int o = 16; o; o >>= 1) {
        lsum += __shfl_xor_sync(0xffffffffu, lsum, o);
        lsq  += __shfl_xor_sync(0xffffffffu, lsq,  o);
    }
    if ((tid & 31) == 0) { rs_[tid >> 5] = lsum; rq_[tid >> 5] = lsq; }
    __syncthreads();
    float s = 0.f, q = 0.f;
    #pragma unroll
    for (int w = 0; w < 8; w++) { s += rs_[w]; q += rq_[w]; }
    float mu   = s * (1.0f / Dd);
    float var  = q * (1.0f / Dd) - mu * mu;
    float rstd = rsqrtf(var + 1e-5f);

    for (int c = tid; c < Dd; c += 256) {
        float v  = sxn[c];
        float xn = (v - mu) * rstd * g2[c] + b2[c];
        sxn[c] = xn;
        out[(size_t)token * Dd + c] = xn;
    }
    __syncthreads();

    float ar[8] = {}, an_[8] = {};
    for (int c = tid; c < Dd; c += 256) {
        float v = sxn[c];
        float4 w0 = *(const float4*)&Wr[(size_t)c * Ee];
        float4 w1 = *(const float4*)&Wr[(size_t)c * Ee + 4];
        ar[0] += v * w0.x; ar[1] += v * w0.y; ar[2] += v * w0.z; ar[3] += v * w0.w;
        ar[4] += v * w1.x; ar[5] += v * w1.y; ar[6] += v * w1.z; ar[7] += v * w1.w;
        float4 n0 = *(const float4*)&Wn[(size_t)c * Ee];
        float4 n1 = *(const float4*)&Wn[(size_t)c * Ee + 4];
        an_[0] += v * n0.x; an_[1] += v * n0.y; an_[2] += v * n0.z; an_[3] += v * n0.w;
        an_[4] += v * n1.x; an_[5] += v * n1.y; an_[6] += v * n1.z; an_[7] += v * n1.w;
    }
    #pragma unroll
    for (int o = 16; o; o >>= 1) {
        #pragma unroll
        for (int e = 0; e < 8; e++) {
            ar[e]  += __shfl_xor_sync(0xffffffffu, ar[e],  o);
            an_[e] += __shfl_xor_sync(0xffffffffu, an_[e], o);
        }
    }
    int w = tid >> 5;
    if ((tid & 31) == 0) {
        #pragma unroll
        for (int e = 0; e < 8; e++) { red[w][e] = ar[e]; red[w][8 + e] = an_[e]; }
    }
    __syncthreads();

    if (tid == 0) {
        float lg[8], nl[8];
        #pragma unroll
        for (int e = 0; e < 8; e++) { lg[e] = br[e]; nl[e] = bn[e]; }
        for (int ww = 0; ww < 8; ww++)
            #pragma unroll
            for (int e = 0; e < 8; e++) { lg[e] += red[ww][e]; nl[e] += red[ww][8 + e]; }

        float noisy[8];
        #pragma unroll
        for (int e = 0; e < 8; e++) {
            float nz = jax_noise((uint32_t)(token * Ee + e));
            noisy[e] = lg[e] + nz * softplus_f(nl[e]);
        }
        int i0 = 0; float v0 = noisy[0];
        #pragma unroll
        for (int e = 1; e < 8; e++) if (noisy[e] > v0) { v0 = noisy[e]; i0 = e; }
        int i1 = -1; float v1 = neg_inf();
        #pragma unroll
        for (int e = 0; e < 8; e++)
            if (e != i0 && noisy[e] > v1) { v1 = noisy[e]; i1 = e; }

        float e1 = expf(v1 - v0);
        float inv = 1.0f / (1.0f + e1);
        float p0 = inv, p1 = e1 * inv;

        float probs[8] = {};
        probs[i0] = p0; probs[i1] = p1;
        float* pout = out + OUT_OFF_PROBS + (size_t)token * Ee;
        #pragma unroll
        for (int e = 0; e < 8; e++) pout[e] = probs[e];
        out[OUT_OFF_IDX + (size_t)token * 2 + 0] = (float)i0;
        out[OUT_OFF_IDX + (size_t)token * 2 + 1] = (float)i1;
    }
}

// ---------------- launcher ---------------------------------------------------
extern "C" void kernel_launch(void* const* d_in, const int* in_sizes, int n_in,
                              void* d_out, int out_size)
{
    const int*   idx = (const int*)  d_in[0];
    const float* tok = (const float*)d_in[1];
    const float* pos = (const float*)d_in[2];
    const float* Wq  = (const float*)d_in[3];
    const float* Wk  = (const float*)d_in[4];
    const float* Wv  = (const float*)d_in[5];
    const float* Wo  = (const float*)d_in[6];
    const float* bo  = (const float*)d_in[7];
    const float* g1  = (const float*)d_in[8];
    const float* b1  = (const float*)d_in[9];
    const float* g2  = (const float*)d_in[10];
    const float* b2  = (const float*)d_in[11];
    const float* Wr  = (const float*)d_in[12];
    const float* br  = (const float*)d_in[13];
    const float* Wn  = (const float*)d_in[14];
    const float* bn  = (const float*)d_in[15];
    float* out = (float*)d_out;

    cudaFuncSetAttribute(attn_mma_kernel, cudaFuncAttributeMaxDynamicSharedMemorySize,
                         ATT_SMEM_F * (int)sizeof(float));
    cudaFuncSetAttribute(qkv_mma_kernel, cudaFuncAttributeMaxDynamicSharedMemorySize,
                         GEMM_SMEM_BYTES);
    cudaFuncSetAttribute(proj_mma_kernel, cudaFuncAttributeMaxDynamicSharedMemorySize,
                         GEMM_SMEM_BYTES);

    embed_ln_kernel<<<BT, 256>>>(idx, tok, pos, g1, b1);
    transpose_qkv_kernel<<<dim3(32, 4, 24), dim3(32, 8)>>>(Wq, Wk, Wv);
    transpose_wo_kernel<<<dim3(32, 32), dim3(32, 8)>>>(Wo);
    qkv_mma_kernel<<<dim3(BT / 256, 24), 256, GEMM_SMEM_BYTES>>>();
    attn_mma_kernel<<<dim3(Tt / 128, Bb * Hh), 256, ATT_SMEM_F * sizeof(float)>>>();
    proj_mma_kernel<<<dim3(BT / 256, Dd / 128), 256, GEMM_SMEM_BYTES>>>(bo);
    ln2_router_kernel<<<BT, 256>>>(g2, b2, Wr, br, Wn, bn, out);
}

// round 10
// speedup vs baseline: 2.6075x; 1.4713x over previous
#include <cuda_runtime.h>
#include <cstdint>

typedef unsigned short u16;

// Problem dims
#define Bb 4
#define Tt 2048
#define Dd 1024
#define Hh 8
#define HD 128
#define Ee 8
#define BT 8192            // Bb*Tt
#define TH (Tt*HD)         // 262144

// ---------------- scratch (device globals; no allocations allowed) ----------
__device__ float g_x   [BT*Dd];   // running residual x
__device__ u16   g_xn0 [BT*Dd];   // LN1(x) fp16 hi
__device__ u16   g_xn1 [BT*Dd];   // LN1(x) fp16 lo
__device__ float g_q   [BT*Dd];   // [B,H,T,HD]
__device__ float g_k   [BT*Dd];
__device__ float g_v   [BT*Dd];
__device__ u16   g_att0[BT*Dd];   // attention out fp16 hi  [B,T,H*HD]
__device__ u16   g_att1[BT*Dd];
__device__ u16   g_wt0 [3*Hh*HD*Dd];  // transposed QKV weights hi [z][d][c]
__device__ u16   g_wt1 [3*Hh*HD*Dd];
__device__ u16   g_wot0[Dd*Dd];       // Wo^T hi [n][k]
__device__ u16   g_wot1[Dd*Dd];

__device__ __forceinline__ float neg_inf() { return __int_as_float(0xff800000); }

// fp32 -> (fp16 hi, fp16 lo) split (base PTX)
__device__ __forceinline__ void splith(float v, u16& h, u16& l) {
    u16 hu; asm("cvt.rn.f16.f32 %0, %1;" : "=h"(hu) : "f"(v));
    float hf; asm("cvt.f32.f16 %0, %1;" : "=f"(hf) : "h"(hu));
    u16 lu; asm("cvt.rn.f16.f32 %0, %1;" : "=h"(lu) : "f"(v - hf));
    h = hu; l = lu;
}
__device__ __forceinline__ uint32_t pack2(u16 a, u16 b) {
    return (uint32_t)a | ((uint32_t)b << 16);
}

// m16n8k16 fp16 MMA, fp32 accum (base PTX, sm_80+)
__device__ __forceinline__ void mma_f16(float* d, const uint32_t* a, const uint32_t* b) {
    asm volatile("mma.sync.aligned.m16n8k16.row.col.f32.f16.f16.f32 "
        "{%0,%1,%2,%3}, {%4,%5,%6,%7}, {%8,%9}, {%0,%1,%2,%3};"
        : "+f"(d[0]), "+f"(d[1]), "+f"(d[2]), "+f"(d[3])
        : "r"(a[0]), "r"(a[1]), "r"(a[2]), "r"(a[3]), "r"(b[0]), "r"(b[1]));
}

// ldmatrix x4 b16 (base PTX, sm_75+)
__device__ __forceinline__ void ldsm4(uint32_t* r, uint32_t saddr) {
    asm volatile("ldmatrix.sync.aligned.m8n8.x4.shared.b16 {%0,%1,%2,%3}, [%4];"
        : "=r"(r[0]), "=r"(r[1]), "=r"(r[2]), "=r"(r[3]) : "r"(saddr));
}

// cp.async (base PTX, sm_80+)
__device__ __forceinline__ uint32_t smem_to_u32(const void* p) {
    uint32_t a;
    asm("{ .reg .u64 t; cvta.to.shared.u64 t, %1; cvt.u32.u64 %0, t; }" : "=r"(a) : "l"(p));
    return a;
}
__device__ __forceinline__ void cp_async16(uint32_t saddr, const void* gaddr) {
    asm volatile("cp.async.cg.shared.global [%0], [%1], 16;" :: "r"(saddr), "l"(gaddr));
}
__device__ __forceinline__ void cp_commit() { asm volatile("cp.async.commit_group;" ::: "memory"); }
template<int N> __device__ __forceinline__ void cp_wait() {
    asm volatile("cp.async.wait_group %0;" :: "n"(N) : "memory");
}

// ---------------- JAX threefry2x32 noise (partitionable scheme) --------------
__device__ __forceinline__ uint32_t rotl32(uint32_t v, int r) {
    return (v << r) | (v >> (32 - r));
}
__device__ float jax_noise(uint32_t i) {
    uint32_t x0 = 0u, x1 = i;
    const uint32_t k0 = 0u, k1 = 42u, k2 = 0u ^ 42u ^ 0x1BD11BDAu;
    x0 += k0; x1 += k1;
#define TF_ROUND(r) { x0 += x1; x1 = rotl32(x1, r); x1 ^= x0; }
#define TF_G0 TF_ROUND(13) TF_ROUND(15) TF_ROUND(26) TF_ROUND(6)
#define TF_G1 TF_ROUND(17) TF_ROUND(29) TF_ROUND(16) TF_ROUND(24)
    TF_G0; x0 += k1; x1 += k2 + 1u;
    TF_G1; x0 += k2; x1 += k0 + 2u;
    TF_G0; x0 += k0; x1 += k1 + 3u;
    TF_G1; x0 += k1; x1 += k2 + 4u;
    TF_G0; x0 += k2; x1 += k0 + 5u;
#undef TF_G1
#undef TF_G0
#undef TF_ROUND
    uint32_t bits = x0 ^ x1;
    float f = __uint_as_float((bits >> 9) | 0x3f800000u) - 1.0f;
    const float lo = -0.99999994f;
    float u = f * (1.0f - lo) + lo;
    u = fmaxf(u, lo);
    return 1.41421354f * erfinvf(u);
}
__device__ __forceinline__ float softplus_f(float x) {
    return fmaxf(x, 0.0f) + log1pf(expf(-fabsf(x)));
}

// ---------------- kernel 1: embedding + LayerNorm1 (writes split xn) ---------
__global__ __launch_bounds__(256) void embed_ln_kernel(
    const int* __restrict__ idx, const float* __restrict__ tok,
    const float* __restrict__ pos, const float* __restrict__ g1,
    const float* __restrict__ b1)
{
    int token = blockIdx.x;
    int t     = token & (Tt - 1);
    int tid   = threadIdx.x;
    __shared__ float sx[Dd];
    __shared__ float rs_[8], rq_[8];

    const float* trow = tok + (size_t)idx[token] * Dd;
    const float* prow = pos + (size_t)t * Dd;

    float lsum = 0.f, lsq = 0.f;
    for (int c = tid; c < Dd; c += 256) {
        float v = trow[c] + prow[c];
        sx[c] = v; lsum += v; lsq += v * v;
    }
    #pragma unroll
    for (int o = 16; o; o >>= 1) {
        lsum += __shfl_xor_sync(0xffffffffu, lsum, o);
        lsq  += __shfl_xor_sync(0xffffffffu, lsq,  o);
    }
    if ((tid & 31) == 0) { rs_[tid >> 5] = lsum; rq_[tid >> 5] = lsq; }
    __syncthreads();
    float s = 0.f, q = 0.f;
    #pragma unroll
    for (int w = 0; w < 8; w++) { s += rs_[w]; q += rq_[w]; }
    float mu   = s * (1.0f / Dd);
    float var  = q * (1.0f / Dd) - mu * mu;
    float rstd = rsqrtf(var + 1e-5f);

    float* xr = g_x + (size_t)token * Dd;
    for (int c = tid; c < Dd; c += 256) {
        float v = sx[c];
        xr[c] = v;
        float xn = (v - mu) * rstd * g1[c] + b1[c];
        u16 h, l; splith(xn, h, l);
        g_xn0[(size_t)token * Dd + c] = h;
        g_xn1[(size_t)token * Dd + c] = l;
    }
}

// ---------------- weight transposes (split to fp16 hi/lo) --------------------
__global__ __launch_bounds__(256) void transpose_qkv_kernel(
    const float* __restrict__ Wq, const float* __restrict__ Wk,
    const float* __restrict__ Wv)
{
    __shared__ float tile[32][33];
    int z = blockIdx.z; int which = z >> 3, h = z & 7;
    const float* src = (which == 0 ? Wq : which == 1 ? Wk : Wv) + (size_t)h * Dd * HD;
    size_t dbase = (size_t)z * HD * Dd;
    int c0 = blockIdx.x * 32, d0 = blockIdx.y * 32;
    int tx = threadIdx.x, ty = threadIdx.y;
    #pragma unroll
    for (int j = 0; j < 32; j += 8)
        tile[ty + j][tx] = src[(size_t)(c0 + ty + j) * HD + d0 + tx];
    __syncthreads();
    #pragma unroll
    for (int j = 0; j < 32; j += 8) {
        float v = tile[tx][ty + j];
        u16 hh, ll; splith(v, hh, ll);
        size_t o = dbase + (size_t)(d0 + ty + j) * Dd + c0 + tx;
        g_wt0[o] = hh;
        g_wt1[o] = ll;
    }
}

__global__ __launch_bounds__(256) void transpose_wo_kernel(const float* __restrict__ Wo)
{
    __shared__ float tile[32][33];
    int k0 = blockIdx.x * 32, n0 = blockIdx.y * 32;
    int tx = threadIdx.x, ty = threadIdx.y;
    #pragma unroll
    for (int j = 0; j < 32; j += 8)
        tile[ty + j][tx] = Wo[(size_t)(k0 + ty + j) * Dd + n0 + tx];
    __syncthreads();
    #pragma unroll
    for (int j = 0; j < 32; j += 8) {
        float v = tile[tx][ty + j];
        u16 hh, ll; splith(v, hh, ll);
        size_t o = (size_t)(n0 + ty + j) * Dd + k0 + tx;
        g_wot0[o] = hh;
        g_wot1[o] = ll;
    }
}

// ---------------- fp16x4 cp.async double-buffered GEMM core ------------------
// C[128x128] = A[128x1024] * B[128x1024]^T  (B stored [n][k]); fp16 hi/lo pre-split
// 256 threads (8 warps, 4x2); warp tile 32x64; K-chunk 32, 2 stages, 2 CTAs/SM.
#define NCHUNK 32
#define PCH 80                         // bytes per chunk-row (64B data + 16 pad)
#define ARR_B (128 * PCH)              // 10240 B per array
#define STAGE_B (4 * ARR_B)            // A0,A1,B0,B1 = 40960
#define GEMM_SMEM (2 * STAGE_B)        // 81920

__device__ __forceinline__ void gemm_issue(
    uint32_t sbase, int stage, int c,
    const u16* __restrict__ A0g, const u16* __restrict__ A1g,
    const u16* __restrict__ B0g, const u16* __restrict__ B1g, int tid)
{
    uint32_t sb = sbase + (uint32_t)(stage * STAGE_B);
    #pragma unroll
    for (int p = 0; p < 2; p++) {
        int f = tid + p * 256;              // 512 16B slots per array
        int row = f >> 2, c16 = f & 3;
        uint32_t so = (uint32_t)(row * PCH + c16 * 16);
        size_t go = (size_t)row * Dd + c * 32 + c16 * 8;
        cp_async16(sb + so,             A0g + go);
        cp_async16(sb + ARR_B + so,     A1g + go);
        cp_async16(sb + 2 * ARR_B + so, B0g + go);
        cp_async16(sb + 3 * ARR_B + so, B1g + go);
    }
}

__device__ __forceinline__ void gemm_mainloop(
    const u16* __restrict__ A0g, const u16* __restrict__ A1g,
    const u16* __restrict__ B0g, const u16* __restrict__ B1g,
    float acc[2][8][4], char* sm, int tid)
{
    uint32_t sbase = smem_to_u32(sm);
    int wid = tid >> 5, lane = tid & 31;
    int wm = (wid & 3) * 32, wn = (wid >> 2) * 64;
    int la15 = lane & 15, lh = lane >> 4;
    int lb = (lane & 7) + ((lane >> 4) << 3), lk = (lane >> 3) & 1;
    uint32_t aoff = (uint32_t)((wm + la15) * PCH + lh * 16);
    uint32_t boff = (uint32_t)(2 * ARR_B + (wn + lb) * PCH + lk * 16);

    gemm_issue(sbase, 0, 0, A0g, A1g, B0g, B1g, tid);
    cp_commit();

    for (int c = 0; c < NCHUNK; c++) {
        if (c + 1 < NCHUNK) {
            gemm_issue(sbase, (c + 1) & 1, c + 1, A0g, A1g, B0g, B1g, tid);
            cp_commit();
            cp_wait<1>();
        } else {
            cp_wait<0>();
        }
        __syncthreads();

        uint32_t stg = sbase + (uint32_t)((c & 1) * STAGE_B);
        #pragma unroll
        for (int k16 = 0; k16 < 2; k16++) {
            uint32_t ko = (uint32_t)(k16 * 32);
            uint32_t a0f[2][4], a1f[2][4];
            #pragma unroll
            for (int mt = 0; mt < 2; mt++) {
                ldsm4(a0f[mt], stg + aoff + mt * (16 * PCH) + ko);
                ldsm4(a1f[mt], stg + ARR_B + aoff + mt * (16 * PCH) + ko);
            }
            #pragma unroll
            for (int g = 0; g < 4; g++) {
                uint32_t b0f[4], b1f[4];
                ldsm4(b0f, stg + boff + g * (16 * PCH) + ko);
                ldsm4(b1f, stg + ARR_B + boff + g * (16 * PCH) + ko);
                #pragma unroll
                for (int h2 = 0; h2 < 2; h2++) {
                    int nt = 2 * g + h2;
                    uint32_t bh[2] = {b0f[2 * h2], b0f[2 * h2 + 1]};
                    uint32_t bl[2] = {b1f[2 * h2], b1f[2 * h2 + 1]};
                    #pragma unroll
                    for (int mt = 0; mt < 2; mt++) {
                        mma_f16(acc[mt][nt], a0f[mt], bh);
                        mma_f16(acc[mt][nt], a0f[mt], bl);
                        mma_f16(acc[mt][nt], a1f[mt], bh);
                        mma_f16(acc[mt][nt], a1f[mt], bl);
                    }
                }
            }
        }
        __syncthreads();
    }
}

// ---------------- kernel 2: QKV via fp16x4 mma (grid 64 x 24, 256 thr) -------
__global__ __launch_bounds__(256, 2) void qkv_mma_kernel()
{
    extern __shared__ char sm[];
    int tid = threadIdx.x, wid = tid >> 5, lane = tid & 31;
    int m0 = blockIdx.x * 128;
    int z  = blockIdx.y;
    const u16* A0 = g_xn0 + (size_t)m0 * Dd;
    const u16* A1 = g_xn1 + (size_t)m0 * Dd;
    const u16* B0 = g_wt0 + (size_t)z * HD * Dd;
    const u16* B1 = g_wt1 + (size_t)z * HD * Dd;

    float acc[2][8][4];
    #pragma unroll
    for (int mt = 0; mt < 2; mt++)
        #pragma unroll
        for (int nt = 0; nt < 8; nt++)
            #pragma unroll
            for (int r = 0; r < 4; r++) acc[mt][nt][r] = 0.f;

    gemm_mainloop(A0, A1, B0, B1, acc, sm, tid);

    int wm = (wid & 3) * 32, wn = (wid >> 2) * 64;
    int lr = lane >> 2, lc = lane & 3;
    int which = z >> 3, h = z & 7;
    float* Ob = (which == 0 ? g_q : which == 1 ? g_k : g_v);
    #pragma unroll
    for (int mt = 0; mt < 2; mt++) {
        int m = m0 + wm + mt * 16 + lr;
        int bb = m >> 11, tt = m & (Tt - 1);
        float* row0 = Ob + ((size_t)(bb * Hh + h) * Tt + tt) * HD + wn + lc * 2;
        #pragma unroll
        for (int nt = 0; nt < 8; nt++) {
            float* p0 = row0 + nt * 8;
            p0[0]          = acc[mt][nt][0];
            p0[1]          = acc[mt][nt][1];
            p0[8 * HD]     = acc[mt][nt][2];
            p0[8 * HD + 1] = acc[mt][nt][3];
        }
    }
}

// ---------------- kernel 4: proj + residual (grid 64 x 8, 256 thr) -----------
__global__ __launch_bounds__(256, 2) void proj_mma_kernel(const float* __restrict__ bo)
{
    extern __shared__ char sm[];
    int tid = threadIdx.x, wid = tid >> 5, lane = tid & 31;
    int m0 = blockIdx.x * 128;
    int n0 = blockIdx.y * 128;
    const u16* A0 = g_att0 + (size_t)m0 * Dd;
    const u16* A1 = g_att1 + (size_t)m0 * Dd;
    const u16* B0 = g_wot0 + (size_t)n0 * Dd;
    const u16* B1 = g_wot1 + (size_t)n0 * Dd;

    float acc[2][8][4];
    #pragma unroll
    for (int mt = 0; mt < 2; mt++)
        #pragma unroll
        for (int nt = 0; nt < 8; nt++)
            #pragma unroll
            for (int r = 0; r < 4; r++) acc[mt][nt][r] = 0.f;

    gemm_mainloop(A0, A1, B0, B1, acc, sm, tid);

    int wm = (wid & 3) * 32, wn = (wid >> 2) * 64;
    int lr = lane >> 2, lc = lane & 3;
    #pragma unroll
    for (int mt = 0; mt < 2; mt++) {
        int m = m0 + wm + mt * 16 + lr;
        float* xrow = g_x + (size_t)m * Dd + n0 + wn + lc * 2;
        const float* brow = bo + n0 + wn + lc * 2;
        #pragma unroll
        for (int nt = 0; nt < 8; nt++) {
            float* p0 = xrow + nt * 8;
            const float* b0 = brow + nt * 8;
            p0[0]          += acc[mt][nt][0] + b0[0];
            p0[1]          += acc[mt][nt][1] + b0[1];
            p0[8 * Dd]     += acc[mt][nt][2] + b0[0];
            p0[8 * Dd + 1] += acc[mt][nt][3] + b0[1];
        }
    }
}

// ---------------- kernel 3: causal flash attention, fp16x4 -------------------
// Q tile 128 x KV tile 64; 256 thr, 8 warps; warp w owns rows [16w,16w+16).
// smem (bytes): Q0/Q1 [128][272], K0/K1 [64][272], V0/V1 [128][144], P0/P1 [128][144]
#define OFF_Q0 0
#define OFF_Q1 34816
#define OFF_K0 69632
#define OFF_K1 87040
#define OFF_V0 104448
#define OFF_V1 122880
#define OFF_P0 141312
#define OFF_P1 159744
#define ATT_SMEM_B 178176
__global__ __launch_bounds__(256) void attn_mma_kernel()
{
    extern __shared__ char smx[];
    int bh = blockIdx.y, qt = blockIdx.x;
    int t0 = qt * 128;
    const float* Qg = g_q + (size_t)bh * TH;
    const float* Kg = g_k + (size_t)bh * TH;
    const float* Vg = g_v + (size_t)bh * TH;

    int tid = threadIdx.x, wid = tid >> 5, lane = tid & 31;
    int lr = lane >> 2, lc = lane & 3;
    const float scale = 0.03125f;

    int la15 = lane & 15, lh = lane >> 4;
    int lb = (lane & 7) + ((lane >> 4) << 3), lk = (lane >> 3) & 1;
    uint32_t sb = smem_to_u32(smx);
    uint32_t q0u = sb + OFF_Q0 + (uint32_t)((16 * wid + la15) * 272 + lh * 16);
    uint32_t q1u = q0u + (OFF_Q1 - OFF_Q0);
    uint32_t k0u = sb + OFF_K0 + (uint32_t)(lb * 272 + lk * 16);
    uint32_t k1u = k0u + (OFF_K1 - OFF_K0);
    uint32_t p0u = sb + OFF_P0 + (uint32_t)((16 * wid + la15) * 144 + lh * 16);
    uint32_t p1u = p0u + (OFF_P1 - OFF_P0);
    uint32_t v0u = sb + OFF_V0 + (uint32_t)(lb * 144 + lk * 16);
    uint32_t v1u = v0u + (OFF_V1 - OFF_V0);

    // Q tile: load fp32, scale, split fp16 hi/lo
    #pragma unroll 4
    for (int i = tid; i < 128 * 32; i += 256) {
        int r = i >> 5, c4 = (i & 31) << 2;
        float4 qv = *(const float4*)&Qg[(size_t)(t0 + r) * HD + c4];
        u16 h0,l0,h1,l1,h2,l2,h3,l3;
        splith(qv.x * scale, h0, l0); splith(qv.y * scale, h1, l1);
        splith(qv.z * scale, h2, l2); splith(qv.w * scale, h3, l3);
        *(uint2*)(smx + OFF_Q0 + r * 272 + c4 * 2) = make_uint2(pack2(h0,h1), pack2(h2,h3));
        *(uint2*)(smx + OFF_Q1 + r * 272 + c4 * 2) = make_uint2(pack2(l0,l1), pack2(l2,l3));
    }

    float o_acc[16][4];
    #pragma unroll
    for (int nt = 0; nt < 16; nt++)
        #pragma unroll
        for (int r = 0; r < 4; r++) o_acc[nt][r] = 0.f;
    float m_i[2] = {neg_inf(), neg_inf()};
    float l_i[2] = {0.f, 0.f};

    int row_w = t0 + 16 * wid;
    int ntiles = 2 * (qt + 1);
    for (int j = 0; j < ntiles; j++) {
        int s0 = 64 * j;
        __syncthreads();                 // prior tile's readers done
        // K tile: split fp16 hi/lo, layout [s][d]
        #pragma unroll
        for (int p = 0; p < 8; p++) {
            int i = tid + p * 256;
            int s = i >> 5, c4 = (i & 31) << 2;
            float4 kv = *(const float4*)&Kg[(size_t)(s0 + s) * HD + c4];
            u16 h0,l0,h1,l1,h2,l2,h3,l3;
            splith(kv.x, h0, l0); splith(kv.y, h1, l1);
            splith(kv.z, h2, l2); splith(kv.w, h3, l3);
            *(uint2*)(smx + OFF_K0 + s * 272 + c4 * 2) = make_uint2(pack2(h0,h1), pack2(h2,h3));
            *(uint2*)(smx + OFF_K1 + s * 272 + c4 * 2) = make_uint2(pack2(l0,l1), pack2(l2,l3));
        }
        // V tile: split, transposed [d][s]
        #pragma unroll
        for (int p = 0; p < 8; p++) {
            int i = tid + p * 256;
            int dq = i & 3, sg = (i >> 2) & 7, blk = i >> 5;
            int s = (blk & 7) * 8 + sg, d = (blk >> 3) * 16 + dq * 4;
            float4 vv = *(const float4*)&Vg[(size_t)(s0 + s) * HD + d];
            u16* V0p = (u16*)(smx + OFF_V0);
            u16* V1p = (u16*)(smx + OFF_V1);
            u16 hh, ll;
            splith(vv.x, hh, ll); V0p[(d + 0) * 72 + s] = hh; V1p[(d + 0) * 72 + s] = ll;
            splith(vv.y, hh, ll); V0p[(d + 1) * 72 + s] = hh; V1p[(d + 1) * 72 + s] = ll;
            splith(vv.z, hh, ll); V0p[(d + 2) * 72 + s] = hh; V1p[(d + 2) * 72 + s] = ll;
            splith(vv.w, hh, ll); V0p[(d + 3) * 72 + s] = hh; V1p[(d + 3) * 72 + s] = ll;
        }
        __syncthreads();

        bool active = (s0 <= row_w + 15);
        if (active) {
            float sacc[8][4];
            #pragma unroll
            for (int nt = 0; nt < 8; nt++)
                #pragma unroll
                for (int r = 0; r < 4; r++) sacc[nt][r] = 0.f;

            // S = Q K^T (16x64), fp16x4
            #pragma unroll 2
            for (int k16 = 0; k16 < 8; k16++) {
                uint32_t ko = (uint32_t)(k16 * 32);
                uint32_t qa0[4], qa1[4];
                ldsm4(qa0, q0u + ko);
                ldsm4(qa1, q1u + ko);
                #pragma unroll
                for (int g = 0; g < 4; g++) {
                    uint32_t kf0[4], kf1[4];
                    ldsm4(kf0, k0u + g * (16 * 272) + ko);
                    ldsm4(kf1, k1u + g * (16 * 272) + ko);
                    #pragma unroll
                    for (int h2 = 0; h2 < 2; h2++) {
                        int nt = 2 * g + h2;
                        uint32_t bh[2] = {kf0[2 * h2], kf0[2 * h2 + 1]};
                        uint32_t bl[2] = {kf1[2 * h2], kf1[2 * h2 + 1]};
                        mma_f16(sacc[nt], qa0, bh);
                        mma_f16(sacc[nt], qa0, bl);
                        mma_f16(sacc[nt], qa1, bh);
                        mma_f16(sacc[nt], qa1, bl);
                    }
                }
            }
            // causal mask
            if (s0 + 63 > row_w) {
                int r0 = row_w + lr;
                #pragma unroll
                for (int nt = 0; nt < 8; nt++) {
                    int cb = s0 + 8 * nt + 2 * lc;
                    if (cb     > r0)     sacc[nt][0] = neg_inf();
                    if (cb + 1 > r0)     sacc[nt][1] = neg_inf();
                    if (cb     > r0 + 8) sacc[nt][2] = neg_inf();
                    if (cb + 1 > r0 + 8) sacc[nt][3] = neg_inf();
                }
            }
            // online softmax (rows lr, lr+8; quad shuffles)
            float rm0 = neg_inf(), rm1 = neg_inf();
            #pragma unroll
            for (int nt = 0; nt < 8; nt++) {
                rm0 = fmaxf(rm0, fmaxf(sacc[nt][0], sacc[nt][1]));
                rm1 = fmaxf(rm1, fmaxf(sacc[nt][2], sacc[nt][3]));
            }
            rm0 = fmaxf(rm0, __shfl_xor_sync(0xffffffffu, rm0, 1));
            rm0 = fmaxf(rm0, __shfl_xor_sync(0xffffffffu, rm0, 2));
            rm1 = fmaxf(rm1, __shfl_xor_sync(0xffffffffu, rm1, 1));
            rm1 = fmaxf(rm1, __shfl_xor_sync(0xffffffffu, rm1, 2));
            float mn0 = fmaxf(m_i[0], rm0), mn1 = fmaxf(m_i[1], rm1);
            float al0 = expf(m_i[0] - mn0), al1 = expf(m_i[1] - mn1);
            float rs0 = 0.f, rs1 = 0.f;
            #pragma unroll
            for (int nt = 0; nt < 8; nt++) {
                sacc[nt][0] = expf(sacc[nt][0] - mn0);
                sacc[nt][1] = expf(sacc[nt][1] - mn0);
                sacc[nt][2] = expf(sacc[nt][2] - mn1);
                sacc[nt][3] = expf(sacc[nt][3] - mn1);
                rs0 += sacc[nt][0] + sacc[nt][1];
                rs1 += sacc[nt][2] + sacc[nt][3];
            }
            rs0 += __shfl_xor_sync(0xffffffffu, rs0, 1);
            rs0 += __shfl_xor_sync(0xffffffffu, rs0, 2);
            rs1 += __shfl_xor_sync(0xffffffffu, rs1, 1);
            rs1 += __shfl_xor_sync(0xffffffffu, rs1, 2);
            l_i[0] = l_i[0] * al0 + rs0;  m_i[0] = mn0;
            l_i[1] = l_i[1] * al1 + rs1;  m_i[1] = mn1;
            #pragma unroll
            for (int nt = 0; nt < 16; nt++) {
                o_acc[nt][0] *= al0; o_acc[nt][1] *= al0;
                o_acc[nt][2] *= al1; o_acc[nt][3] *= al1;
            }
            // store P split to smem (warp-private rows)
            #pragma unroll
            for (int nt = 0; nt < 8; nt++) {
                u16 h0,l0,h1,l1,h2,l2,h3,l3;
                splith(sacc[nt][0], h0, l0); splith(sacc[nt][1], h1, l1);
                splith(sacc[nt][2], h2, l2); splith(sacc[nt][3], h3, l3);
                int co = (8 * nt + 2 * lc) * 2;
                *(uint32_t*)(smx + OFF_P0 + (16 * wid + lr) * 144 + co)       = pack2(h0, h1);
                *(uint32_t*)(smx + OFF_P1 + (16 * wid + lr) * 144 + co)       = pack2(l0, l1);
                *(uint32_t*)(smx + OFF_P0 + (16 * wid + lr + 8) * 144 + co)   = pack2(h2, h3);
                *(uint32_t*)(smx + OFF_P1 + (16 * wid + lr + 8) * 144 + co)   = pack2(l2, l3);
            }
            __syncwarp();
            // O += P V (16x128), fp16x4
            #pragma unroll 2
            for (int k16 = 0; k16 < 4; k16++) {
                uint32_t ko = (uint32_t)(k16 * 32);
                uint32_t pa0[4], pa1[4];
                ldsm4(pa0, p0u + ko);
                ldsm4(pa1, p1u + ko);
                #pragma unroll
                for (int g = 0; g < 8; g++) {
                    uint32_t vf0[4], vf1[4];
                    ldsm4(vf0, v0u + g * (16 * 144) + ko);
                    ldsm4(vf1, v1u + g * (16 * 144) + ko);
                    #pragma unroll
                    for (int h2 = 0; h2 < 2; h2++) {
                        int nt = 2 * g + h2;
                        uint32_t bh[2] = {vf0[2 * h2], vf0[2 * h2 + 1]};
                        uint32_t bl[2] = {vf1[2 * h2], vf1[2 * h2 + 1]};
                        mma_f16(o_acc[nt], pa0, bh);
                        mma_f16(o_acc[nt], pa0, bl);
                        mma_f16(o_acc[nt], pa1, bh);
                        mma_f16(o_acc[nt], pa1, bl);
                    }
                }
            }
        }
    }

    // epilogue: write split attention output [B, T, H*HD] (fp16 hi/lo)
    float inv0 = 1.0f / l_i[0], inv1 = 1.0f / l_i[1];
    int bb = bh >> 3, h = bh & 7;
    int r0 = row_w + lr;
    size_t base0 = ((size_t)(bb * Tt + r0)) * Dd + h * HD;
    size_t base1 = ((size_t)(bb * Tt + r0 + 8)) * Dd + h * HD;
    #pragma unroll
    for (int nt = 0; nt < 16; nt++) {
        int col = 8 * nt + 2 * lc;
        u16 h0,l0,h1,l1,h2,l2,h3,l3;
        splith(o_acc[nt][0] * inv0, h0, l0); splith(o_acc[nt][1] * inv0, h1, l1);
        splith(o_acc[nt][2] * inv1, h2, l2); splith(o_acc[nt][3] * inv1, h3, l3);
        *(uint32_t*)&g_att0[base0 + col] = pack2(h0, h1);
        *(uint32_t*)&g_att1[base0 + col] = pack2(l0, l1);
        *(uint32_t*)&g_att0[base1 + col] = pack2(h2, h3);
        *(uint32_t*)&g_att1[base1 + col] = pack2(l2, l3);
    }
}

// ---------------- kernel 5: LayerNorm2 + noisy top-2 router + outputs --------
#define OUT_OFF_PROBS (BT * Dd)
#define OUT_OFF_IDX   (OUT_OFF_PROBS + BT * Ee)
#define OUT_OFF_X     (OUT_OFF_IDX + BT * 2)
__global__ __launch_bounds__(256) void ln2_router_kernel(
    const float* __restrict__ g2, const float* __restrict__ b2,
    const float* __restrict__ Wr, const float* __restrict__ br,
    const float* __restrict__ Wn, const float* __restrict__ bn,
    float* __restrict__ out)
{
    int token = blockIdx.x;
    int tid = threadIdx.x;
    __shared__ float sxn[Dd];
    __shared__ float rs_[8], rq_[8];
    __shared__ float red[8][16];

    const float* xr = g_x + (size_t)token * Dd;
    float lsum = 0.f, lsq = 0.f;
    for (int c = tid; c < Dd; c += 256) {
        float v = xr[c];
        sxn[c] = v;
        out[OUT_OFF_X + (size_t)token * Dd + c] = v;
        lsum += v; lsq += v * v;
    }
    #pragma unroll
    for (int o = 16; o; o >>= 1) {
        lsum += __shfl_xor_sync(0xffffffffu, lsum, o);
        lsq  += __shfl_xor_sync(0xffffffffu, lsq,  o);
    }
    if ((tid & 31) == 0) { rs_[tid >> 5] = lsum; rq_[tid >> 5] = lsq; }
    __syncthreads();
    float s = 0.f, q = 0.f;
    #pragma unroll
    for (int w = 0; w < 8; w++) { s += rs_[w]; q += rq_[w]; }
    float mu   = s * (1.0f / Dd);
    float var  = q * (1.0f / Dd) - mu * mu;
    float rstd = rsqrtf(var + 1e-5f);

    for (int c = tid; c < Dd; c += 256) {
        float v  = sxn[c];
        float xn = (v - mu) * rstd * g2[c] + b2[c];
        sxn[c] = xn;
        out[(size_t)token * Dd + c] = xn;
    }
    __syncthreads();

    float ar[8] = {}, an_[8] = {};
    for (int c = tid; c < Dd; c += 256) {
        float v = sxn[c];
        float4 w0 = *(const float4*)&Wr[(size_t)c * Ee];
        float4 w1 = *(const float4*)&Wr[(size_t)c * Ee + 4];
        ar[0] += v * w0.x; ar[1] += v * w0.y; ar[2] += v * w0.z; ar[3] += v * w0.w;
        ar[4] += v * w1.x; ar[5] += v * w1.y; ar[6] += v * w1.z; ar[7] += v * w1.w;
        float4 n0 = *(const float4*)&Wn[(size_t)c * Ee];
        float4 n1 = *(const float4*)&Wn[(size_t)c * Ee + 4];
        an_[0] += v * n0.x; an_[1] += v * n0.y; an_[2] += v * n0.z; an_[3] += v * n0.w;
        an_[4] += v * n1.x; an_[5] += v * n1.y; an_[6] += v * n1.z; an_[7] += v * n1.w;
    }
    #pragma unroll
    for (int o = 16; o; o >>= 1) {
        #pragma unroll
        for (int e = 0; e < 8; e++) {
            ar[e]  += __shfl_xor_sync(0xffffffffu, ar[e],  o);
            an_[e] += __shfl_xor_sync(0xffffffffu, an_[e], o);
        }
    }
    int w = tid >> 5;
    if ((tid & 31) == 0) {
        #pragma unroll
        for (int e = 0; e < 8; e++) { red[w][e] = ar[e]; red[w][8 + e] = an_[e]; }
    }
    __syncthreads();

    if (tid == 0) {
        float lg[8], nl[8];
        #pragma unroll
        for (int e = 0; e < 8; e++) { lg[e] = br[e]; nl[e] = bn[e]; }
        for (int ww = 0; ww < 8; ww++)
            #pragma unroll
            for (int e = 0; e < 8; e++) { lg[e] += red[ww][e]; nl[e] += red[ww][8 + e]; }

        float noisy[8];
        #pragma unroll
        for (int e = 0; e < 8; e++) {
            float nz = jax_noise((uint32_t)(token * Ee + e));
            noisy[e] = lg[e] + nz * softplus_f(nl[e]);
        }
        int i0 = 0; float v0 = noisy[0];
        #pragma unroll
        for (int e = 1; e < 8; e++) if (noisy[e] > v0) { v0 = noisy[e]; i0 = e; }
        int i1 = -1; float v1 = neg_inf();
        #pragma unroll
        for (int e = 0; e < 8; e++)
            if (e != i0 && noisy[e] > v1) { v1 = noisy[e]; i1 = e; }

        float e1 = expf(v1 - v0);
        float inv = 1.0f / (1.0f + e1);
        float p0 = inv, p1 = e1 * inv;

        float probs[8] = {};
        probs[i0] = p0; probs[i1] = p1;
        float* pout = out + OUT_OFF_PROBS + (size_t)token * Ee;
        #pragma unroll
        for (int e = 0; e < 8; e++) pout[e] = probs[e];
        out[OUT_OFF_IDX + (size_t)token * 2 + 0] = (float)i0;
        out[OUT_OFF_IDX + (size_t)token * 2 + 1] = (float)i1;
    }
}

// ---------------- launcher ---------------------------------------------------
extern "C" void kernel_launch(void* const* d_in, const int* in_sizes, int n_in,
                              void* d_out, int out_size)
{
    const int*   idx = (const int*)  d_in[0];
    const float* tok = (const float*)d_in[1];
    const float* pos = (const float*)d_in[2];
    const float* Wq  = (const float*)d_in[3];
    const float* Wk  = (const float*)d_in[4];
    const float* Wv  = (const float*)d_in[5];
    const float* Wo  = (const float*)d_in[6];
    const float* bo  = (const float*)d_in[7];
    const float* g1  = (const float*)d_in[8];
    const float* b1  = (const float*)d_in[9];
    const float* g2  = (const float*)d_in[10];
    const float* b2  = (const float*)d_in[11];
    const float* Wr  = (const float*)d_in[12];
    const float* br  = (const float*)d_in[13];
    const float* Wn  = (const float*)d_in[14];
    const float* bn  = (const float*)d_in[15];
    float* out = (float*)d_out;

    cudaFuncSetAttribute(attn_mma_kernel, cudaFuncAttributeMaxDynamicSharedMemorySize,
                         ATT_SMEM_B);
    cudaFuncSetAttribute(qkv_mma_kernel, cudaFuncAttributeMaxDynamicSharedMemorySize,
                         GEMM_SMEM);
    cudaFuncSetAttribute(proj_mma_kernel, cudaFuncAttributeMaxDynamicSharedMemorySize,
                         GEMM_SMEM);

    embed_ln_kernel<<<BT, 256>>>(idx, tok, pos, g1, b1);
    transpose_qkv_kernel<<<dim3(32, 4, 24), dim3(32, 8)>>>(Wq, Wk, Wv);
    transpose_wo_kernel<<<dim3(32, 32), dim3(32, 8)>>>(Wo);
    qkv_mma_kernel<<<dim3(BT / 128, 24), 256, GEMM_SMEM>>>();
    attn_mma_kernel<<<dim3(Tt / 128, Bb * Hh), 256, ATT_SMEM_B>>>();
    proj_mma_kernel<<<dim3(BT / 128, Dd / 128), 256, GEMM_SMEM>>>(bo);
    ln2_router_kernel<<<BT, 256>>>(g2, b2, Wr, br, Wn, bn, out);
}

// round 11
// speedup vs baseline: 3.1127x; 1.1938x over previous
#include <cuda_runtime.h>
#include <cstdint>

typedef unsigned short u16;

// Problem dims
#define Bb 4
#define Tt 2048
#define Dd 1024
#define Hh 8
#define HD 128
#define Ee 8
#define BT 8192            // Bb*Tt
#define TH (Tt*HD)         // 262144

// ---------------- scratch (device globals; no allocations allowed) ----------
__device__ float g_x   [BT*Dd];   // running residual x
__device__ u16   g_xn0 [BT*Dd];   // LN1(x) fp16 hi
__device__ u16   g_xn1 [BT*Dd];   // LN1(x) fp16 lo
__device__ u16   g_q0  [BT*Dd];   // scaled Q fp16 hi  [bh][t][d]
__device__ u16   g_q1  [BT*Dd];
__device__ u16   g_k0  [BT*Dd];   // K fp16 hi  [bh][t][d]
__device__ u16   g_k1  [BT*Dd];
__device__ u16   g_v0t [BT*Dd];   // V fp16 hi, transposed [bh][d][t]
__device__ u16   g_v1t [BT*Dd];
__device__ u16   g_att0[BT*Dd];   // attention out fp16 hi  [B,T,H*HD]
__device__ u16   g_att1[BT*Dd];
__device__ u16   g_wt0 [3*Hh*HD*Dd];  // transposed QKV weights hi [z][d][c]
__device__ u16   g_wt1 [3*Hh*HD*Dd];
__device__ u16   g_wot0[Dd*Dd];       // Wo^T hi [n][k]
__device__ u16   g_wot1[Dd*Dd];

__device__ __forceinline__ float neg_inf() { return __int_as_float(0xff800000); }

// fp32 -> (fp16 hi, fp16 lo) split (base PTX)
__device__ __forceinline__ void splith(float v, u16& h, u16& l) {
    u16 hu; asm("cvt.rn.f16.f32 %0, %1;" : "=h"(hu) : "f"(v));
    float hf; asm("cvt.f32.f16 %0, %1;" : "=f"(hf) : "h"(hu));
    u16 lu; asm("cvt.rn.f16.f32 %0, %1;" : "=h"(lu) : "f"(v - hf));
    h = hu; l = lu;
}
__device__ __forceinline__ uint32_t pack2(u16 a, u16 b) {
    return (uint32_t)a | ((uint32_t)b << 16);
}

// m16n8k16 fp16 MMA, fp32 accum (base PTX, sm_80+)
__device__ __forceinline__ void mma_f16(float* d, const uint32_t* a, const uint32_t* b) {
    asm volatile("mma.sync.aligned.m16n8k16.row.col.f32.f16.f16.f32 "
        "{%0,%1,%2,%3}, {%4,%5,%6,%7}, {%8,%9}, {%0,%1,%2,%3};"
        : "+f"(d[0]), "+f"(d[1]), "+f"(d[2]), "+f"(d[3])
        : "r"(a[0]), "r"(a[1]), "r"(a[2]), "r"(a[3]), "r"(b[0]), "r"(b[1]));
}

// ldmatrix x4 b16 (base PTX, sm_75+)
__device__ __forceinline__ void ldsm4(uint32_t* r, uint32_t saddr) {
    asm volatile("ldmatrix.sync.aligned.m8n8.x4.shared.b16 {%0,%1,%2,%3}, [%4];"
        : "=r"(r[0]), "=r"(r[1]), "=r"(r[2]), "=r"(r[3]) : "r"(saddr));
}

// cp.async (base PTX, sm_80+)
__device__ __forceinline__ uint32_t smem_to_u32(const void* p) {
    uint32_t a;
    asm("{ .reg .u64 t; cvta.to.shared.u64 t, %1; cvt.u32.u64 %0, t; }" : "=r"(a) : "l"(p));
    return a;
}
__device__ __forceinline__ void cp_async16(uint32_t saddr, const void* gaddr) {
    asm volatile("cp.async.cg.shared.global [%0], [%1], 16;" :: "r"(saddr), "l"(gaddr));
}
__device__ __forceinline__ void cp_commit() { asm volatile("cp.async.commit_group;" ::: "memory"); }
template<int N> __device__ __forceinline__ void cp_wait() {
    asm volatile("cp.async.wait_group %0;" :: "n"(N) : "memory");
}

// ---------------- JAX threefry2x32 noise (partitionable scheme) --------------
__device__ __forceinline__ uint32_t rotl32(uint32_t v, int r) {
    return (v << r) | (v >> (32 - r));
}
__device__ float jax_noise(uint32_t i) {
    uint32_t x0 = 0u, x1 = i;
    const uint32_t k0 = 0u, k1 = 42u, k2 = 0u ^ 42u ^ 0x1BD11BDAu;
    x0 += k0; x1 += k1;
#define TF_ROUND(r) { x0 += x1; x1 = rotl32(x1, r); x1 ^= x0; }
#define TF_G0 TF_ROUND(13) TF_ROUND(15) TF_ROUND(26) TF_ROUND(6)
#define TF_G1 TF_ROUND(17) TF_ROUND(29) TF_ROUND(16) TF_ROUND(24)
    TF_G0; x0 += k1; x1 += k2 + 1u;
    TF_G1; x0 += k2; x1 += k0 + 2u;
    TF_G0; x0 += k0; x1 += k1 + 3u;
    TF_G1; x0 += k1; x1 += k2 + 4u;
    TF_G0; x0 += k2; x1 += k0 + 5u;
#undef TF_G1
#undef TF_G0
#undef TF_ROUND
    uint32_t bits = x0 ^ x1;
    float f = __uint_as_float((bits >> 9) | 0x3f800000u) - 1.0f;
    const float lo = -0.99999994f;
    float u = f * (1.0f - lo) + lo;
    u = fmaxf(u, lo);
    return 1.41421354f * erfinvf(u);
}
__device__ __forceinline__ float softplus_f(float x) {
    return fmaxf(x, 0.0f) + log1pf(expf(-fabsf(x)));
}

// ---------------- kernel 1: embedding + LayerNorm1 (writes split xn) ---------
__global__ __launch_bounds__(256) void embed_ln_kernel(
    const int* __restrict__ idx, const float* __restrict__ tok,
    const float* __restrict__ pos, const float* __restrict__ g1,
    const float* __restrict__ b1)
{
    int token = blockIdx.x;
    int t     = token & (Tt - 1);
    int tid   = threadIdx.x;
    __shared__ float sx[Dd];
    __shared__ float rs_[8], rq_[8];

    const float* trow = tok + (size_t)idx[token] * Dd;
    const float* prow = pos + (size_t)t * Dd;

    float lsum = 0.f, lsq = 0.f;
    for (int c = tid; c < Dd; c += 256) {
        float v = trow[c] + prow[c];
        sx[c] = v; lsum += v; lsq += v * v;
    }
    #pragma unroll
    for (int o = 16; o; o >>= 1) {
        lsum += __shfl_xor_sync(0xffffffffu, lsum, o);
        lsq  += __shfl_xor_sync(0xffffffffu, lsq,  o);
    }
    if ((tid & 31) == 0) { rs_[tid >> 5] = lsum; rq_[tid >> 5] = lsq; }
    __syncthreads();
    float s = 0.f, q = 0.f;
    #pragma unroll
    for (int w = 0; w < 8; w++) { s += rs_[w]; q += rq_[w]; }
    float mu   = s * (1.0f / Dd);
    float var  = q * (1.0f / Dd) - mu * mu;
    float rstd = rsqrtf(var + 1e-5f);

    float* xr = g_x + (size_t)token * Dd;
    for (int c = tid; c < Dd; c += 256) {
        float v = sx[c];
        xr[c] = v;
        float xn = (v - mu) * rstd * g1[c] + b1[c];
        u16 h, l; splith(xn, h, l);
        g_xn0[(size_t)token * Dd + c] = h;
        g_xn1[(size_t)token * Dd + c] = l;
    }
}

// ---------------- weight transposes (split to fp16 hi/lo) --------------------
__global__ __launch_bounds__(256) void transpose_qkv_kernel(
    const float* __restrict__ Wq, const float* __restrict__ Wk,
    const float* __restrict__ Wv)
{
    __shared__ float tile[32][33];
    int z = blockIdx.z; int which = z >> 3, h = z & 7;
    const float* src = (which == 0 ? Wq : which == 1 ? Wk : Wv) + (size_t)h * Dd * HD;
    size_t dbase = (size_t)z * HD * Dd;
    int c0 = blockIdx.x * 32, d0 = blockIdx.y * 32;
    int tx = threadIdx.x, ty = threadIdx.y;
    #pragma unroll
    for (int j = 0; j < 32; j += 8)
        tile[ty + j][tx] = src[(size_t)(c0 + ty + j) * HD + d0 + tx];
    __syncthreads();
    #pragma unroll
    for (int j = 0; j < 32; j += 8) {
        float v = tile[tx][ty + j];
        u16 hh, ll; splith(v, hh, ll);
        size_t o = dbase + (size_t)(d0 + ty + j) * Dd + c0 + tx;
        g_wt0[o] = hh;
        g_wt1[o] = ll;
    }
}

__global__ __launch_bounds__(256) void transpose_wo_kernel(const float* __restrict__ Wo)
{
    __shared__ float tile[32][33];
    int k0 = blockIdx.x * 32, n0 = blockIdx.y * 32;
    int tx = threadIdx.x, ty = threadIdx.y;
    #pragma unroll
    for (int j = 0; j < 32; j += 8)
        tile[ty + j][tx] = Wo[(size_t)(k0 + ty + j) * Dd + n0 + tx];
    __syncthreads();
    #pragma unroll
    for (int j = 0; j < 32; j += 8) {
        float v = tile[tx][ty + j];
        u16 hh, ll; splith(v, hh, ll);
        size_t o = (size_t)(n0 + ty + j) * Dd + k0 + tx;
        g_wot0[o] = hh;
        g_wot1[o] = ll;
    }
}

// ---------------- fp16x3 cp.async double-buffered GEMM core ------------------
// C[128x128] = A[128x1024] * B[128x1024]^T; fp16 hi/lo pre-split; 3-MMA scheme
#define NCHUNK 32
#define PCH 80
#define ARR_B (128 * PCH)              // 10240 B per array
#define STAGE_B (4 * ARR_B)            // 40960
#define GEMM_SMEM (2 * STAGE_B)        // 81920

__device__ __forceinline__ void gemm_issue(
    uint32_t sbase, int stage, int c,
    const u16* __restrict__ A0g, const u16* __restrict__ A1g,
    const u16* __restrict__ B0g, const u16* __restrict__ B1g, int tid)
{
    uint32_t sb = sbase + (uint32_t)(stage * STAGE_B);
    #pragma unroll
    for (int p = 0; p < 2; p++) {
        int f = tid + p * 256;
        int row = f >> 2, c16 = f & 3;
        uint32_t so = (uint32_t)(row * PCH + c16 * 16);
        size_t go = (size_t)row * Dd + c * 32 + c16 * 8;
        cp_async16(sb + so,             A0g + go);
        cp_async16(sb + ARR_B + so,     A1g + go);
        cp_async16(sb + 2 * ARR_B + so, B0g + go);
        cp_async16(sb + 3 * ARR_B + so, B1g + go);
    }
}

__device__ __forceinline__ void gemm_mainloop(
    const u16* __restrict__ A0g, const u16* __restrict__ A1g,
    const u16* __restrict__ B0g, const u16* __restrict__ B1g,
    float acc[2][8][4], char* sm, int tid)
{
    uint32_t sbase = smem_to_u32(sm);
    int wid = tid >> 5, lane = tid & 31;
    int wm = (wid & 3) * 32, wn = (wid >> 2) * 64;
    int la15 = lane & 15, lh = lane >> 4;
    int lb = (lane & 7) + ((lane >> 4) << 3), lk = (lane >> 3) & 1;
    uint32_t aoff = (uint32_t)((wm + la15) * PCH + lh * 16);
    uint32_t boff = (uint32_t)(2 * ARR_B + (wn + lb) * PCH + lk * 16);

    gemm_issue(sbase, 0, 0, A0g, A1g, B0g, B1g, tid);
    cp_commit();

    for (int c = 0; c < NCHUNK; c++) {
        if (c + 1 < NCHUNK) {
            gemm_issue(sbase, (c + 1) & 1, c + 1, A0g, A1g, B0g, B1g, tid);
            cp_commit();
            cp_wait<1>();
        } else {
            cp_wait<0>();
        }
        __syncthreads();

        uint32_t stg = sbase + (uint32_t)((c & 1) * STAGE_B);
        #pragma unroll
        for (int k16 = 0; k16 < 2; k16++) {
            uint32_t ko = (uint32_t)(k16 * 32);
            uint32_t a0f[2][4], a1f[2][4];
            #pragma unroll
            for (int mt = 0; mt < 2; mt++) {
                ldsm4(a0f[mt], stg + aoff + mt * (16 * PCH) + ko);
                ldsm4(a1f[mt], stg + ARR_B + aoff + mt * (16 * PCH) + ko);
            }
            #pragma unroll
            for (int g = 0; g < 4; g++) {
                uint32_t b0f[4], b1f[4];
                ldsm4(b0f, stg + boff + g * (16 * PCH) + ko);
                ldsm4(b1f, stg + ARR_B + boff + g * (16 * PCH) + ko);
                #pragma unroll
                for (int h2 = 0; h2 < 2; h2++) {
                    int nt = 2 * g + h2;
                    uint32_t bh[2] = {b0f[2 * h2], b0f[2 * h2 + 1]};
                    uint32_t bl[2] = {b1f[2 * h2], b1f[2 * h2 + 1]};
                    #pragma unroll
                    for (int mt = 0; mt < 2; mt++) {
                        mma_f16(acc[mt][nt], a0f[mt], bh);
                        mma_f16(acc[mt][nt], a0f[mt], bl);
                        mma_f16(acc[mt][nt], a1f[mt], bh);
                    }
                }
            }
        }
        __syncthreads();
    }
}

// ---------------- kernel 2: QKV (grid 64 x 24, 256 thr) ----------------------
// Epilogue writes Q (scaled, split), K (split), V (split + transposed).
__global__ __launch_bounds__(256, 2) void qkv_mma_kernel()
{
    extern __shared__ char sm[];
    int tid = threadIdx.x, wid = tid >> 5, lane = tid & 31;
    int m0 = blockIdx.x * 128;
    int z  = blockIdx.y;
    const u16* A0 = g_xn0 + (size_t)m0 * Dd;
    const u16* A1 = g_xn1 + (size_t)m0 * Dd;
    const u16* B0 = g_wt0 + (size_t)z * HD * Dd;
    const u16* B1 = g_wt1 + (size_t)z * HD * Dd;

    float acc[2][8][4];
    #pragma unroll
    for (int mt = 0; mt < 2; mt++)
        #pragma unroll
        for (int nt = 0; nt < 8; nt++)
            #pragma unroll
            for (int r = 0; r < 4; r++) acc[mt][nt][r] = 0.f;

    gemm_mainloop(A0, A1, B0, B1, acc, sm, tid);

    int wm = (wid & 3) * 32, wn = (wid >> 2) * 64;
    int lr = lane >> 2, lc = lane & 3;
    int which = z >> 3, h = z & 7;
    const float scale = (which == 0) ? 0.03125f : 1.0f;
    #pragma unroll
    for (int mt = 0; mt < 2; mt++) {
        int m = m0 + wm + mt * 16 + lr;
        int bb = m >> 11, tt = m & (Tt - 1);
        int bh_ = bb * Hh + h;
        size_t b0 = (size_t)bh_ * TH + (size_t)tt * HD;
        size_t b1 = b0 + 8 * HD;
        #pragma unroll
        for (int nt = 0; nt < 8; nt++) {
            int col = wn + nt * 8 + 2 * lc;
            u16 h0,l0,h1,l1,h2,l2,h3,l3;
            splith(acc[mt][nt][0] * scale, h0, l0);
            splith(acc[mt][nt][1] * scale, h1, l1);
            splith(acc[mt][nt][2] * scale, h2, l2);
            splith(acc[mt][nt][3] * scale, h3, l3);
            if (which == 0) {
                *(uint32_t*)&g_q0[b0 + col] = pack2(h0, h1);
                *(uint32_t*)&g_q1[b0 + col] = pack2(l0, l1);
                *(uint32_t*)&g_q0[b1 + col] = pack2(h2, h3);
                *(uint32_t*)&g_q1[b1 + col] = pack2(l2, l3);
            } else if (which == 1) {
                *(uint32_t*)&g_k0[b0 + col] = pack2(h0, h1);
                *(uint32_t*)&g_k1[b0 + col] = pack2(l0, l1);
                *(uint32_t*)&g_k0[b1 + col] = pack2(h2, h3);
                *(uint32_t*)&g_k1[b1 + col] = pack2(l2, l3);
            } else {
                size_t vb = (size_t)bh_ * TH;
                g_v0t[vb + (size_t)(col    ) * Tt + tt] = h0;
                g_v0t[vb + (size_t)(col + 1) * Tt + tt] = h1;
                g_v1t[vb + (size_t)(col    ) * Tt + tt] = l0;
                g_v1t[vb + (size_t)(col + 1) * Tt + tt] = l1;
                g_v0t[vb + (size_t)(col    ) * Tt + tt + 8] = h2;
                g_v0t[vb + (size_t)(col + 1) * Tt + tt + 8] = h3;
                g_v1t[vb + (size_t)(col    ) * Tt + tt + 8] = l2;
                g_v1t[vb + (size_t)(col + 1) * Tt + tt + 8] = l3;
            }
        }
    }
}

// ---------------- kernel 4: proj + residual (grid 64 x 8, 256 thr) -----------
__global__ __launch_bounds__(256, 2) void proj_mma_kernel(const float* __restrict__ bo)
{
    extern __shared__ char sm[];
    int tid = threadIdx.x, wid = tid >> 5, lane = tid & 31;
    int m0 = blockIdx.x * 128;
    int n0 = blockIdx.y * 128;
    const u16* A0 = g_att0 + (size_t)m0 * Dd;
    const u16* A1 = g_att1 + (size_t)m0 * Dd;
    const u16* B0 = g_wot0 + (size_t)n0 * Dd;
    const u16* B1 = g_wot1 + (size_t)n0 * Dd;

    float acc[2][8][4];
    #pragma unroll
    for (int mt = 0; mt < 2; mt++)
        #pragma unroll
        for (int nt = 0; nt < 8; nt++)
            #pragma unroll
            for (int r = 0; r < 4; r++) acc[mt][nt][r] = 0.f;

    gemm_mainloop(A0, A1, B0, B1, acc, sm, tid);

    int wm = (wid & 3) * 32, wn = (wid >> 2) * 64;
    int lr = lane >> 2, lc = lane & 3;
    #pragma unroll
    for (int mt = 0; mt < 2; mt++) {
        int m = m0 + wm + mt * 16 + lr;
        float* xrow = g_x + (size_t)m * Dd + n0 + wn + lc * 2;
        const float* brow = bo + n0 + wn + lc * 2;
        #pragma unroll
        for (int nt = 0; nt < 8; nt++) {
            float* p0 = xrow + nt * 8;
            const float* b0 = brow + nt * 8;
            p0[0]          += acc[mt][nt][0] + b0[0];
            p0[1]          += acc[mt][nt][1] + b0[1];
            p0[8 * Dd]     += acc[mt][nt][2] + b0[0];
            p0[8 * Dd + 1] += acc[mt][nt][3] + b0[1];
        }
    }
}

// ---------------- kernel 3: causal flash attention, fp16x3, cp.async ---------
// Q tile 128 x KV tile 64; 256 thr, 8 warps; warp w owns rows [16w,16w+16).
#define OFF_Q0 0
#define OFF_Q1 34816
#define OFF_K0 69632
#define OFF_K1 87040
#define OFF_V0 104448
#define OFF_V1 122880
#define OFF_P0 141312
#define OFF_P1 159744
#define ATT_SMEM_B 178176
__global__ __launch_bounds__(256) void attn_mma_kernel()
{
    extern __shared__ char smx[];
    int bh = blockIdx.y, qt = blockIdx.x;
    int t0 = qt * 128;
    const u16* gQ0 = g_q0  + (size_t)bh * TH;
    const u16* gQ1 = g_q1  + (size_t)bh * TH;
    const u16* gK0 = g_k0  + (size_t)bh * TH;
    const u16* gK1 = g_k1  + (size_t)bh * TH;
    const u16* gV0 = g_v0t + (size_t)bh * TH;
    const u16* gV1 = g_v1t + (size_t)bh * TH;

    int tid = threadIdx.x, wid = tid >> 5, lane = tid & 31;
    int lr = lane >> 2, lc = lane & 3;

    int la15 = lane & 15, lh = lane >> 4;
    int lb = (lane & 7) + ((lane >> 4) << 3), lk = (lane >> 3) & 1;
    uint32_t sb = smem_to_u32(smx);
    uint32_t q0u = sb + OFF_Q0 + (uint32_t)((16 * wid + la15) * 272 + lh * 16);
    uint32_t q1u = q0u + (OFF_Q1 - OFF_Q0);
    uint32_t k0u = sb + OFF_K0 + (uint32_t)(lb * 272 + lk * 16);
    uint32_t k1u = k0u + (OFF_K1 - OFF_K0);
    uint32_t p0u = sb + OFF_P0 + (uint32_t)((16 * wid + la15) * 144 + lh * 16);
    uint32_t p1u = p0u + (OFF_P1 - OFF_P0);
    uint32_t v0u = sb + OFF_V0 + (uint32_t)(lb * 144 + lk * 16);
    uint32_t v1u = v0u + (OFF_V1 - OFF_V0);

    // Q tile: cp.async (pre-scaled, pre-split in gmem)
    #pragma unroll
    for (int p = 0; p < 8; p++) {
        int f = tid + p * 256;                 // 0..2047
        int r = f >> 4, c16 = f & 15;
        uint32_t so = (uint32_t)(r * 272 + c16 * 16);
        size_t go = (size_t)(t0 + r) * HD + c16 * 8;
        cp_async16(sb + OFF_Q0 + so, gQ0 + go);
        cp_async16(sb + OFF_Q1 + so, gQ1 + go);
    }
    cp_commit();

    float o_acc[16][4];
    #pragma unroll
    for (int nt = 0; nt < 16; nt++)
        #pragma unroll
        for (int r = 0; r < 4; r++) o_acc[nt][r] = 0.f;
    float m_i[2] = {neg_inf(), neg_inf()};
    float l_i[2] = {0.f, 0.f};

    int row_w = t0 + 16 * wid;
    int ntiles = 2 * (qt + 1);
    for (int j = 0; j < ntiles; j++) {
        int s0 = 64 * j;
        __syncthreads();                 // prior tile's readers done
        // K tile [s][d] and V tile [d][s] via cp.async (pre-split in gmem)
        #pragma unroll
        for (int p = 0; p < 4; p++) {
            int f = tid + p * 256;             // 0..1023
            int kr = f >> 4, kc = f & 15;
            uint32_t kso = (uint32_t)(kr * 272 + kc * 16);
            size_t kgo = (size_t)(s0 + kr) * HD + kc * 8;
            cp_async16(sb + OFF_K0 + kso, gK0 + kgo);
            cp_async16(sb + OFF_K1 + kso, gK1 + kgo);
            int vr = f >> 3, vc = f & 7;
            uint32_t vso = (uint32_t)(vr * 144 + vc * 16);
            size_t vgo = (size_t)vr * Tt + s0 + vc * 8;
            cp_async16(sb + OFF_V0 + vso, gV0 + vgo);
            cp_async16(sb + OFF_V1 + vso, gV1 + vgo);
        }
        cp_commit();
        cp_wait<0>();
        __syncthreads();

        bool active = (s0 <= row_w + 15);
        if (active) {
            float sacc[8][4];
            #pragma unroll
            for (int nt = 0; nt < 8; nt++)
                #pragma unroll
                for (int r = 0; r < 4; r++) sacc[nt][r] = 0.f;

            // S = Q K^T (16x64), fp16x3
            #pragma unroll 2
            for (int k16 = 0; k16 < 8; k16++) {
                uint32_t ko = (uint32_t)(k16 * 32);
                uint32_t qa0[4], qa1[4];
                ldsm4(qa0, q0u + ko);
                ldsm4(qa1, q1u + ko);
                #pragma unroll
                for (int g = 0; g < 4; g++) {
                    uint32_t kf0[4], kf1[4];
                    ldsm4(kf0, k0u + g * (16 * 272) + ko);
                    ldsm4(kf1, k1u + g * (16 * 272) + ko);
                    #pragma unroll
                    for (int h2 = 0; h2 < 2; h2++) {
                        int nt = 2 * g + h2;
                        uint32_t bh2[2] = {kf0[2 * h2], kf0[2 * h2 + 1]};
                        uint32_t bl2[2] = {kf1[2 * h2], kf1[2 * h2 + 1]};
                        mma_f16(sacc[nt], qa0, bh2);
                        mma_f16(sacc[nt], qa0, bl2);
                        mma_f16(sacc[nt], qa1, bh2);
                    }
                }
            }
            // causal mask
            if (s0 + 63 > row_w) {
                int r0 = row_w + lr;
                #pragma unroll
                for (int nt = 0; nt < 8; nt++) {
                    int cb = s0 + 8 * nt + 2 * lc;
                    if (cb     > r0)     sacc[nt][0] = neg_inf();
                    if (cb + 1 > r0)     sacc[nt][1] = neg_inf();
                    if (cb     > r0 + 8) sacc[nt][2] = neg_inf();
                    if (cb + 1 > r0 + 8) sacc[nt][3] = neg_inf();
                }
            }
            // online softmax (rows lr, lr+8; quad shuffles)
            float rm0 = neg_inf(), rm1 = neg_inf();
            #pragma unroll
            for (int nt = 0; nt < 8; nt++) {
                rm0 = fmaxf(rm0, fmaxf(sacc[nt][0], sacc[nt][1]));
                rm1 = fmaxf(rm1, fmaxf(sacc[nt][2], sacc[nt][3]));
            }
            rm0 = fmaxf(rm0, __shfl_xor_sync(0xffffffffu, rm0, 1));
            rm0 = fmaxf(rm0, __shfl_xor_sync(0xffffffffu, rm0, 2));
            rm1 = fmaxf(rm1, __shfl_xor_sync(0xffffffffu, rm1, 1));
            rm1 = fmaxf(rm1, __shfl_xor_sync(0xffffffffu, rm1, 2));
            float mn0 = fmaxf(m_i[0], rm0), mn1 = fmaxf(m_i[1], rm1);
            float al0 = expf(m_i[0] - mn0), al1 = expf(m_i[1] - mn1);
            float rs0 = 0.f, rs1 = 0.f;
            #pragma unroll
            for (int nt = 0; nt < 8; nt++) {
                sacc[nt][0] = expf(sacc[nt][0] - mn0);
                sacc[nt][1] = expf(sacc[nt][1] - mn0);
                sacc[nt][2] = expf(sacc[nt][2] - mn1);
                sacc[nt][3] = expf(sacc[nt][3] - mn1);
                rs0 += sacc[nt][0] + sacc[nt][1];
                rs1 += sacc[nt][2] + sacc[nt][3];
            }
            rs0 += __shfl_xor_sync(0xffffffffu, rs0, 1);
            rs0 += __shfl_xor_sync(0xffffffffu, rs0, 2);
            rs1 += __shfl_xor_sync(0xffffffffu, rs1, 1);
            rs1 += __shfl_xor_sync(0xffffffffu, rs1, 2);
            l_i[0] = l_i[0] * al0 + rs0;  m_i[0] = mn0;
            l_i[1] = l_i[1] * al1 + rs1;  m_i[1] = mn1;
            #pragma unroll
            for (int nt = 0; nt < 16; nt++) {
                o_acc[nt][0] *= al0; o_acc[nt][1] *= al0;
                o_acc[nt][2] *= al1; o_acc[nt][3] *= al1;
            }
            // store P split to smem (warp-private rows)
            #pragma unroll
            for (int nt = 0; nt < 8; nt++) {
                u16 h0,l0,h1,l1,h2,l2,h3,l3;
                splith(sacc[nt][0], h0, l0); splith(sacc[nt][1], h1, l1);
                splith(sacc[nt][2], h2, l2); splith(sacc[nt][3], h3, l3);
                int co = (8 * nt + 2 * lc) * 2;
                *(uint32_t*)(smx + OFF_P0 + (16 * wid + lr) * 144 + co)       = pack2(h0, h1);
                *(uint32_t*)(smx + OFF_P1 + (16 * wid + lr) * 144 + co)       = pack2(l0, l1);
                *(uint32_t*)(smx + OFF_P0 + (16 * wid + lr + 8) * 144 + co)   = pack2(h2, h3);
                *(uint32_t*)(smx + OFF_P1 + (16 * wid + lr + 8) * 144 + co)   = pack2(l2, l3);
            }
            __syncwarp();
            // O += P V (16x128), fp16x3
            #pragma unroll 2
            for (int k16 = 0; k16 < 4; k16++) {
                uint32_t ko = (uint32_t)(k16 * 32);
                uint32_t pa0[4], pa1[4];
                ldsm4(pa0, p0u + ko);
                ldsm4(pa1, p1u + ko);
                #pragma unroll
                for (int g = 0; g < 8; g++) {
                    uint32_t vf0[4], vf1[4];
                    ldsm4(vf0, v0u + g * (16 * 144) + ko);
                    ldsm4(vf1, v1u + g * (16 * 144) + ko);
                    #pragma unroll
                    for (int h2 = 0; h2 < 2; h2++) {
                        int nt = 2 * g + h2;
                        uint32_t bh2[2] = {vf0[2 * h2], vf0[2 * h2 + 1]};
                        uint32_t bl2[2] = {vf1[2 * h2], vf1[2 * h2 + 1]};
                        mma_f16(o_acc[nt], pa0, bh2);
                        mma_f16(o_acc[nt], pa0, bl2);
                        mma_f16(o_acc[nt], pa1, bh2);
                    }
                }
            }
        }
    }

    // epilogue: write split attention output [B, T, H*HD] (fp16 hi/lo)
    float inv0 = 1.0f / l_i[0], inv1 = 1.0f / l_i[1];
    int bb = bh >> 3, h = bh & 7;
    int r0 = row_w + lr;
    size_t base0 = ((size_t)(bb * Tt + r0)) * Dd + h * HD;
    size_t base1 = ((size_t)(bb * Tt + r0 + 8)) * Dd + h * HD;
    #pragma unroll
    for (int nt = 0; nt < 16; nt++) {
        int col = 8 * nt + 2 * lc;
        u16 h0,l0,h1,l1,h2,l2,h3,l3;
        splith(o_acc[nt][0] * inv0, h0, l0); splith(o_acc[nt][1] * inv0, h1, l1);
        splith(o_acc[nt][2] * inv1, h2, l2); splith(o_acc[nt][3] * inv1, h3, l3);
        *(uint32_t*)&g_att0[base0 + col] = pack2(h0, h1);
        *(uint32_t*)&g_att1[base0 + col] = pack2(l0, l1);
        *(uint32_t*)&g_att0[base1 + col] = pack2(h2, h3);
        *(uint32_t*)&g_att1[base1 + col] = pack2(l2, l3);
    }
}

// ---------------- kernel 5: LayerNorm2 + noisy top-2 router + outputs --------
#define OUT_OFF_PROBS (BT * Dd)
#define OUT_OFF_IDX   (OUT_OFF_PROBS + BT * Ee)
#define OUT_OFF_X     (OUT_OFF_IDX + BT * 2)
__global__ __launch_bounds__(256) void ln2_router_kernel(
    const float* __restrict__ g2, const float* __restrict__ b2,
    const float* __restrict__ Wr, const float* __restrict__ br,
    const float* __restrict__ Wn, const float* __restrict__ bn,
    float* __restrict__ out)
{
    int token = blockIdx.x;
    int tid = threadIdx.x;
    __shared__ float sxn[Dd];
    __shared__ float rs_[8], rq_[8];
    __shared__ float red[8][16];

    const float* xr = g_x + (size_t)token * Dd;
    float lsum = 0.f, lsq = 0.f;
    for (int c = tid; c < Dd; c += 256) {
        float v = xr[c];
        sxn[c] = v;
        out[OUT_OFF_X + (size_t)token * Dd + c] = v;
        lsum += v; lsq += v * v;
    }
    #pragma unroll
    for (int o = 16; o; o >>= 1) {
        lsum += __shfl_xor_sync(0xffffffffu, lsum, o);
        lsq  += __shfl_xor_sync(0xffffffffu, lsq,  o);
    }
    if ((tid & 31) == 0) { rs_[tid >> 5] = lsum; rq_[tid >> 5] = lsq; }
    __syncthreads();
    float s = 0.f, q = 0.f;
    #pragma unroll
    for (int w = 0; w < 8; w++) { s += rs_[w]; q += rq_[w]; }
    float mu   = s * (1.0f / Dd);
    float var  = q * (1.0f / Dd) - mu * mu;
    float rstd = rsqrtf(var + 1e-5f);

    for (int c = tid; c < Dd; c += 256) {
        float v  = sxn[c];
        float xn = (v - mu) * rstd * g2[c] + b2[c];
        sxn[c] = xn;
        out[(size_t)token * Dd + c] = xn;
    }
    __syncthreads();

    float ar[8] = {}, an_[8] = {};
    for (int c = tid; c < Dd; c += 256) {
        float v = sxn[c];
        float4 w0 = *(const float4*)&Wr[(size_t)c * Ee];
        float4 w1 = *(const float4*)&Wr[(size_t)c * Ee + 4];
        ar[0] += v * w0.x; ar[1] += v * w0.y; ar[2] += v * w0.z; ar[3] += v * w0.w;
        ar[4] += v * w1.x; ar[5] += v * w1.y; ar[6] += v * w1.z; ar[7] += v * w1.w;
        float4 n0 = *(const float4*)&Wn[(size_t)c * Ee];
        float4 n1 = *(const float4*)&Wn[(size_t)c * Ee + 4];
        an_[0] += v * n0.x; an_[1] += v * n0.y; an_[2] += v * n0.z; an_[3] += v * n0.w;
        an_[4] += v * n1.x; an_[5] += v * n1.y; an_[6] += v * n1.z; an_[7] += v * n1.w;
    }
    #pragma unroll
    for (int o = 16; o; o >>= 1) {
        #pragma unroll
        for (int e = 0; e < 8; e++) {
            ar[e]  += __shfl_xor_sync(0xffffffffu, ar[e],  o);
            an_[e] += __shfl_xor_sync(0xffffffffu, an_[e], o);
        }
    }
    int w = tid >> 5;
    if ((tid & 31) == 0) {
        #pragma unroll
        for (int e = 0; e < 8; e++) { red[w][e] = ar[e]; red[w][8 + e] = an_[e]; }
    }
    __syncthreads();

    if (tid == 0) {
        float lg[8], nl[8];
        #pragma unroll
        for (int e = 0; e < 8; e++) { lg[e] = br[e]; nl[e] = bn[e]; }
        for (int ww = 0; ww < 8; ww++)
            #pragma unroll
            for (int e = 0; e < 8; e++) { lg[e] += red[ww][e]; nl[e] += red[ww][8 + e]; }

        float noisy[8];
        #pragma unroll
        for (int e = 0; e < 8; e++) {
            float nz = jax_noise((uint32_t)(token * Ee + e));
            noisy[e] = lg[e] + nz * softplus_f(nl[e]);
        }
        int i0 = 0; float v0 = noisy[0];
        #pragma unroll
        for (int e = 1; e < 8; e++) if (noisy[e] > v0) { v0 = noisy[e]; i0 = e; }
        int i1 = -1; float v1 = neg_inf();
        #pragma unroll
        for (int e = 0; e < 8; e++)
            if (e != i0 && noisy[e] > v1) { v1 = noisy[e]; i1 = e; }

        float e1 = expf(v1 - v0);
        float inv = 1.0f / (1.0f + e1);
        float p0 = inv, p1 = e1 * inv;

        float probs[8] = {};
        probs[i0] = p0; probs[i1] = p1;
        float* pout = out + OUT_OFF_PROBS + (size_t)token * Ee;
        #pragma unroll
        for (int e = 0; e < 8; e++) pout[e] = probs[e];
        out[OUT_OFF_IDX + (size_t)token * 2 + 0] = (float)i0;
        out[OUT_OFF_IDX + (size_t)token * 2 + 1] = (float)i1;
    }
}

// ---------------- launcher ---------------------------------------------------
extern "C" void kernel_launch(void* const* d_in, const int* in_sizes, int n_in,
                              void* d_out, int out_size)
{
    const int*   idx = (const int*)  d_in[0];
    const float* tok = (const float*)d_in[1];
    const float* pos = (const float*)d_in[2];
    const float* Wq  = (const float*)d_in[3];
    const float* Wk  = (const float*)d_in[4];
    const float* Wv  = (const float*)d_in[5];
    const float* Wo  = (const float*)d_in[6];
    const float* bo  = (const float*)d_in[7];
    const float* g1  = (const float*)d_in[8];
    const float* b1  = (const float*)d_in[9];
    const float* g2  = (const float*)d_in[10];
    const float* b2  = (const float*)d_in[11];
    const float* Wr  = (const float*)d_in[12];
    const float* br  = (const float*)d_in[13];
    const float* Wn  = (const float*)d_in[14];
    const float* bn  = (const float*)d_in[15];
    float* out = (float*)d_out;

    cudaFuncSetAttribute(attn_mma_kernel, cudaFuncAttributeMaxDynamicSharedMemorySize,
                         ATT_SMEM_B);
    cudaFuncSetAttribute(qkv_mma_kernel, cudaFuncAttributeMaxDynamicSharedMemorySize,
                         GEMM_SMEM);
    cudaFuncSetAttribute(proj_mma_kernel, cudaFuncAttributeMaxDynamicSharedMemorySize,
                         GEMM_SMEM);

    embed_ln_kernel<<<BT, 256>>>(idx, tok, pos, g1, b1);
    transpose_qkv_kernel<<<dim3(32, 4, 24), dim3(32, 8)>>>(Wq, Wk, Wv);
    transpose_wo_kernel<<<dim3(32, 32), dim3(32, 8)>>>(Wo);
    qkv_mma_kernel<<<dim3(BT / 128, 24), 256, GEMM_SMEM>>>();
    attn_mma_kernel<<<dim3(Tt / 128, Bb * Hh), 256, ATT_SMEM_B>>>();
    proj_mma_kernel<<<dim3(BT / 128, Dd / 128), 256, GEMM_SMEM>>>(bo);
    ln2_router_kernel<<<BT, 256>>>(g2, b2, Wr, br, Wn, bn, out);
}

// round 12
// speedup vs baseline: 3.2269x; 1.0367x over previous
#include <cuda_runtime.h>
#include <cstdint>

typedef unsigned short u16;

// Problem dims
#define Bb 4
#define Tt 2048
#define Dd 1024
#define Hh 8
#define HD 128
#define Ee 8
#define BT 8192            // Bb*Tt
#define TH (Tt*HD)         // 262144

// ---------------- scratch (device globals; no allocations allowed) ----------
__device__ float g_x   [BT*Dd];   // running residual x
__device__ u16   g_xn0 [BT*Dd];   // LN1(x) fp16 hi
__device__ u16   g_xn1 [BT*Dd];   // LN1(x) fp16 lo
__device__ u16   g_q0  [BT*Dd];   // scaled Q fp16 hi  [bh][t][d]
__device__ u16   g_q1  [BT*Dd];
__device__ u16   g_k0  [BT*Dd];   // K fp16 hi  [bh][t][d]
__device__ u16   g_k1  [BT*Dd];
__device__ u16   g_v0t [BT*Dd];   // V fp16 hi, transposed [bh][d][t]
__device__ u16   g_v1t [BT*Dd];
__device__ u16   g_att0[BT*Dd];   // attention out fp16 hi  [B,T,H*HD]
__device__ u16   g_att1[BT*Dd];
__device__ u16   g_wt0 [3*Hh*HD*Dd];  // transposed QKV weights hi [z][d][c]
__device__ u16   g_wt1 [3*Hh*HD*Dd];
__device__ u16   g_wot0[Dd*Dd];       // Wo^T hi [n][k]
__device__ u16   g_wot1[Dd*Dd];

__device__ __forceinline__ float neg_inf() { return __int_as_float(0xff800000); }

// fp32 -> (fp16 hi, fp16 lo) split (base PTX)
__device__ __forceinline__ void splith(float v, u16& h, u16& l) {
    u16 hu; asm("cvt.rn.f16.f32 %0, %1;" : "=h"(hu) : "f"(v));
    float hf; asm("cvt.f32.f16 %0, %1;" : "=f"(hf) : "h"(hu));
    u16 lu; asm("cvt.rn.f16.f32 %0, %1;" : "=h"(lu) : "f"(v - hf));
    h = hu; l = lu;
}
__device__ __forceinline__ uint32_t pack2(u16 a, u16 b) {
    return (uint32_t)a | ((uint32_t)b << 16);
}

// m16n8k16 fp16 MMA, fp32 accum (base PTX, sm_80+)
__device__ __forceinline__ void mma_f16(float* d, const uint32_t* a, const uint32_t* b) {
    asm volatile("mma.sync.aligned.m16n8k16.row.col.f32.f16.f16.f32 "
        "{%0,%1,%2,%3}, {%4,%5,%6,%7}, {%8,%9}, {%0,%1,%2,%3};"
        : "+f"(d[0]), "+f"(d[1]), "+f"(d[2]), "+f"(d[3])
        : "r"(a[0]), "r"(a[1]), "r"(a[2]), "r"(a[3]), "r"(b[0]), "r"(b[1]));
}

// ldmatrix x4 b16 (base PTX, sm_75+)
__device__ __forceinline__ void ldsm4(uint32_t* r, uint32_t saddr) {
    asm volatile("ldmatrix.sync.aligned.m8n8.x4.shared.b16 {%0,%1,%2,%3}, [%4];"
        : "=r"(r[0]), "=r"(r[1]), "=r"(r[2]), "=r"(r[3]) : "r"(saddr));
}

// cp.async (base PTX, sm_80+)
__device__ __forceinline__ uint32_t smem_to_u32(const void* p) {
    uint32_t a;
    asm("{ .reg .u64 t; cvta.to.shared.u64 t, %1; cvt.u32.u64 %0, t; }" : "=r"(a) : "l"(p));
    return a;
}
__device__ __forceinline__ void cp_async16(uint32_t saddr, const void* gaddr) {
    asm volatile("cp.async.cg.shared.global [%0], [%1], 16;" :: "r"(saddr), "l"(gaddr));
}
__device__ __forceinline__ void cp_commit() { asm volatile("cp.async.commit_group;" ::: "memory"); }
template<int N> __device__ __forceinline__ void cp_wait() {
    asm volatile("cp.async.wait_group %0;" :: "n"(N) : "memory");
}

// ---------------- JAX threefry2x32 noise (partitionable scheme) --------------
__device__ __forceinline__ uint32_t rotl32(uint32_t v, int r) {
    return (v << r) | (v >> (32 - r));
}
__device__ float jax_noise(uint32_t i) {
    uint32_t x0 = 0u, x1 = i;
    const uint32_t k0 = 0u, k1 = 42u, k2 = 0u ^ 42u ^ 0x1BD11BDAu;
    x0 += k0; x1 += k1;
#define TF_ROUND(r) { x0 += x1; x1 = rotl32(x1, r); x1 ^= x0; }
#define TF_G0 TF_ROUND(13) TF_ROUND(15) TF_ROUND(26) TF_ROUND(6)
#define TF_G1 TF_ROUND(17) TF_ROUND(29) TF_ROUND(16) TF_ROUND(24)
    TF_G0; x0 += k1; x1 += k2 + 1u;
    TF_G1; x0 += k2; x1 += k0 + 2u;
    TF_G0; x0 += k0; x1 += k1 + 3u;
    TF_G1; x0 += k1; x1 += k2 + 4u;
    TF_G0; x0 += k2; x1 += k0 + 5u;
#undef TF_G1
#undef TF_G0
#undef TF_ROUND
    uint32_t bits = x0 ^ x1;
    float f = __uint_as_float((bits >> 9) | 0x3f800000u) - 1.0f;
    const float lo = -0.99999994f;
    float u = f * (1.0f - lo) + lo;
    u = fmaxf(u, lo);
    return 1.41421354f * erfinvf(u);
}
__device__ __forceinline__ float softplus_f(float x) {
    return fmaxf(x, 0.0f) + log1pf(expf(-fabsf(x)));
}

// ---------------- kernel 1: embedding + LayerNorm1 (writes split xn) ---------
__global__ __launch_bounds__(256) void embed_ln_kernel(
    const int* __restrict__ idx, const float* __restrict__ tok,
    const float* __restrict__ pos, const float* __restrict__ g1,
    const float* __restrict__ b1)
{
    int token = blockIdx.x;
    int t     = token & (Tt - 1);
    int tid   = threadIdx.x;
    __shared__ float sx[Dd];
    __shared__ float rs_[8], rq_[8];

    const float* trow = tok + (size_t)idx[token] * Dd;
    const float* prow = pos + (size_t)t * Dd;

    float lsum = 0.f, lsq = 0.f;
    for (int c = tid; c < Dd; c += 256) {
        float v = trow[c] + prow[c];
        sx[c] = v; lsum += v; lsq += v * v;
    }
    #pragma unroll
    for (int o = 16; o; o >>= 1) {
        lsum += __shfl_xor_sync(0xffffffffu, lsum, o);
        lsq  += __shfl_xor_sync(0xffffffffu, lsq,  o);
    }
    if ((tid & 31) == 0) { rs_[tid >> 5] = lsum; rq_[tid >> 5] = lsq; }
    __syncthreads();
    float s = 0.f, q = 0.f;
    #pragma unroll
    for (int w = 0; w < 8; w++) { s += rs_[w]; q += rq_[w]; }
    float mu   = s * (1.0f / Dd);
    float var  = q * (1.0f / Dd) - mu * mu;
    float rstd = rsqrtf(var + 1e-5f);

    float* xr = g_x + (size_t)token * Dd;
    for (int c = tid; c < Dd; c += 256) {
        float v = sx[c];
        xr[c] = v;
        float xn = (v - mu) * rstd * g1[c] + b1[c];
        u16 h, l; splith(xn, h, l);
        g_xn0[(size_t)token * Dd + c] = h;
        g_xn1[(size_t)token * Dd + c] = l;
    }
}

// ---------------- weight transposes (split to fp16 hi/lo) --------------------
__global__ __launch_bounds__(256) void transpose_qkv_kernel(
    const float* __restrict__ Wq, const float* __restrict__ Wk,
    const float* __restrict__ Wv)
{
    __shared__ float tile[32][33];
    int z = blockIdx.z; int which = z >> 3, h = z & 7;
    const float* src = (which == 0 ? Wq : which == 1 ? Wk : Wv) + (size_t)h * Dd * HD;
    size_t dbase = (size_t)z * HD * Dd;
    int c0 = blockIdx.x * 32, d0 = blockIdx.y * 32;
    int tx = threadIdx.x, ty = threadIdx.y;
    #pragma unroll
    for (int j = 0; j < 32; j += 8)
        tile[ty + j][tx] = src[(size_t)(c0 + ty + j) * HD + d0 + tx];
    __syncthreads();
    #pragma unroll
    for (int j = 0; j < 32; j += 8) {
        float v = tile[tx][ty + j];
        u16 hh, ll; splith(v, hh, ll);
        size_t o = dbase + (size_t)(d0 + ty + j) * Dd + c0 + tx;
        g_wt0[o] = hh;
        g_wt1[o] = ll;
    }
}

__global__ __launch_bounds__(256) void transpose_wo_kernel(const float* __restrict__ Wo)
{
    __shared__ float tile[32][33];
    int k0 = blockIdx.x * 32, n0 = blockIdx.y * 32;
    int tx = threadIdx.x, ty = threadIdx.y;
    #pragma unroll
    for (int j = 0; j < 32; j += 8)
        tile[ty + j][tx] = Wo[(size_t)(k0 + ty + j) * Dd + n0 + tx];
    __syncthreads();
    #pragma unroll
    for (int j = 0; j < 32; j += 8) {
        float v = tile[tx][ty + j];
        u16 hh, ll; splith(v, hh, ll);
        size_t o = (size_t)(n0 + ty + j) * Dd + k0 + tx;
        g_wot0[o] = hh;
        g_wot1[o] = ll;
    }
}

// ---------------- fp16x3 3-stage cp.async GEMM core --------------------------
// C[128x128] = A[128x1024] * B[128x1024]^T; fp16 hi/lo pre-split.
// 64B rows with XOR chunk swizzle: phys16Bchunk = (c + (row>>1)) & 3.
#define NCHUNK 32
#define ARR_B (128 * 64)               // 8192 B per array
#define STAGE_B (4 * ARR_B)            // 32768 (A0,A1,B0,B1)
#define GEMM_SMEM (3 * STAGE_B)        // 98304

__device__ __forceinline__ void gemm_issue(
    uint32_t sbase, int stage, int c,
    const u16* __restrict__ A0g, const u16* __restrict__ A1g,
    const u16* __restrict__ B0g, const u16* __restrict__ B1g, int tid)
{
    uint32_t sb = sbase + (uint32_t)(stage * STAGE_B);
    #pragma unroll
    for (int p = 0; p < 2; p++) {
        int f = tid + p * 256;              // 512 16B slots per array
        int row = f >> 2, cc = f & 3;
        int pc = (cc + ((row >> 1) & 3)) & 3;
        uint32_t so = (uint32_t)(row * 64 + pc * 16);
        size_t go = (size_t)row * Dd + c * 32 + cc * 8;
        cp_async16(sb + so,             A0g + go);
        cp_async16(sb + ARR_B + so,     A1g + go);
        cp_async16(sb + 2 * ARR_B + so, B0g + go);
        cp_async16(sb + 3 * ARR_B + so, B1g + go);
    }
}

__device__ __forceinline__ void gemm_mainloop(
    const u16* __restrict__ A0g, const u16* __restrict__ A1g,
    const u16* __restrict__ B0g, const u16* __restrict__ B1g,
    float acc[2][8][4], char* sm, int tid)
{
    uint32_t sbase = smem_to_u32(sm);
    int wid = tid >> 5, lane = tid & 31;
    int wm = (wid & 3) * 32, wn = (wid >> 2) * 64;
    int m_row = ((lane >> 3) & 1) * 8 + (lane & 7);
    int lh = lane >> 4;
    int n_row = (lane & 7) + ((lane >> 4) << 3);
    int lk = (lane >> 3) & 1;

    uint32_t arow[2]; int arot[2];
    #pragma unroll
    for (int mt = 0; mt < 2; mt++) {
        int R = wm + mt * 16 + m_row;
        arow[mt] = (uint32_t)(R * 64);
        arot[mt] = (R >> 1) & 3;
    }
    uint32_t brow[4]; int brot[4];
    #pragma unroll
    for (int g = 0; g < 4; g++) {
        int R = wn + g * 16 + n_row;
        brow[g] = (uint32_t)(R * 64);
        brot[g] = (R >> 1) & 3;
    }

    gemm_issue(sbase, 0, 0, A0g, A1g, B0g, B1g, tid);
    cp_commit();
    gemm_issue(sbase, 1, 1, A0g, A1g, B0g, B1g, tid);
    cp_commit();

    for (int c = 0; c < NCHUNK; c++) {
        if (c == NCHUNK - 1) cp_wait<0>(); else cp_wait<1>();
        __syncthreads();
        if (c + 2 < NCHUNK) {
            gemm_issue(sbase, (c + 2) % 3, c + 2, A0g, A1g, B0g, B1g, tid);
            cp_commit();
        }
        uint32_t stg = sbase + (uint32_t)((c % 3) * STAGE_B);
        #pragma unroll
        for (int k16 = 0; k16 < 2; k16++) {
            uint32_t a0f[2][4], a1f[2][4];
            #pragma unroll
            for (int mt = 0; mt < 2; mt++) {
                uint32_t pcA = (uint32_t)(((lh + 2 * k16 + arot[mt]) & 3) << 4);
                ldsm4(a0f[mt], stg + arow[mt] + pcA);
                ldsm4(a1f[mt], stg + ARR_B + arow[mt] + pcA);
            }
            #pragma unroll
            for (int g = 0; g < 4; g++) {
                uint32_t pcB = (uint32_t)(((lk + 2 * k16 + brot[g]) & 3) << 4);
                uint32_t b0f[4], b1f[4];
                ldsm4(b0f, stg + 2 * ARR_B + brow[g] + pcB);
                ldsm4(b1f, stg + 3 * ARR_B + brow[g] + pcB);
                #pragma unroll
                for (int h2 = 0; h2 < 2; h2++) {
                    int nt = 2 * g + h2;
                    uint32_t bh[2] = {b0f[2 * h2], b0f[2 * h2 + 1]};
                    uint32_t bl[2] = {b1f[2 * h2], b1f[2 * h2 + 1]};
                    #pragma unroll
                    for (int mt = 0; mt < 2; mt++) {
                        mma_f16(acc[mt][nt], a0f[mt], bh);
                        mma_f16(acc[mt][nt], a0f[mt], bl);
                        mma_f16(acc[mt][nt], a1f[mt], bh);
                    }
                }
            }
        }
    }
}

// ---------------- kernel 2: QKV (grid 64 x 24, 256 thr) ----------------------
__global__ __launch_bounds__(256, 2) void qkv_mma_kernel()
{
    extern __shared__ char sm[];
    int tid = threadIdx.x, wid = tid >> 5, lane = tid & 31;
    int m0 = blockIdx.x * 128;
    int z  = blockIdx.y;
    const u16* A0 = g_xn0 + (size_t)m0 * Dd;
    const u16* A1 = g_xn1 + (size_t)m0 * Dd;
    const u16* B0 = g_wt0 + (size_t)z * HD * Dd;
    const u16* B1 = g_wt1 + (size_t)z * HD * Dd;

    float acc[2][8][4];
    #pragma unroll
    for (int mt = 0; mt < 2; mt++)
        #pragma unroll
        for (int nt = 0; nt < 8; nt++)
            #pragma unroll
            for (int r = 0; r < 4; r++) acc[mt][nt][r] = 0.f;

    gemm_mainloop(A0, A1, B0, B1, acc, sm, tid);

    int wm = (wid & 3) * 32, wn = (wid >> 2) * 64;
    int lr = lane >> 2, lc = lane & 3;
    int which = z >> 3, h = z & 7;
    const float scale = (which == 0) ? 0.03125f : 1.0f;
    #pragma unroll
    for (int mt = 0; mt < 2; mt++) {
        int m = m0 + wm + mt * 16 + lr;
        int bb = m >> 11, tt = m & (Tt - 1);
        int bh_ = bb * Hh + h;
        size_t b0 = (size_t)bh_ * TH + (size_t)tt * HD;
        size_t b1 = b0 + 8 * HD;
        #pragma unroll
        for (int nt = 0; nt < 8; nt++) {
            int col = wn + nt * 8 + 2 * lc;
            u16 h0,l0,h1,l1,h2,l2,h3,l3;
            splith(acc[mt][nt][0] * scale, h0, l0);
            splith(acc[mt][nt][1] * scale, h1, l1);
            splith(acc[mt][nt][2] * scale, h2, l2);
            splith(acc[mt][nt][3] * scale, h3, l3);
            if (which == 0) {
                *(uint32_t*)&g_q0[b0 + col] = pack2(h0, h1);
                *(uint32_t*)&g_q1[b0 + col] = pack2(l0, l1);
                *(uint32_t*)&g_q0[b1 + col] = pack2(h2, h3);
                *(uint32_t*)&g_q1[b1 + col] = pack2(l2, l3);
            } else if (which == 1) {
                *(uint32_t*)&g_k0[b0 + col] = pack2(h0, h1);
                *(uint32_t*)&g_k1[b0 + col] = pack2(l0, l1);
                *(uint32_t*)&g_k0[b1 + col] = pack2(h2, h3);
                *(uint32_t*)&g_k1[b1 + col] = pack2(l2, l3);
            } else {
                size_t vb = (size_t)bh_ * TH;
                g_v0t[vb + (size_t)(col    ) * Tt + tt] = h0;
                g_v0t[vb + (size_t)(col + 1) * Tt + tt] = h1;
                g_v1t[vb + (size_t)(col    ) * Tt + tt] = l0;
                g_v1t[vb + (size_t)(col + 1) * Tt + tt] = l1;
                g_v0t[vb + (size_t)(col    ) * Tt + tt + 8] = h2;
                g_v0t[vb + (size_t)(col + 1) * Tt + tt + 8] = h3;
                g_v1t[vb + (size_t)(col    ) * Tt + tt + 8] = l2;
                g_v1t[vb + (size_t)(col + 1) * Tt + tt + 8] = l3;
            }
        }
    }
}

// ---------------- kernel 4: proj + residual (grid 64 x 8, 256 thr) -----------
__global__ __launch_bounds__(256, 2) void proj_mma_kernel(const float* __restrict__ bo)
{
    extern __shared__ char sm[];
    int tid = threadIdx.x, wid = tid >> 5, lane = tid & 31;
    int m0 = blockIdx.x * 128;
    int n0 = blockIdx.y * 128;
    const u16* A0 = g_att0 + (size_t)m0 * Dd;
    const u16* A1 = g_att1 + (size_t)m0 * Dd;
    const u16* B0 = g_wot0 + (size_t)n0 * Dd;
    const u16* B1 = g_wot1 + (size_t)n0 * Dd;

    float acc[2][8][4];
    #pragma unroll
    for (int mt = 0; mt < 2; mt++)
        #pragma unroll
        for (int nt = 0; nt < 8; nt++)
            #pragma unroll
            for (int r = 0; r < 4; r++) acc[mt][nt][r] = 0.f;

    gemm_mainloop(A0, A1, B0, B1, acc, sm, tid);

    int wm = (wid & 3) * 32, wn = (wid >> 2) * 64;
    int lr = lane >> 2, lc = lane & 3;
    #pragma unroll
    for (int mt = 0; mt < 2; mt++) {
        int m = m0 + wm + mt * 16 + lr;
        float* xrow = g_x + (size_t)m * Dd + n0 + wn + lc * 2;
        const float* brow = bo + n0 + wn + lc * 2;
        #pragma unroll
        for (int nt = 0; nt < 8; nt++) {
            float* p0 = xrow + nt * 8;
            const float* b0 = brow + nt * 8;
            p0[0]          += acc[mt][nt][0] + b0[0];
            p0[1]          += acc[mt][nt][1] + b0[1];
            p0[8 * Dd]     += acc[mt][nt][2] + b0[0];
            p0[8 * Dd + 1] += acc[mt][nt][3] + b0[1];
        }
    }
}

// ---------------- kernel 3: attention, fp16x3, P-in-regs, dbl-buffered KV ----
// Q tile 128 x KV tile 64; 256 thr, 8 warps; warp w owns rows [16w,16w+16).
// smem: Q0/Q1 [128][272]; 2 x (K0/K1 [64][272] + V0/V1 [128][144])
#define AOFF_Q0 0
#define AOFF_Q1 34816
#define ABUF0   69632
#define KB_SZ   17408
#define VB_SZ   18432
#define BUF_SZ  (2*KB_SZ + 2*VB_SZ)     // 71680
#define ATT_SMEM_B (ABUF0 + 2*BUF_SZ)   // 212992

__device__ __forceinline__ void attn_issue_kv(
    uint32_t sb, int buf, int s0,
    const u16* __restrict__ gK0, const u16* __restrict__ gK1,
    const u16* __restrict__ gV0, const u16* __restrict__ gV1, int tid)
{
    uint32_t bb = sb + ABUF0 + (uint32_t)(buf * BUF_SZ);
    #pragma unroll
    for (int p = 0; p < 4; p++) {
        int f = tid + p * 256;
        int kr = f >> 4, kc = f & 15;
        uint32_t kso = (uint32_t)(kr * 272 + kc * 16);
        size_t kgo = (size_t)(s0 + kr) * HD + kc * 8;
        cp_async16(bb + kso,         gK0 + kgo);
        cp_async16(bb + KB_SZ + kso, gK1 + kgo);
        int vr = f >> 3, vc = f & 7;
        uint32_t vso = (uint32_t)(vr * 144 + vc * 16);
        size_t vgo = (size_t)vr * Tt + s0 + vc * 8;
        cp_async16(bb + 2 * KB_SZ + vso,         gV0 + vgo);
        cp_async16(bb + 2 * KB_SZ + VB_SZ + vso, gV1 + vgo);
    }
}

__global__ __launch_bounds__(256) void attn_mma_kernel()
{
    extern __shared__ char smx[];
    int bh = blockIdx.y, qt = blockIdx.x;
    int t0 = qt * 128;
    const u16* gQ0 = g_q0  + (size_t)bh * TH;
    const u16* gQ1 = g_q1  + (size_t)bh * TH;
    const u16* gK0 = g_k0  + (size_t)bh * TH;
    const u16* gK1 = g_k1  + (size_t)bh * TH;
    const u16* gV0 = g_v0t + (size_t)bh * TH;
    const u16* gV1 = g_v1t + (size_t)bh * TH;

    int tid = threadIdx.x, wid = tid >> 5, lane = tid & 31;
    int lr = lane >> 2, lc = lane & 3;

    int la15 = lane & 15, lh = lane >> 4;
    int lb = (lane & 7) + ((lane >> 4) << 3), lk = (lane >> 3) & 1;
    uint32_t sb = smem_to_u32(smx);
    uint32_t q0u = sb + AOFF_Q0 + (uint32_t)((16 * wid + la15) * 272 + lh * 16);
    uint32_t q1u = q0u + (AOFF_Q1 - AOFF_Q0);
    uint32_t klane = (uint32_t)(lb * 272 + lk * 16);
    uint32_t vlane = (uint32_t)(lb * 144 + lk * 16);

    // prologue: Q tile + KV(0) in one group
    #pragma unroll
    for (int p = 0; p < 8; p++) {
        int f = tid + p * 256;
        int r = f >> 4, c16 = f & 15;
        uint32_t so = (uint32_t)(r * 272 + c16 * 16);
        size_t go = (size_t)(t0 + r) * HD + c16 * 8;
        cp_async16(sb + AOFF_Q0 + so, gQ0 + go);
        cp_async16(sb + AOFF_Q1 + so, gQ1 + go);
    }
    attn_issue_kv(sb, 0, 0, gK0, gK1, gV0, gV1, tid);
    cp_commit();

    float o_acc[16][4];
    #pragma unroll
    for (int nt = 0; nt < 16; nt++)
        #pragma unroll
        for (int r = 0; r < 4; r++) o_acc[nt][r] = 0.f;
    float m_i[2] = {neg_inf(), neg_inf()};
    float l_i[2] = {0.f, 0.f};

    int row_w = t0 + 16 * wid;
    int ntiles = 2 * (qt + 1);
    for (int j = 0; j < ntiles; j++) {
        int s0 = 64 * j;
        cp_wait<0>();
        __syncthreads();                 // data visible + prev buf readers done
        if (j + 1 < ntiles) {
            attn_issue_kv(sb, (j + 1) & 1, s0 + 64, gK0, gK1, gV0, gV1, tid);
            cp_commit();
        }
        uint32_t bufb = sb + ABUF0 + (uint32_t)((j & 1) * BUF_SZ);
        uint32_t k0u = bufb + klane;
        uint32_t k1u = k0u + KB_SZ;
        uint32_t v0u = bufb + 2 * KB_SZ + vlane;
        uint32_t v1u = v0u + VB_SZ;

        bool active = (s0 <= row_w + 15);
        if (active) {
            float sacc[8][4];
            #pragma unroll
            for (int nt = 0; nt < 8; nt++)
                #pragma unroll
                for (int r = 0; r < 4; r++) sacc[nt][r] = 0.f;

            // S = Q K^T (16x64), fp16x3
            #pragma unroll 2
            for (int k16 = 0; k16 < 8; k16++) {
                uint32_t ko = (uint32_t)(k16 * 32);
                uint32_t qa0[4], qa1[4];
                ldsm4(qa0, q0u + ko);
                ldsm4(qa1, q1u + ko);
                #pragma unroll
                for (int g = 0; g < 4; g++) {
                    uint32_t kf0[4], kf1[4];
                    ldsm4(kf0, k0u + g * (16 * 272) + ko);
                    ldsm4(kf1, k1u + g * (16 * 272) + ko);
                    #pragma unroll
                    for (int h2 = 0; h2 < 2; h2++) {
                        int nt = 2 * g + h2;
                        uint32_t bh2[2] = {kf0[2 * h2], kf0[2 * h2 + 1]};
                        uint32_t bl2[2] = {kf1[2 * h2], kf1[2 * h2 + 1]};
                        mma_f16(sacc[nt], qa0, bh2);
                        mma_f16(sacc[nt], qa0, bl2);
                        mma_f16(sacc[nt], qa1, bh2);
                    }
                }
            }
            // causal mask
            if (s0 + 63 > row_w) {
                int r0 = row_w + lr;
                #pragma unroll
                for (int nt = 0; nt < 8; nt++) {
                    int cb = s0 + 8 * nt + 2 * lc;
                    if (cb     > r0)     sacc[nt][0] = neg_inf();
                    if (cb + 1 > r0)     sacc[nt][1] = neg_inf();
                    if (cb     > r0 + 8) sacc[nt][2] = neg_inf();
                    if (cb + 1 > r0 + 8) sacc[nt][3] = neg_inf();
                }
            }
            // online softmax (rows lr, lr+8; quad shuffles)
            float rm0 = neg_inf(), rm1 = neg_inf();
            #pragma unroll
            for (int nt = 0; nt < 8; nt++) {
                rm0 = fmaxf(rm0, fmaxf(sacc[nt][0], sacc[nt][1]));
                rm1 = fmaxf(rm1, fmaxf(sacc[nt][2], sacc[nt][3]));
            }
            rm0 = fmaxf(rm0, __shfl_xor_sync(0xffffffffu, rm0, 1));
            rm0 = fmaxf(rm0, __shfl_xor_sync(0xffffffffu, rm0, 2));
            rm1 = fmaxf(rm1, __shfl_xor_sync(0xffffffffu, rm1, 1));
            rm1 = fmaxf(rm1, __shfl_xor_sync(0xffffffffu, rm1, 2));
            float mn0 = fmaxf(m_i[0], rm0), mn1 = fmaxf(m_i[1], rm1);
            float al0 = expf(m_i[0] - mn0), al1 = expf(m_i[1] - mn1);
            float rs0 = 0.f, rs1 = 0.f;
            #pragma unroll
            for (int nt = 0; nt < 8; nt++) {
                sacc[nt][0] = expf(sacc[nt][0] - mn0);
                sacc[nt][1] = expf(sacc[nt][1] - mn0);
                sacc[nt][2] = expf(sacc[nt][2] - mn1);
                sacc[nt][3] = expf(sacc[nt][3] - mn1);
                rs0 += sacc[nt][0] + sacc[nt][1];
                rs1 += sacc[nt][2] + sacc[nt][3];
            }
            rs0 += __shfl_xor_sync(0xffffffffu, rs0, 1);
            rs0 += __shfl_xor_sync(0xffffffffu, rs0, 2);
            rs1 += __shfl_xor_sync(0xffffffffu, rs1, 1);
            rs1 += __shfl_xor_sync(0xffffffffu, rs1, 2);
            l_i[0] = l_i[0] * al0 + rs0;  m_i[0] = mn0;
            l_i[1] = l_i[1] * al1 + rs1;  m_i[1] = mn1;
            #pragma unroll
            for (int nt = 0; nt < 16; nt++) {
                o_acc[nt][0] *= al0; o_acc[nt][1] *= al0;
                o_acc[nt][2] *= al1; o_acc[nt][3] *= al1;
            }
            // P frags directly in registers (C-layout == A-layout)
            uint32_t ph[8][2], pl[8][2];
            #pragma unroll
            for (int nt = 0; nt < 8; nt++) {
                u16 h0,l0,h1,l1,h2,l2,h3,l3;
                splith(sacc[nt][0], h0, l0); splith(sacc[nt][1], h1, l1);
                splith(sacc[nt][2], h2, l2); splith(sacc[nt][3], h3, l3);
                ph[nt][0] = pack2(h0, h1); ph[nt][1] = pack2(h2, h3);
                pl[nt][0] = pack2(l0, l1); pl[nt][1] = pack2(l2, l3);
            }
            // O += P V (16x128), fp16x3
            #pragma unroll 2
            for (int k16 = 0; k16 < 4; k16++) {
                uint32_t ko = (uint32_t)(k16 * 32);
                uint32_t pa0[4] = {ph[2*k16][0], ph[2*k16][1], ph[2*k16+1][0], ph[2*k16+1][1]};
                uint32_t pa1[4] = {pl[2*k16][0], pl[2*k16][1], pl[2*k16+1][0], pl[2*k16+1][1]};
                #pragma unroll
                for (int g = 0; g < 8; g++) {
                    uint32_t vf0[4], vf1[4];
                    ldsm4(vf0, v0u + g * (16 * 144) + ko);
                    ldsm4(vf1, v1u + g * (16 * 144) + ko);
                    #pragma unroll
                    for (int h2 = 0; h2 < 2; h2++) {
                        int nt = 2 * g + h2;
                        uint32_t bh2[2] = {vf0[2 * h2], vf0[2 * h2 + 1]};
                        uint32_t bl2[2] = {vf1[2 * h2], vf1[2 * h2 + 1]};
                        mma_f16(o_acc[nt], pa0, bh2);
                        mma_f16(o_acc[nt], pa0, bl2);
                        mma_f16(o_acc[nt], pa1, bh2);
                    }
                }
            }
        }
    }

    // epilogue: write split attention output [B, T, H*HD] (fp16 hi/lo)
    float inv0 = 1.0f / l_i[0], inv1 = 1.0f / l_i[1];
    int bb = bh >> 3, h = bh & 7;
    int r0 = row_w + lr;
    size_t base0 = ((size_t)(bb * Tt + r0)) * Dd + h * HD;
    size_t base1 = ((size_t)(bb * Tt + r0 + 8)) * Dd + h * HD;
    #pragma unroll
    for (int nt = 0; nt < 16; nt++) {
        int col = 8 * nt + 2 * lc;
        u16 h0,l0,h1,l1,h2,l2,h3,l3;
        splith(o_acc[nt][0] * inv0, h0, l0); splith(o_acc[nt][1] * inv0, h1, l1);
        splith(o_acc[nt][2] * inv1, h2, l2); splith(o_acc[nt][3] * inv1, h3, l3);
        *(uint32_t*)&g_att0[base0 + col] = pack2(h0, h1);
        *(uint32_t*)&g_att1[base0 + col] = pack2(l0, l1);
        *(uint32_t*)&g_att0[base1 + col] = pack2(h2, h3);
        *(uint32_t*)&g_att1[base1 + col] = pack2(l2, l3);
    }
}

// ---------------- kernel 5: LayerNorm2 + noisy top-2 router + outputs --------
#define OUT_OFF_PROBS (BT * Dd)
#define OUT_OFF_IDX   (OUT_OFF_PROBS + BT * Ee)
#define OUT_OFF_X     (OUT_OFF_IDX + BT * 2)
__global__ __launch_bounds__(256) void ln2_router_kernel(
    const float* __restrict__ g2, const float* __restrict__ b2,
    const float* __restrict__ Wr, const float* __restrict__ br,
    const float* __restrict__ Wn, const float* __restrict__ bn,
    float* __restrict__ out)
{
    int token = blockIdx.x;
    int tid = threadIdx.x;
    __shared__ float sxn[Dd];
    __shared__ float rs_[8], rq_[8];
    __shared__ float red[8][16];

    const float* xr = g_x + (size_t)token * Dd;
    float lsum = 0.f, lsq = 0.f;
    for (int c = tid; c < Dd; c += 256) {
        float v = xr[c];
        sxn[c] = v;
        out[OUT_OFF_X + (size_t)token * Dd + c] = v;
        lsum += v; lsq += v * v;
    }
    #pragma unroll
    for (int o = 16; o; o >>= 1) {
        lsum += __shfl_xor_sync(0xffffffffu, lsum, o);
        lsq  += __shfl_xor_sync(0xffffffffu, lsq,  o);
    }
    if ((tid & 31) == 0) { rs_[tid >> 5] = lsum; rq_[tid >> 5] = lsq; }
    __syncthreads();
    float s = 0.f, q = 0.f;
    #pragma unroll
    for (int w = 0; w < 8; w++) { s += rs_[w]; q += rq_[w]; }
    float mu   = s * (1.0f / Dd);
    float var  = q * (1.0f / Dd) - mu * mu;
    float rstd = rsqrtf(var + 1e-5f);

    for (int c = tid; c < Dd; c += 256) {
        float v  = sxn[c];
        float xn = (v - mu) * rstd * g2[c] + b2[c];
        sxn[c] = xn;
        out[(size_t)token * Dd + c] = xn;
    }
    __syncthreads();

    float ar[8] = {}, an_[8] = {};
    for (int c = tid; c < Dd; c += 256) {
        float v = sxn[c];
        float4 w0 = *(const float4*)&Wr[(size_t)c * Ee];
        float4 w1 = *(const float4*)&Wr[(size_t)c * Ee + 4];
        ar[0] += v * w0.x; ar[1] += v * w0.y; ar[2] += v * w0.z; ar[3] += v * w0.w;
        ar[4] += v * w1.x; ar[5] += v * w1.y; ar[6] += v * w1.z; ar[7] += v * w1.w;
        float4 n0 = *(const float4*)&Wn[(size_t)c * Ee];
        float4 n1 = *(const float4*)&Wn[(size_t)c * Ee + 4];
        an_[0] += v * n0.x; an_[1] += v * n0.y; an_[2] += v * n0.z; an_[3] += v * n0.w;
        an_[4] += v * n1.x; an_[5] += v * n1.y; an_[6] += v * n1.z; an_[7] += v * n1.w;
    }
    #pragma unroll
    for (int o = 16; o; o >>= 1) {
        #pragma unroll
        for (int e = 0; e < 8; e++) {
            ar[e]  += __shfl_xor_sync(0xffffffffu, ar[e],  o);
            an_[e] += __shfl_xor_sync(0xffffffffu, an_[e], o);
        }
    }
    int w = tid >> 5;
    if ((tid & 31) == 0) {
        #pragma unroll
        for (int e = 0; e < 8; e++) { red[w][e] = ar[e]; red[w][8 + e] = an_[e]; }
    }
    __syncthreads();

    if (tid == 0) {
        float lg[8], nl[8];
        #pragma unroll
        for (int e = 0; e < 8; e++) { lg[e] = br[e]; nl[e] = bn[e]; }
        for (int ww = 0; ww < 8; ww++)
            #pragma unroll
            for (int e = 0; e < 8; e++) { lg[e] += red[ww][e]; nl[e] += red[ww][8 + e]; }

        float noisy[8];
        #pragma unroll
        for (int e = 0; e < 8; e++) {
            float nz = jax_noise((uint32_t)(token * Ee + e));
            noisy[e] = lg[e] + nz * softplus_f(nl[e]);
        }
        int i0 = 0; float v0 = noisy[0];
        #pragma unroll
        for (int e = 1; e < 8; e++) if (noisy[e] > v0) { v0 = noisy[e]; i0 = e; }
        int i1 = -1; float v1 = neg_inf();
        #pragma unroll
        for (int e = 0; e < 8; e++)
            if (e != i0 && noisy[e] > v1) { v1 = noisy[e]; i1 = e; }

        float e1 = expf(v1 - v0);
        float inv = 1.0f / (1.0f + e1);
        float p0 = inv, p1 = e1 * inv;

        float probs[8] = {};
        probs[i0] = p0; probs[i1] = p1;
        float* pout = out + OUT_OFF_PROBS + (size_t)token * Ee;
        #pragma unroll
        for (int e = 0; e < 8; e++) pout[e] = probs[e];
        out[OUT_OFF_IDX + (size_t)token * 2 + 0] = (float)i0;
        out[OUT_OFF_IDX + (size_t)token * 2 + 1] = (float)i1;
    }
}

// ---------------- launcher ---------------------------------------------------
extern "C" void kernel_launch(void* const* d_in, const int* in_sizes, int n_in,
                              void* d_out, int out_size)
{
    const int*   idx = (const int*)  d_in[0];
    const float* tok = (const float*)d_in[1];
    const float* pos = (const float*)d_in[2];
    const float* Wq  = (const float*)d_in[3];
    const float* Wk  = (const float*)d_in[4];
    const float* Wv  = (const float*)d_in[5];
    const float* Wo  = (const float*)d_in[6];
    const float* bo  = (const float*)d_in[7];
    const float* g1  = (const float*)d_in[8];
    const float* b1  = (const float*)d_in[9];
    const float* g2  = (const float*)d_in[10];
    const float* b2  = (const float*)d_in[11];
    const float* Wr  = (const float*)d_in[12];
    const float* br  = (const float*)d_in[13];
    const float* Wn  = (const float*)d_in[14];
    const float* bn  = (const float*)d_in[15];
    float* out = (float*)d_out;

    cudaFuncSetAttribute(attn_mma_kernel, cudaFuncAttributeMaxDynamicSharedMemorySize,
                         ATT_SMEM_B);
    cudaFuncSetAttribute(qkv_mma_kernel, cudaFuncAttributeMaxDynamicSharedMemorySize,
                         GEMM_SMEM);
    cudaFuncSetAttribute(proj_mma_kernel, cudaFuncAttributeMaxDynamicSharedMemorySize,
                         GEMM_SMEM);

    embed_ln_kernel<<<BT, 256>>>(idx, tok, pos, g1, b1);
    transpose_qkv_kernel<<<dim3(32, 4, 24), dim3(32, 8)>>>(Wq, Wk, Wv);
    transpose_wo_kernel<<<dim3(32, 32), dim3(32, 8)>>>(Wo);
    qkv_mma_kernel<<<dim3(BT / 128, 24), 256, GEMM_SMEM>>>();
    attn_mma_kernel<<<dim3(Tt / 128, Bb * Hh), 256, ATT_SMEM_B>>>();
    proj_mma_kernel<<<dim3(BT / 128, Dd / 128), 256, GEMM_SMEM>>>(bo);
    ln2_router_kernel<<<BT, 256>>>(g2, b2, Wr, br, Wn, bn, out);
}